// round 9
// baseline (speedup 1.0000x reference)
#include <cuda_runtime.h>
#include <cuda_bf16.h>
#include <math.h>
#include <stdint.h>

#define B_   4
#define S_   2048
#define EMB_ 1024
#define H_   16
#define HD_  64
#define M_   (B_ * S_)   // 8192

// ---- ptx helpers (mma.sync / ldmatrix / cp.async) — baseline sm_103 legal --
__device__ __forceinline__ uint32_t smem_u32(const void* p) {
    uint32_t a;
    asm("{ .reg .u64 t; cvta.to.shared.u64 t, %1; cvt.u32.u64 %0, t; }"
        : "=r"(a) : "l"(p));
    return a;
}
__device__ __forceinline__ void cpa16(uint32_t dst, const void* src) {
    asm volatile("cp.async.cg.shared.global [%0], [%1], 16;" :: "r"(dst), "l"(src) : "memory");
}
#define CPA_COMMIT() asm volatile("cp.async.commit_group;" ::: "memory")
#define CPA_WAIT1()  asm volatile("cp.async.wait_group 1;"  ::: "memory")

#define LDSM4(r0, r1, r2, r3, addr) \
    asm volatile("ldmatrix.sync.aligned.m8n8.x4.shared.b16 {%0,%1,%2,%3}, [%4];" \
        : "=r"(r0), "=r"(r1), "=r"(r2), "=r"(r3) : "r"(addr))
#define LDSM4T(r0, r1, r2, r3, addr) \
    asm volatile("ldmatrix.sync.aligned.m8n8.x4.trans.shared.b16 {%0,%1,%2,%3}, [%4];" \
        : "=r"(r0), "=r"(r1), "=r"(r2), "=r"(r3) : "r"(addr))

#define MMA16816(c, a, b0, b1) \
    asm volatile("mma.sync.aligned.m16n8k16.row.col.f32.bf16.bf16.f32 " \
        "{%0,%1,%2,%3},{%4,%5,%6,%7},{%8,%9},{%0,%1,%2,%3};" \
        : "+f"((c)[0]), "+f"((c)[1]), "+f"((c)[2]), "+f"((c)[3]) \
        : "r"((a)[0]), "r"((a)[1]), "r"((a)[2]), "r"((a)[3]), "r"(b0), "r"(b1))

__device__ __forceinline__ uint32_t packbf(float lo, float hi) {
    uint32_t r;
    asm("cvt.rn.bf16x2.f32 %0, %1, %2;" : "=r"(r) : "f"(hi), "f"(lo));
    return r;
}
__device__ __forceinline__ float bflo(uint32_t p) { return __uint_as_float(p << 16); }
__device__ __forceinline__ float bfhi(uint32_t p) { return __uint_as_float(p & 0xffff0000u); }
__device__ __forceinline__ float ex2(float x) {
    float r; asm("ex2.approx.f32 %0, %1;" : "=f"(r) : "f"(x)); return r;
}

// ---------------- scratch (device globals; no allocation allowed) ----------
__device__ __align__(16) __nv_bfloat16 g_xhi[(size_t)M_ * EMB_];
__device__ __align__(16) __nv_bfloat16 g_xlo[(size_t)M_ * EMB_];
__device__ __align__(16) __nv_bfloat16 g_whi[(size_t)4 * EMB_ * EMB_];
__device__ __align__(16) __nv_bfloat16 g_wlo[(size_t)4 * EMB_ * EMB_];
__device__ __align__(16) __nv_bfloat16 g_qhi[(size_t)M_ * EMB_];
__device__ __align__(16) __nv_bfloat16 g_qlo[(size_t)M_ * EMB_];
__device__ __align__(16) __nv_bfloat16 g_khi[(size_t)M_ * EMB_];
__device__ __align__(16) __nv_bfloat16 g_klo[(size_t)M_ * EMB_];
__device__ __align__(16) __nv_bfloat16 g_vhi[(size_t)M_ * EMB_];
__device__ __align__(16) __nv_bfloat16 g_vlo[(size_t)M_ * EMB_];
__device__ __align__(16) __nv_bfloat16 g_ahi[(size_t)M_ * EMB_];
__device__ __align__(16) __nv_bfloat16 g_alo[(size_t)M_ * EMB_];

// ---------------- fp32 -> bf16 hi/lo split ----------------------------------
__global__ __launch_bounds__(256) void conv_split_x(
    const float* __restrict__ src, int n4)
{
    int i = blockIdx.x * 256 + threadIdx.x;
    if (i >= n4) return;
    float4 v = ((const float4*)src)[i];
    uint32_t h01 = packbf(v.x, v.y), h23 = packbf(v.z, v.w);
    uint32_t l01 = packbf(v.x - bflo(h01), v.y - bfhi(h01));
    uint32_t l23 = packbf(v.z - bflo(h23), v.w - bfhi(h23));
    ((uint32_t*)g_xhi)[2 * i] = h01; ((uint32_t*)g_xhi)[2 * i + 1] = h23;
    ((uint32_t*)g_xlo)[2 * i] = l01; ((uint32_t*)g_xlo)[2 * i + 1] = l23;
}
__global__ __launch_bounds__(256) void conv_split_w(
    const float* __restrict__ w0, const float* __restrict__ w1,
    const float* __restrict__ w2, const float* __restrict__ w3)
{
    const int which = blockIdx.y;
    const float* src = (which == 0) ? w0 : (which == 1) ? w1 : (which == 2) ? w2 : w3;
    __nv_bfloat16* hi = g_whi + (size_t)which * EMB_ * EMB_;
    __nv_bfloat16* lo = g_wlo + (size_t)which * EMB_ * EMB_;
    int i = blockIdx.x * 256 + threadIdx.x;
    float4 v = ((const float4*)src)[i];
    uint32_t h01 = packbf(v.x, v.y), h23 = packbf(v.z, v.w);
    uint32_t l01 = packbf(v.x - bflo(h01), v.y - bfhi(h01));
    uint32_t l23 = packbf(v.z - bflo(h23), v.w - bfhi(h23));
    ((uint32_t*)hi)[2 * i] = h01; ((uint32_t*)hi)[2 * i + 1] = h23;
    ((uint32_t*)lo)[2 * i] = l01; ((uint32_t*)lo)[2 * i + 1] = l23;
}

// ---------------- mma.sync GEMM: D = A @ W^T + bias --------------------------
constexpr int GSTRIDE = 144;
constexpr int GMAT    = 128 * GSTRIDE;             // 18432
constexpr int GSTAGE  = 4 * GMAT;                  // 73728
constexpr int GEMM_SMEM = 2 * GSTAGE;              // 147456

__device__ __forceinline__ void gload_chunk(
    uint32_t sbase, const __nv_bfloat16* Ahi, const __nv_bfloat16* Alo,
    const __nv_bfloat16* Bhi, const __nv_bfloat16* Blo,
    int row0, int col0, int k0, int tid)
{
    #pragma unroll
    for (int i = tid; i < 4096; i += 256) {
        int mat = i >> 10;
        int r   = (i >> 3) & 127;
        int c   = i & 7;
        uint32_t dst = sbase + mat * GMAT + r * GSTRIDE + c * 16;
        const __nv_bfloat16* m =
            (mat == 0) ? Ahi : (mat == 1) ? Alo : (mat == 2) ? Bhi : Blo;
        int gr = ((mat < 2) ? row0 : col0) + r;
        cpa16(dst, m + (size_t)gr * EMB_ + k0 + c * 8);
    }
    CPA_COMMIT();
}

__global__ __launch_bounds__(256) void gemm_mma_kernel(
    const float* __restrict__ bq, const float* __restrict__ bk,
    const float* __restrict__ bv, float* __restrict__ outp, int mode)
{
    extern __shared__ char smem[];
    const uint32_t sb = smem_u32(smem);
    const int tid = threadIdx.x, wid = tid >> 5, lane = tid & 31;
    const int row0 = blockIdx.y * 128, col0 = blockIdx.x * 128;
    const int z = blockIdx.z;

    const __nv_bfloat16 *Ahi, *Alo, *Bhi, *Blo;
    const float* bias;
    if (mode == 0) {
        Ahi = g_xhi; Alo = g_xlo;
        Bhi = g_whi + (size_t)z * EMB_ * EMB_;
        Blo = g_wlo + (size_t)z * EMB_ * EMB_;
        bias = (z == 0) ? bq : (z == 1) ? bk : bv;
    } else {
        Ahi = g_ahi; Alo = g_alo;
        Bhi = g_whi + (size_t)3 * EMB_ * EMB_;
        Blo = g_wlo + (size_t)3 * EMB_ * EMB_;
        bias = bq;
    }

    const int wm = (wid & 1) * 64;
    const int wn = (wid >> 1) * 32;

    float c[4][4][4] = {};

    gload_chunk(sb,          Ahi, Alo, Bhi, Blo, row0, col0, 0,  tid);
    gload_chunk(sb + GSTAGE, Ahi, Alo, Bhi, Blo, row0, col0, 64, tid);

    const int a_row = wm + (lane & 7) + ((lane >> 3) & 1) * 8;
    const int a_kc  = ((lane >> 4) & 1) * 8;
    const int b_row = wn + (lane & 7) + ((lane >> 4) & 1) * 8;
    const int b_kc  = ((lane >> 3) & 1) * 8;

    for (int ch = 0; ch < 16; ++ch) {
        const int s = ch & 1;
        CPA_WAIT1();
        __syncthreads();
        const uint32_t st = sb + s * GSTAGE;

        #pragma unroll
        for (int kk = 0; kk < 64; kk += 16) {
            uint32_t bh[2][4], bl[2][4];
            #pragma unroll
            for (int pt = 0; pt < 2; ++pt) {
                uint32_t addr = st + 2 * GMAT + (b_row + pt * 16) * GSTRIDE
                              + (kk + b_kc) * 2;
                LDSM4(bh[pt][0], bh[pt][1], bh[pt][2], bh[pt][3], addr);
                LDSM4(bl[pt][0], bl[pt][1], bl[pt][2], bl[pt][3], addr + GMAT);
            }
            #pragma unroll
            for (int mt = 0; mt < 4; ++mt) {
                uint32_t addr = st + (a_row + mt * 16) * GSTRIDE
                              + (kk + a_kc) * 2;
                uint32_t ah[4], al[4];
                LDSM4(ah[0], ah[1], ah[2], ah[3], addr);
                LDSM4(al[0], al[1], al[2], al[3], addr + GMAT);
                // term-major issue: dependency distance 4 on each accumulator
                #pragma unroll
                for (int nt = 0; nt < 4; ++nt) {
                    const int pt = nt >> 1, hf = (nt & 1) * 2;
                    MMA16816(c[mt][nt], ah, bh[pt][hf], bh[pt][hf + 1]);
                }
                #pragma unroll
                for (int nt = 0; nt < 4; ++nt) {
                    const int pt = nt >> 1, hf = (nt & 1) * 2;
                    MMA16816(c[mt][nt], ah, bl[pt][hf], bl[pt][hf + 1]);
                }
                #pragma unroll
                for (int nt = 0; nt < 4; ++nt) {
                    const int pt = nt >> 1, hf = (nt & 1) * 2;
                    MMA16816(c[mt][nt], al, bh[pt][hf], bh[pt][hf + 1]);
                }
            }
        }
        __syncthreads();
        if (ch + 2 < 16)
            gload_chunk(sb + s * GSTAGE, Ahi, Alo, Bhi, Blo,
                        row0, col0, (ch + 2) * 64, tid);
        else
            CPA_COMMIT();
    }

    #pragma unroll
    for (int mt = 0; mt < 4; ++mt) {
        #pragma unroll
        for (int nt = 0; nt < 4; ++nt) {
            int r = row0 + wm + mt * 16 + (lane >> 2);
            int n = col0 + wn + nt * 8 + (lane & 3) * 2;
            float2 bv2 = *(const float2*)&bias[n];
            float p0 = c[mt][nt][0] + bv2.x, p1 = c[mt][nt][1] + bv2.y;
            float p2 = c[mt][nt][2] + bv2.x, p3 = c[mt][nt][3] + bv2.y;
            if (mode == 0) {
                __nv_bfloat16 *dh, *dl;
                if (z == 0)      { dh = g_qhi; dl = g_qlo; }
                else if (z == 1) { dh = g_khi; dl = g_klo; }
                else             { dh = g_vhi; dl = g_vlo; }
                int h = n >> 6, d = n & 63;
                int bb0 = r >> 11, s0 = r & 2047;
                int bb1 = (r + 8) >> 11, s1 = (r + 8) & 2047;
                size_t i0 = (((size_t)bb0 * H_ + h) * S_ + s0) * HD_ + d;
                size_t i1 = (((size_t)bb1 * H_ + h) * S_ + s1) * HD_ + d;
                uint32_t h01 = packbf(p0, p1);
                uint32_t l01 = packbf(p0 - bflo(h01), p1 - bfhi(h01));
                uint32_t h23 = packbf(p2, p3);
                uint32_t l23 = packbf(p2 - bflo(h23), p3 - bfhi(h23));
                *(uint32_t*)&dh[i0] = h01; *(uint32_t*)&dl[i0] = l01;
                *(uint32_t*)&dh[i1] = h23; *(uint32_t*)&dl[i1] = l23;
            } else {
                float2 v0 = {p0, p1}, v1 = {p2, p3};
                *(float2*)&outp[(size_t)r * EMB_ + n] = v0;
                *(float2*)&outp[(size_t)(r + 8) * EMB_ + n] = v1;
            }
        }
    }
}

// ---------------- mma.sync causal flash attention ---------------------------
constexpr int ASTR   = 144;
constexpr int AQMAT  = 128 * ASTR;                  // 18432
constexpr int AKMAT  = 64 * ASTR;                   // 9216
constexpr int ASTAGE = 4 * AKMAT;                   // 36864
constexpr int ATTN_SMEM = 2 * AQMAT + 2 * ASTAGE;   // 110592

__device__ __forceinline__ void akv_load(
    uint32_t base, const __nv_bfloat16* Kh, const __nv_bfloat16* Kl,
    const __nv_bfloat16* Vh, const __nv_bfloat16* Vl, int kt, int tid)
{
    #pragma unroll
    for (int i = tid; i < 2048; i += 256) {
        int mat = i >> 9;
        int r   = (i >> 3) & 63;
        int c   = i & 7;
        const __nv_bfloat16* m =
            (mat == 0) ? Kh : (mat == 1) ? Kl : (mat == 2) ? Vh : Vl;
        cpa16(base + mat * AKMAT + r * ASTR + c * 16,
              m + (size_t)(kt * 64 + r) * HD_ + c * 8);
    }
}

__global__ __launch_bounds__(256) void attn_mma_kernel()
{
    extern __shared__ char smem[];
    const uint32_t sb = smem_u32(smem);
    const int tid = threadIdx.x, wid = tid >> 5, lane = tid & 31;
    const int qt = (S_ / 128 - 1) - blockIdx.y;   // heavy tiles dispatch first
    const int bh = blockIdx.x;
    const size_t off = (size_t)bh * S_ * HD_;
    const __nv_bfloat16 *Qh = g_qhi + off, *Ql = g_qlo + off;
    const __nv_bfloat16 *Kh = g_khi + off, *Kl = g_klo + off;
    const __nv_bfloat16 *Vh = g_vhi + off, *Vl = g_vlo + off;
    const int ntiles = 2 * qt + 2;

    #pragma unroll
    for (int i = tid; i < 2048; i += 256) {
        int mat = i >> 10, r = (i >> 3) & 127, c = i & 7;
        const __nv_bfloat16* m = mat ? Ql : Qh;
        cpa16(sb + mat * AQMAT + r * ASTR + c * 16,
              m + (size_t)(qt * 128 + r) * HD_ + c * 8);
    }
    akv_load(sb + 2 * AQMAT, Kh, Kl, Vh, Vl, 0, tid);
    CPA_COMMIT();
    akv_load(sb + 2 * AQMAT + ASTAGE, Kh, Kl, Vh, Vl, 1, tid);
    CPA_COMMIT();

    const int a_row = wid * 16 + (lane & 7) + ((lane >> 3) & 1) * 8;
    const int a_kc2 = ((lane >> 4) & 1) * 16;
    const int b_row = (lane & 7) + ((lane >> 4) & 1) * 8;
    const int b_kc2 = ((lane >> 3) & 1) * 16;
    const int v_row = (lane & 7) + ((lane >> 3) & 1) * 8;
    const int v_cc2 = ((lane >> 4) & 1) * 16;
    const int row0g = qt * 128 + wid * 16 + (lane >> 2);

    float O[8][4] = {};
    float m0 = -1e30f, m1 = -1e30f, l0 = 0.0f, l1 = 0.0f;
    const float sc = 0.125f * 1.44269504f;   // scale * log2(e)

    for (int kt = 0; kt < ntiles; ++kt) {
        CPA_WAIT1();
        __syncthreads();
        const uint32_t st = sb + 2 * AQMAT + (kt & 1) * ASTAGE;

        // ---- S = Q K^T (3-term split; term-major across 4 accumulators) ----
        float S[8][4] = {};
        #pragma unroll
        for (int ks = 0; ks < 4; ++ks) {
            uint32_t qaddr = sb + a_row * ASTR + ks * 32 + a_kc2;
            uint32_t ah[4], al[4];
            LDSM4(ah[0], ah[1], ah[2], ah[3], qaddr);
            LDSM4(al[0], al[1], al[2], al[3], qaddr + AQMAT);
            #pragma unroll
            for (int gp = 0; gp < 2; ++gp) {
                uint32_t addr0 = st + ((2 * gp)     * 16 + b_row) * ASTR + ks * 32 + b_kc2;
                uint32_t addr1 = st + ((2 * gp + 1) * 16 + b_row) * ASTR + ks * 32 + b_kc2;
                uint32_t kh0[4], kl0[4], kh1[4], kl1[4];
                LDSM4(kh0[0], kh0[1], kh0[2], kh0[3], addr0);
                LDSM4(kl0[0], kl0[1], kl0[2], kl0[3], addr0 + AKMAT);
                LDSM4(kh1[0], kh1[1], kh1[2], kh1[3], addr1);
                LDSM4(kl1[0], kl1[1], kl1[2], kl1[3], addr1 + AKMAT);
                float* S0 = S[4 * gp + 0]; float* S1 = S[4 * gp + 1];
                float* S2 = S[4 * gp + 2]; float* S3 = S[4 * gp + 3];
                MMA16816(S0, ah, kh0[0], kh0[1]);
                MMA16816(S1, ah, kh0[2], kh0[3]);
                MMA16816(S2, ah, kh1[0], kh1[1]);
                MMA16816(S3, ah, kh1[2], kh1[3]);
                MMA16816(S0, ah, kl0[0], kl0[1]);
                MMA16816(S1, ah, kl0[2], kl0[3]);
                MMA16816(S2, ah, kl1[0], kl1[1]);
                MMA16816(S3, ah, kl1[2], kl1[3]);
                MMA16816(S0, al, kh0[0], kh0[1]);
                MMA16816(S1, al, kh0[2], kh0[3]);
                MMA16816(S2, al, kh1[0], kh1[1]);
                MMA16816(S3, al, kh1[2], kh1[3]);
            }
        }

        // ---- scale (log2 domain) + causal mask ----
        #pragma unroll
        for (int j = 0; j < 8; ++j) {
            S[j][0] *= sc; S[j][1] *= sc; S[j][2] *= sc; S[j][3] *= sc;
        }
        if (kt * 64 + 63 > qt * 128 + wid * 16) {
            #pragma unroll
            for (int j = 0; j < 8; ++j) {
                int col = kt * 64 + j * 8 + (lane & 3) * 2;
                if (col     > row0g)     S[j][0] = -1e30f;
                if (col + 1 > row0g)     S[j][1] = -1e30f;
                if (col     > row0g + 8) S[j][2] = -1e30f;
                if (col + 1 > row0g + 8) S[j][3] = -1e30f;
            }
        }

        // ---- online softmax ----
        float mx0 = -1e30f, mx1 = -1e30f;
        #pragma unroll
        for (int j = 0; j < 8; ++j) {
            mx0 = fmaxf(mx0, fmaxf(S[j][0], S[j][1]));
            mx1 = fmaxf(mx1, fmaxf(S[j][2], S[j][3]));
        }
        mx0 = fmaxf(mx0, __shfl_xor_sync(0xffffffffu, mx0, 1));
        mx0 = fmaxf(mx0, __shfl_xor_sync(0xffffffffu, mx0, 2));
        mx1 = fmaxf(mx1, __shfl_xor_sync(0xffffffffu, mx1, 1));
        mx1 = fmaxf(mx1, __shfl_xor_sync(0xffffffffu, mx1, 2));
        float nm0 = fmaxf(m0, mx0), nm1 = fmaxf(m1, mx1);
        float f0 = ex2(m0 - nm0), f1 = ex2(m1 - nm1);
        m0 = nm0; m1 = nm1;
        float s0 = 0.0f, s1 = 0.0f;
        #pragma unroll
        for (int j = 0; j < 8; ++j) {
            S[j][0] = ex2(S[j][0] - nm0); S[j][1] = ex2(S[j][1] - nm0);
            S[j][2] = ex2(S[j][2] - nm1); S[j][3] = ex2(S[j][3] - nm1);
            s0 += S[j][0] + S[j][1];
            s1 += S[j][2] + S[j][3];
        }
        s0 += __shfl_xor_sync(0xffffffffu, s0, 1);
        s0 += __shfl_xor_sync(0xffffffffu, s0, 2);
        s1 += __shfl_xor_sync(0xffffffffu, s1, 1);
        s1 += __shfl_xor_sync(0xffffffffu, s1, 2);
        l0 = l0 * f0 + s0; l1 = l1 * f1 + s1;
        #pragma unroll
        for (int j = 0; j < 8; ++j) {
            O[j][0] *= f0; O[j][1] *= f0; O[j][2] *= f1; O[j][3] *= f1;
        }

        // ---- O += P V (3-term split; term-major across 4 accumulators) ----
        #pragma unroll
        for (int ks = 0; ks < 4; ++ks) {
            uint32_t ph[4], pl[4];
            ph[0] = packbf(S[2 * ks][0],     S[2 * ks][1]);
            ph[1] = packbf(S[2 * ks][2],     S[2 * ks][3]);
            ph[2] = packbf(S[2 * ks + 1][0], S[2 * ks + 1][1]);
            ph[3] = packbf(S[2 * ks + 1][2], S[2 * ks + 1][3]);
            pl[0] = packbf(S[2 * ks][0]     - bflo(ph[0]), S[2 * ks][1]     - bfhi(ph[0]));
            pl[1] = packbf(S[2 * ks][2]     - bflo(ph[1]), S[2 * ks][3]     - bfhi(ph[1]));
            pl[2] = packbf(S[2 * ks + 1][0] - bflo(ph[2]), S[2 * ks + 1][1] - bfhi(ph[2]));
            pl[3] = packbf(S[2 * ks + 1][2] - bflo(ph[3]), S[2 * ks + 1][3] - bfhi(ph[3]));
            #pragma unroll
            for (int gp = 0; gp < 2; ++gp) {
                uint32_t addr0 = st + 2 * AKMAT + (ks * 16 + v_row) * ASTR
                               + (2 * gp) * 32 + v_cc2;
                uint32_t addr1 = addr0 + 32;
                uint32_t vh0[4], vl0[4], vh1[4], vl1[4];
                LDSM4T(vh0[0], vh0[1], vh0[2], vh0[3], addr0);
                LDSM4T(vl0[0], vl0[1], vl0[2], vl0[3], addr0 + AKMAT);
                LDSM4T(vh1[0], vh1[1], vh1[2], vh1[3], addr1);
                LDSM4T(vl1[0], vl1[1], vl1[2], vl1[3], addr1 + AKMAT);
                float* O0 = O[4 * gp + 0]; float* O1 = O[4 * gp + 1];
                float* O2 = O[4 * gp + 2]; float* O3 = O[4 * gp + 3];
                MMA16816(O0, ph, vh0[0], vh0[1]);
                MMA16816(O1, ph, vh0[2], vh0[3]);
                MMA16816(O2, ph, vh1[0], vh1[1]);
                MMA16816(O3, ph, vh1[2], vh1[3]);
                MMA16816(O0, ph, vl0[0], vl0[1]);
                MMA16816(O1, ph, vl0[2], vl0[3]);
                MMA16816(O2, ph, vl1[0], vl1[1]);
                MMA16816(O3, ph, vl1[2], vl1[3]);
                MMA16816(O0, pl, vh0[0], vh0[1]);
                MMA16816(O1, pl, vh0[2], vh0[3]);
                MMA16816(O2, pl, vh1[0], vh1[1]);
                MMA16816(O3, pl, vh1[2], vh1[3]);
            }
        }

        __syncthreads();
        if (kt + 2 < ntiles) {
            akv_load(sb + 2 * AQMAT + (kt & 1) * ASTAGE, Kh, Kl, Vh, Vl, kt + 2, tid);
            CPA_COMMIT();
        } else {
            CPA_COMMIT();
        }
    }

    // ---- epilogue: normalize, split bf16 hi/lo, write [B,S,EMB] ----
    const float inv0 = 1.0f / l0, inv1 = 1.0f / l1;
    const int b = bh >> 4, h = bh & 15;
    const int r0 = qt * 128 + wid * 16 + (lane >> 2);
    const int cc = (lane & 3) * 2;
    #pragma unroll
    for (int j = 0; j < 8; ++j) {
        float p0 = O[j][0] * inv0, p1 = O[j][1] * inv0;
        float p2 = O[j][2] * inv1, p3 = O[j][3] * inv1;
        size_t i0 = ((size_t)b * S_ + r0) * EMB_ + h * 64 + j * 8 + cc;
        size_t i1 = i0 + (size_t)8 * EMB_;
        uint32_t h01 = packbf(p0, p1);
        uint32_t l01 = packbf(p0 - bflo(h01), p1 - bfhi(h01));
        uint32_t h23 = packbf(p2, p3);
        uint32_t l23 = packbf(p2 - bflo(h23), p3 - bfhi(h23));
        *(uint32_t*)&g_ahi[i0] = h01; *(uint32_t*)&g_alo[i0] = l01;
        *(uint32_t*)&g_ahi[i1] = h23; *(uint32_t*)&g_alo[i1] = l23;
    }
}

// ---------------- launch ---------------------------------------------------
extern "C" void kernel_launch(void* const* d_in, const int* in_sizes, int n_in,
                              void* d_out, int out_size)
{
    const float* x  = (const float*)d_in[0];
    const float* Wq = (const float*)d_in[1];
    const float* bq = (const float*)d_in[2];
    const float* Wk = (const float*)d_in[3];
    const float* bk = (const float*)d_in[4];
    const float* Wv = (const float*)d_in[5];
    const float* bv = (const float*)d_in[6];
    const float* Wo = (const float*)d_in[7];
    const float* bo = (const float*)d_in[8];
    float* out = (float*)d_out;

    cudaFuncSetAttribute(gemm_mma_kernel,
                         cudaFuncAttributeMaxDynamicSharedMemorySize, GEMM_SMEM);
    cudaFuncSetAttribute(attn_mma_kernel,
                         cudaFuncAttributeMaxDynamicSharedMemorySize, ATTN_SMEM);

    const int n4x = M_ * EMB_ / 4;
    const int n4w = EMB_ * EMB_ / 4;
    conv_split_x<<<n4x / 256, 256>>>(x, n4x);
    conv_split_w<<<dim3(n4w / 256, 4), 256>>>(Wq, Wk, Wv, Wo);

    // QKV projections (mma.sync) -> bf16 hi/lo Q/K/V
    gemm_mma_kernel<<<dim3(EMB_ / 128, M_ / 128, 3), 256, GEMM_SMEM>>>(
        bq, bk, bv, nullptr, 0);

    // causal attention (mma.sync flash, heavy-tiles-first dispatch)
    attn_mma_kernel<<<dim3(B_ * H_, S_ / 128), 256, ATTN_SMEM>>>();

    // output projection (mma.sync)
    gemm_mma_kernel<<<dim3(EMB_ / 128, M_ / 128, 1), 256, GEMM_SMEM>>>(
        bo, nullptr, nullptr, out, 1);
}

// round 10
// speedup vs baseline: 1.0253x; 1.0253x over previous
#include <cuda_runtime.h>
#include <cuda_bf16.h>
#include <math.h>
#include <stdint.h>

#define B_   4
#define S_   2048
#define EMB_ 1024
#define H_   16
#define HD_  64
#define M_   (B_ * S_)   // 8192

// ---- ptx helpers (mma.sync / ldmatrix / cp.async) — baseline sm_103 legal --
__device__ __forceinline__ uint32_t smem_u32(const void* p) {
    uint32_t a;
    asm("{ .reg .u64 t; cvta.to.shared.u64 t, %1; cvt.u32.u64 %0, t; }"
        : "=r"(a) : "l"(p));
    return a;
}
__device__ __forceinline__ void cpa16(uint32_t dst, const void* src) {
    asm volatile("cp.async.cg.shared.global [%0], [%1], 16;" :: "r"(dst), "l"(src) : "memory");
}
#define CPA_COMMIT() asm volatile("cp.async.commit_group;" ::: "memory")
#define CPA_WAIT1()  asm volatile("cp.async.wait_group 1;"  ::: "memory")

#define LDSM4(r0, r1, r2, r3, addr) \
    asm volatile("ldmatrix.sync.aligned.m8n8.x4.shared.b16 {%0,%1,%2,%3}, [%4];" \
        : "=r"(r0), "=r"(r1), "=r"(r2), "=r"(r3) : "r"(addr))
#define LDSM4T(r0, r1, r2, r3, addr) \
    asm volatile("ldmatrix.sync.aligned.m8n8.x4.trans.shared.b16 {%0,%1,%2,%3}, [%4];" \
        : "=r"(r0), "=r"(r1), "=r"(r2), "=r"(r3) : "r"(addr))

#define MMA16816(c, a, b0, b1) \
    asm volatile("mma.sync.aligned.m16n8k16.row.col.f32.bf16.bf16.f32 " \
        "{%0,%1,%2,%3},{%4,%5,%6,%7},{%8,%9},{%0,%1,%2,%3};" \
        : "+f"((c)[0]), "+f"((c)[1]), "+f"((c)[2]), "+f"((c)[3]) \
        : "r"((a)[0]), "r"((a)[1]), "r"((a)[2]), "r"((a)[3]), "r"(b0), "r"(b1))

__device__ __forceinline__ uint32_t packbf(float lo, float hi) {
    uint32_t r;
    asm("cvt.rn.bf16x2.f32 %0, %1, %2;" : "=r"(r) : "f"(hi), "f"(lo));
    return r;
}
__device__ __forceinline__ float bflo(uint32_t p) { return __uint_as_float(p << 16); }
__device__ __forceinline__ float bfhi(uint32_t p) { return __uint_as_float(p & 0xffff0000u); }
__device__ __forceinline__ float ex2(float x) {
    float r; asm("ex2.approx.f32 %0, %1;" : "=f"(r) : "f"(x)); return r;
}

// softmax scale folded into Q at projection time: 1/sqrt(64) * log2(e)
#define QSCALE (0.125f * 1.44269504f)

// ---------------- scratch (device globals; no allocation allowed) ----------
__device__ __align__(16) __nv_bfloat16 g_xhi[(size_t)M_ * EMB_];
__device__ __align__(16) __nv_bfloat16 g_xlo[(size_t)M_ * EMB_];
__device__ __align__(16) __nv_bfloat16 g_whi[(size_t)4 * EMB_ * EMB_];
__device__ __align__(16) __nv_bfloat16 g_wlo[(size_t)4 * EMB_ * EMB_];
__device__ __align__(16) __nv_bfloat16 g_qhi[(size_t)M_ * EMB_];
__device__ __align__(16) __nv_bfloat16 g_qlo[(size_t)M_ * EMB_];
__device__ __align__(16) __nv_bfloat16 g_khi[(size_t)M_ * EMB_];
__device__ __align__(16) __nv_bfloat16 g_klo[(size_t)M_ * EMB_];
__device__ __align__(16) __nv_bfloat16 g_vhi[(size_t)M_ * EMB_];
__device__ __align__(16) __nv_bfloat16 g_vlo[(size_t)M_ * EMB_];
__device__ __align__(16) __nv_bfloat16 g_ahi[(size_t)M_ * EMB_];
__device__ __align__(16) __nv_bfloat16 g_alo[(size_t)M_ * EMB_];

// ---------------- fp32 -> bf16 hi/lo split ----------------------------------
__global__ __launch_bounds__(256) void conv_split_x(
    const float* __restrict__ src, int n4)
{
    int i = blockIdx.x * 256 + threadIdx.x;
    if (i >= n4) return;
    float4 v = ((const float4*)src)[i];
    uint32_t h01 = packbf(v.x, v.y), h23 = packbf(v.z, v.w);
    uint32_t l01 = packbf(v.x - bflo(h01), v.y - bfhi(h01));
    uint32_t l23 = packbf(v.z - bflo(h23), v.w - bfhi(h23));
    ((uint32_t*)g_xhi)[2 * i] = h01; ((uint32_t*)g_xhi)[2 * i + 1] = h23;
    ((uint32_t*)g_xlo)[2 * i] = l01; ((uint32_t*)g_xlo)[2 * i + 1] = l23;
}
__global__ __launch_bounds__(256) void conv_split_w(
    const float* __restrict__ w0, const float* __restrict__ w1,
    const float* __restrict__ w2, const float* __restrict__ w3)
{
    const int which = blockIdx.y;
    const float* src = (which == 0) ? w0 : (which == 1) ? w1 : (which == 2) ? w2 : w3;
    __nv_bfloat16* hi = g_whi + (size_t)which * EMB_ * EMB_;
    __nv_bfloat16* lo = g_wlo + (size_t)which * EMB_ * EMB_;
    int i = blockIdx.x * 256 + threadIdx.x;
    float4 v = ((const float4*)src)[i];
    uint32_t h01 = packbf(v.x, v.y), h23 = packbf(v.z, v.w);
    uint32_t l01 = packbf(v.x - bflo(h01), v.y - bfhi(h01));
    uint32_t l23 = packbf(v.z - bflo(h23), v.w - bfhi(h23));
    ((uint32_t*)hi)[2 * i] = h01; ((uint32_t*)hi)[2 * i + 1] = h23;
    ((uint32_t*)lo)[2 * i] = l01; ((uint32_t*)lo)[2 * i + 1] = l23;
}

// ---------------- mma.sync GEMM: D = A @ W^T + bias --------------------------
// 3-stage cp.async pipeline, ONE barrier per K-chunk (CUTLASS multistage order).
constexpr int GSTRIDE = 144;
constexpr int GMAT    = 128 * GSTRIDE;             // 18432
constexpr int GSTAGE  = 4 * GMAT;                  // 73728
constexpr int GEMM_SMEM = 3 * GSTAGE;              // 221184 (1 CTA/SM)

__device__ __forceinline__ void gload_chunk(
    uint32_t sbase, const __nv_bfloat16* Ahi, const __nv_bfloat16* Alo,
    const __nv_bfloat16* Bhi, const __nv_bfloat16* Blo,
    int row0, int col0, int k0, int tid)
{
    #pragma unroll
    for (int i = tid; i < 4096; i += 256) {
        int mat = i >> 10;
        int r   = (i >> 3) & 127;
        int c   = i & 7;
        uint32_t dst = sbase + mat * GMAT + r * GSTRIDE + c * 16;
        const __nv_bfloat16* m =
            (mat == 0) ? Ahi : (mat == 1) ? Alo : (mat == 2) ? Bhi : Blo;
        int gr = ((mat < 2) ? row0 : col0) + r;
        cpa16(dst, m + (size_t)gr * EMB_ + k0 + c * 8);
    }
    CPA_COMMIT();
}

__global__ __launch_bounds__(256) void gemm_mma_kernel(
    const float* __restrict__ bq, const float* __restrict__ bk,
    const float* __restrict__ bv, float* __restrict__ outp, int mode)
{
    extern __shared__ char smem[];
    const uint32_t sb = smem_u32(smem);
    const int tid = threadIdx.x, wid = tid >> 5, lane = tid & 31;
    const int row0 = blockIdx.y * 128, col0 = blockIdx.x * 128;
    const int z = blockIdx.z;

    const __nv_bfloat16 *Ahi, *Alo, *Bhi, *Blo;
    const float* bias;
    if (mode == 0) {
        Ahi = g_xhi; Alo = g_xlo;
        Bhi = g_whi + (size_t)z * EMB_ * EMB_;
        Blo = g_wlo + (size_t)z * EMB_ * EMB_;
        bias = (z == 0) ? bq : (z == 1) ? bk : bv;
    } else {
        Ahi = g_ahi; Alo = g_alo;
        Bhi = g_whi + (size_t)3 * EMB_ * EMB_;
        Blo = g_wlo + (size_t)3 * EMB_ * EMB_;
        bias = bq;
    }

    const int wm = (wid & 1) * 64;
    const int wn = (wid >> 1) * 32;

    float c[4][4][4] = {};

    gload_chunk(sb + 0 * GSTAGE, Ahi, Alo, Bhi, Blo, row0, col0, 0,  tid);
    gload_chunk(sb + 1 * GSTAGE, Ahi, Alo, Bhi, Blo, row0, col0, 64, tid);

    const int a_row = wm + (lane & 7) + ((lane >> 3) & 1) * 8;
    const int a_kc  = ((lane >> 4) & 1) * 8;
    const int b_row = wn + (lane & 7) + ((lane >> 4) & 1) * 8;
    const int b_kc  = ((lane >> 3) & 1) * 8;

    int stage = 0;
    for (int ch = 0; ch < 16; ++ch) {
        CPA_WAIT1();            // chunk ch resident
        __syncthreads();        // all warps past compute of ch-1
        // prefetch ch+2 into the stage compute ch-1 just vacated
        if (ch + 2 < 16) {
            int ps = stage + 2; if (ps >= 3) ps -= 3;
            gload_chunk(sb + ps * GSTAGE, Ahi, Alo, Bhi, Blo,
                        row0, col0, (ch + 2) * 64, tid);
        } else {
            CPA_COMMIT();       // keep group count in lockstep
        }
        const uint32_t st = sb + stage * GSTAGE;

        #pragma unroll
        for (int kk = 0; kk < 64; kk += 16) {
            uint32_t bh[2][4], bl[2][4];
            #pragma unroll
            for (int pt = 0; pt < 2; ++pt) {
                uint32_t addr = st + 2 * GMAT + (b_row + pt * 16) * GSTRIDE
                              + (kk + b_kc) * 2;
                LDSM4(bh[pt][0], bh[pt][1], bh[pt][2], bh[pt][3], addr);
                LDSM4(bl[pt][0], bl[pt][1], bl[pt][2], bl[pt][3], addr + GMAT);
            }
            #pragma unroll
            for (int mt = 0; mt < 4; ++mt) {
                uint32_t addr = st + (a_row + mt * 16) * GSTRIDE
                              + (kk + a_kc) * 2;
                uint32_t ah[4], al[4];
                LDSM4(ah[0], ah[1], ah[2], ah[3], addr);
                LDSM4(al[0], al[1], al[2], al[3], addr + GMAT);
                #pragma unroll
                for (int nt = 0; nt < 4; ++nt) {
                    const int pt = nt >> 1, hf = (nt & 1) * 2;
                    MMA16816(c[mt][nt], ah, bh[pt][hf], bh[pt][hf + 1]);
                    MMA16816(c[mt][nt], ah, bl[pt][hf], bl[pt][hf + 1]);
                    MMA16816(c[mt][nt], al, bh[pt][hf], bh[pt][hf + 1]);
                }
            }
        }
        if (++stage == 3) stage = 0;
    }

    const float oscale = (mode == 0 && z == 0) ? QSCALE : 1.0f;
    #pragma unroll
    for (int mt = 0; mt < 4; ++mt) {
        #pragma unroll
        for (int nt = 0; nt < 4; ++nt) {
            int r = row0 + wm + mt * 16 + (lane >> 2);
            int n = col0 + wn + nt * 8 + (lane & 3) * 2;
            float2 bv2 = *(const float2*)&bias[n];
            float p0 = (c[mt][nt][0] + bv2.x) * oscale;
            float p1 = (c[mt][nt][1] + bv2.y) * oscale;
            float p2 = (c[mt][nt][2] + bv2.x) * oscale;
            float p3 = (c[mt][nt][3] + bv2.y) * oscale;
            if (mode == 0) {
                __nv_bfloat16 *dh, *dl;
                if (z == 0)      { dh = g_qhi; dl = g_qlo; }
                else if (z == 1) { dh = g_khi; dl = g_klo; }
                else             { dh = g_vhi; dl = g_vlo; }
                int h = n >> 6, d = n & 63;
                int bb0 = r >> 11, s0 = r & 2047;
                int bb1 = (r + 8) >> 11, s1 = (r + 8) & 2047;
                size_t i0 = (((size_t)bb0 * H_ + h) * S_ + s0) * HD_ + d;
                size_t i1 = (((size_t)bb1 * H_ + h) * S_ + s1) * HD_ + d;
                uint32_t h01 = packbf(p0, p1);
                uint32_t l01 = packbf(p0 - bflo(h01), p1 - bfhi(h01));
                uint32_t h23 = packbf(p2, p3);
                uint32_t l23 = packbf(p2 - bflo(h23), p3 - bfhi(h23));
                *(uint32_t*)&dh[i0] = h01; *(uint32_t*)&dl[i0] = l01;
                *(uint32_t*)&dh[i1] = h23; *(uint32_t*)&dl[i1] = l23;
            } else {
                float2 v0 = {p0, p1}, v1 = {p2, p3};
                *(float2*)&outp[(size_t)r * EMB_ + n] = v0;
                *(float2*)&outp[(size_t)(r + 8) * EMB_ + n] = v1;
            }
        }
    }
}

// ---------------- mma.sync causal flash attention (R8 body, scale pre-folded)
constexpr int ASTR   = 144;
constexpr int AQMAT  = 128 * ASTR;                  // 18432
constexpr int AKMAT  = 64 * ASTR;                   // 9216
constexpr int ASTAGE = 4 * AKMAT;                   // 36864
constexpr int ATTN_SMEM = 2 * AQMAT + 2 * ASTAGE;   // 110592 (2 CTAs/SM)

__device__ __forceinline__ void akv_load(
    uint32_t base, const __nv_bfloat16* Kh, const __nv_bfloat16* Kl,
    const __nv_bfloat16* Vh, const __nv_bfloat16* Vl, int kt, int tid)
{
    #pragma unroll
    for (int i = tid; i < 2048; i += 256) {
        int mat = i >> 9;
        int r   = (i >> 3) & 63;
        int c   = i & 7;
        const __nv_bfloat16* m =
            (mat == 0) ? Kh : (mat == 1) ? Kl : (mat == 2) ? Vh : Vl;
        cpa16(base + mat * AKMAT + r * ASTR + c * 16,
              m + (size_t)(kt * 64 + r) * HD_ + c * 8);
    }
}

__global__ __launch_bounds__(256) void attn_mma_kernel()
{
    extern __shared__ char smem[];
    const uint32_t sb = smem_u32(smem);
    const int tid = threadIdx.x, wid = tid >> 5, lane = tid & 31;
    const int qt = (S_ / 128 - 1) - blockIdx.y;   // heavy tiles dispatch first
    const int bh = blockIdx.x;
    const size_t off = (size_t)bh * S_ * HD_;
    const __nv_bfloat16 *Qh = g_qhi + off, *Ql = g_qlo + off;
    const __nv_bfloat16 *Kh = g_khi + off, *Kl = g_klo + off;
    const __nv_bfloat16 *Vh = g_vhi + off, *Vl = g_vlo + off;
    const int ntiles = 2 * qt + 2;

    #pragma unroll
    for (int i = tid; i < 2048; i += 256) {
        int mat = i >> 10, r = (i >> 3) & 127, c = i & 7;
        const __nv_bfloat16* m = mat ? Ql : Qh;
        cpa16(sb + mat * AQMAT + r * ASTR + c * 16,
              m + (size_t)(qt * 128 + r) * HD_ + c * 8);
    }
    akv_load(sb + 2 * AQMAT, Kh, Kl, Vh, Vl, 0, tid);
    CPA_COMMIT();
    akv_load(sb + 2 * AQMAT + ASTAGE, Kh, Kl, Vh, Vl, 1, tid);
    CPA_COMMIT();

    const int a_row = wid * 16 + (lane & 7) + ((lane >> 3) & 1) * 8;
    const int a_kc2 = ((lane >> 4) & 1) * 16;
    const int b_row = (lane & 7) + ((lane >> 4) & 1) * 8;
    const int b_kc2 = ((lane >> 3) & 1) * 16;
    const int v_row = (lane & 7) + ((lane >> 3) & 1) * 8;
    const int v_cc2 = ((lane >> 4) & 1) * 16;
    const int row0g = qt * 128 + wid * 16 + (lane >> 2);

    float O[8][4] = {};
    float m0 = -1e30f, m1 = -1e30f, l0 = 0.0f, l1 = 0.0f;

    for (int kt = 0; kt < ntiles; ++kt) {
        CPA_WAIT1();
        __syncthreads();
        const uint32_t st = sb + 2 * AQMAT + (kt & 1) * ASTAGE;

        // ---- S = Q K^T (3-term split); Q pre-scaled by 0.125*log2e ----
        float S[8][4] = {};
        #pragma unroll
        for (int ks = 0; ks < 4; ++ks) {
            uint32_t qaddr = sb + a_row * ASTR + ks * 32 + a_kc2;
            uint32_t ah[4], al[4];
            LDSM4(ah[0], ah[1], ah[2], ah[3], qaddr);
            LDSM4(al[0], al[1], al[2], al[3], qaddr + AQMAT);
            #pragma unroll
            for (int g = 0; g < 4; ++g) {
                uint32_t kaddr = st + (g * 16 + b_row) * ASTR + ks * 32 + b_kc2;
                uint32_t kh[4], kl[4];
                LDSM4(kh[0], kh[1], kh[2], kh[3], kaddr);
                LDSM4(kl[0], kl[1], kl[2], kl[3], kaddr + AKMAT);
                MMA16816(S[2 * g],     ah, kh[0], kh[1]);
                MMA16816(S[2 * g],     ah, kl[0], kl[1]);
                MMA16816(S[2 * g],     al, kh[0], kh[1]);
                MMA16816(S[2 * g + 1], ah, kh[2], kh[3]);
                MMA16816(S[2 * g + 1], ah, kl[2], kl[3]);
                MMA16816(S[2 * g + 1], al, kh[2], kh[3]);
            }
        }

        // ---- causal mask (scores already in log2 domain) ----
        if (kt * 64 + 63 > qt * 128 + wid * 16) {
            #pragma unroll
            for (int j = 0; j < 8; ++j) {
                int col = kt * 64 + j * 8 + (lane & 3) * 2;
                if (col     > row0g)     S[j][0] = -1e30f;
                if (col + 1 > row0g)     S[j][1] = -1e30f;
                if (col     > row0g + 8) S[j][2] = -1e30f;
                if (col + 1 > row0g + 8) S[j][3] = -1e30f;
            }
        }

        // ---- online softmax ----
        float mx0 = -1e30f, mx1 = -1e30f;
        #pragma unroll
        for (int j = 0; j < 8; ++j) {
            mx0 = fmaxf(mx0, fmaxf(S[j][0], S[j][1]));
            mx1 = fmaxf(mx1, fmaxf(S[j][2], S[j][3]));
        }
        mx0 = fmaxf(mx0, __shfl_xor_sync(0xffffffffu, mx0, 1));
        mx0 = fmaxf(mx0, __shfl_xor_sync(0xffffffffu, mx0, 2));
        mx1 = fmaxf(mx1, __shfl_xor_sync(0xffffffffu, mx1, 1));
        mx1 = fmaxf(mx1, __shfl_xor_sync(0xffffffffu, mx1, 2));
        float nm0 = fmaxf(m0, mx0), nm1 = fmaxf(m1, mx1);
        float f0 = ex2(m0 - nm0), f1 = ex2(m1 - nm1);
        m0 = nm0; m1 = nm1;
        float s0 = 0.0f, s1 = 0.0f;
        #pragma unroll
        for (int j = 0; j < 8; ++j) {
            S[j][0] = ex2(S[j][0] - nm0); S[j][1] = ex2(S[j][1] - nm0);
            S[j][2] = ex2(S[j][2] - nm1); S[j][3] = ex2(S[j][3] - nm1);
            s0 += S[j][0] + S[j][1];
            s1 += S[j][2] + S[j][3];
        }
        s0 += __shfl_xor_sync(0xffffffffu, s0, 1);
        s0 += __shfl_xor_sync(0xffffffffu, s0, 2);
        s1 += __shfl_xor_sync(0xffffffffu, s1, 1);
        s1 += __shfl_xor_sync(0xffffffffu, s1, 2);
        l0 = l0 * f0 + s0; l1 = l1 * f1 + s1;
        #pragma unroll
        for (int j = 0; j < 8; ++j) {
            O[j][0] *= f0; O[j][1] *= f0; O[j][2] *= f1; O[j][3] *= f1;
        }

        // ---- O += P V (3-term split) ----
        #pragma unroll
        for (int ks = 0; ks < 4; ++ks) {
            uint32_t ph[4], pl[4];
            ph[0] = packbf(S[2 * ks][0],     S[2 * ks][1]);
            ph[1] = packbf(S[2 * ks][2],     S[2 * ks][3]);
            ph[2] = packbf(S[2 * ks + 1][0], S[2 * ks + 1][1]);
            ph[3] = packbf(S[2 * ks + 1][2], S[2 * ks + 1][3]);
            pl[0] = packbf(S[2 * ks][0]     - bflo(ph[0]), S[2 * ks][1]     - bfhi(ph[0]));
            pl[1] = packbf(S[2 * ks][2]     - bflo(ph[1]), S[2 * ks][3]     - bfhi(ph[1]));
            pl[2] = packbf(S[2 * ks + 1][0] - bflo(ph[2]), S[2 * ks + 1][1] - bfhi(ph[2]));
            pl[3] = packbf(S[2 * ks + 1][2] - bflo(ph[3]), S[2 * ks + 1][3] - bfhi(ph[3]));
            #pragma unroll
            for (int g = 0; g < 4; ++g) {
                uint32_t vaddr = st + 2 * AKMAT + (ks * 16 + v_row) * ASTR
                               + g * 32 + v_cc2;
                uint32_t vh[4], vl[4];
                LDSM4T(vh[0], vh[1], vh[2], vh[3], vaddr);
                LDSM4T(vl[0], vl[1], vl[2], vl[3], vaddr + AKMAT);
                MMA16816(O[2 * g],     ph, vh[0], vh[1]);
                MMA16816(O[2 * g],     ph, vl[0], vl[1]);
                MMA16816(O[2 * g],     pl, vh[0], vh[1]);
                MMA16816(O[2 * g + 1], ph, vh[2], vh[3]);
                MMA16816(O[2 * g + 1], ph, vl[2], vl[3]);
                MMA16816(O[2 * g + 1], pl, vh[2], vh[3]);
            }
        }

        __syncthreads();
        if (kt + 2 < ntiles) {
            akv_load(sb + 2 * AQMAT + (kt & 1) * ASTAGE, Kh, Kl, Vh, Vl, kt + 2, tid);
            CPA_COMMIT();
        } else {
            CPA_COMMIT();
        }
    }

    // ---- epilogue: normalize, split bf16 hi/lo, write [B,S,EMB] ----
    const float inv0 = 1.0f / l0, inv1 = 1.0f / l1;
    const int b = bh >> 4, h = bh & 15;
    const int r0 = qt * 128 + wid * 16 + (lane >> 2);
    const int cc = (lane & 3) * 2;
    #pragma unroll
    for (int j = 0; j < 8; ++j) {
        float p0 = O[j][0] * inv0, p1 = O[j][1] * inv0;
        float p2 = O[j][2] * inv1, p3 = O[j][3] * inv1;
        size_t i0 = ((size_t)b * S_ + r0) * EMB_ + h * 64 + j * 8 + cc;
        size_t i1 = i0 + (size_t)8 * EMB_;
        uint32_t h01 = packbf(p0, p1);
        uint32_t l01 = packbf(p0 - bflo(h01), p1 - bfhi(h01));
        uint32_t h23 = packbf(p2, p3);
        uint32_t l23 = packbf(p2 - bflo(h23), p3 - bfhi(h23));
        *(uint32_t*)&g_ahi[i0] = h01; *(uint32_t*)&g_alo[i0] = l01;
        *(uint32_t*)&g_ahi[i1] = h23; *(uint32_t*)&g_alo[i1] = l23;
    }
}

// ---------------- launch ---------------------------------------------------
extern "C" void kernel_launch(void* const* d_in, const int* in_sizes, int n_in,
                              void* d_out, int out_size)
{
    const float* x  = (const float*)d_in[0];
    const float* Wq = (const float*)d_in[1];
    const float* bq = (const float*)d_in[2];
    const float* Wk = (const float*)d_in[3];
    const float* bk = (const float*)d_in[4];
    const float* Wv = (const float*)d_in[5];
    const float* bv = (const float*)d_in[6];
    const float* Wo = (const float*)d_in[7];
    const float* bo = (const float*)d_in[8];
    float* out = (float*)d_out;

    cudaFuncSetAttribute(gemm_mma_kernel,
                         cudaFuncAttributeMaxDynamicSharedMemorySize, GEMM_SMEM);
    cudaFuncSetAttribute(attn_mma_kernel,
                         cudaFuncAttributeMaxDynamicSharedMemorySize, ATTN_SMEM);

    const int n4x = M_ * EMB_ / 4;
    const int n4w = EMB_ * EMB_ / 4;
    conv_split_x<<<n4x / 256, 256>>>(x, n4x);
    conv_split_w<<<dim3(n4w / 256, 4), 256>>>(Wq, Wk, Wv, Wo);

    // QKV projections (mma.sync, 3-stage pipeline) -> bf16 hi/lo Q/K/V
    gemm_mma_kernel<<<dim3(EMB_ / 128, M_ / 128, 3), 256, GEMM_SMEM>>>(
        bq, bk, bv, nullptr, 0);

    // causal attention (mma.sync flash, heavy-tiles-first dispatch)
    attn_mma_kernel<<<dim3(B_ * H_, S_ / 128), 256, ATTN_SMEM>>>();

    // output projection (mma.sync, 3-stage pipeline)
    gemm_mma_kernel<<<dim3(EMB_ / 128, M_ / 128, 1), 256, GEMM_SMEM>>>(
        bo, nullptr, nullptr, out, 1);
}

// round 11
// speedup vs baseline: 1.3428x; 1.3096x over previous
#include <cuda_runtime.h>
#include <cuda_fp16.h>
#include <math.h>
#include <stdint.h>

#define B_   4
#define S_   2048
#define EMB_ 1024
#define H_   16
#define HD_  64
#define M_   (B_ * S_)   // 8192

// ---- ptx helpers (mma.sync / ldmatrix / cp.async) — baseline sm_103 legal --
__device__ __forceinline__ uint32_t smem_u32(const void* p) {
    uint32_t a;
    asm("{ .reg .u64 t; cvta.to.shared.u64 t, %1; cvt.u32.u64 %0, t; }"
        : "=r"(a) : "l"(p));
    return a;
}
__device__ __forceinline__ void cpa16(uint32_t dst, const void* src) {
    asm volatile("cp.async.cg.shared.global [%0], [%1], 16;" :: "r"(dst), "l"(src) : "memory");
}
#define CPA_COMMIT() asm volatile("cp.async.commit_group;" ::: "memory")
#define CPA_WAIT1()  asm volatile("cp.async.wait_group 1;"  ::: "memory")

#define LDSM4(r0, r1, r2, r3, addr) \
    asm volatile("ldmatrix.sync.aligned.m8n8.x4.shared.b16 {%0,%1,%2,%3}, [%4];" \
        : "=r"(r0), "=r"(r1), "=r"(r2), "=r"(r3) : "r"(addr))
#define LDSM4T(r0, r1, r2, r3, addr) \
    asm volatile("ldmatrix.sync.aligned.m8n8.x4.trans.shared.b16 {%0,%1,%2,%3}, [%4];" \
        : "=r"(r0), "=r"(r1), "=r"(r2), "=r"(r3) : "r"(addr))

#define MMAH16816(c, a, b0, b1) \
    asm volatile("mma.sync.aligned.m16n8k16.row.col.f32.f16.f16.f32 " \
        "{%0,%1,%2,%3},{%4,%5,%6,%7},{%8,%9},{%0,%1,%2,%3};" \
        : "+f"((c)[0]), "+f"((c)[1]), "+f"((c)[2]), "+f"((c)[3]) \
        : "r"((a)[0]), "r"((a)[1]), "r"((a)[2]), "r"((a)[3]), "r"(b0), "r"(b1))

__device__ __forceinline__ uint32_t packh2(float lo, float hi) {
    __half2 h = __floats2half2_rn(lo, hi);
    return *(uint32_t*)&h;
}
__device__ __forceinline__ float h2lo(uint32_t p) {
    __half2 h = *(__half2*)&p; return __low2float(h);
}
__device__ __forceinline__ float h2hi(uint32_t p) {
    __half2 h = *(__half2*)&p; return __high2float(h);
}
__device__ __forceinline__ float ex2(float x) {
    float r; asm("ex2.approx.f32 %0, %1;" : "=f"(r) : "f"(x)); return r;
}

// softmax scale folded into Q at projection time: 1/sqrt(64) * log2(e)
#define QSCALE (0.125f * 1.44269504f)

// ---------------- scratch (device globals; no allocation allowed) ----------
__device__ __align__(16) __half g_xhi[(size_t)M_ * EMB_];
__device__ __align__(16) __half g_xlo[(size_t)M_ * EMB_];
__device__ __align__(16) __half g_wh [(size_t)4 * EMB_ * EMB_];   // weights: fp16 hi only
__device__ __align__(16) __half g_qhi[(size_t)M_ * EMB_];
__device__ __align__(16) __half g_qlo[(size_t)M_ * EMB_];
__device__ __align__(16) __half g_kh [(size_t)M_ * EMB_];          // K: hi only
__device__ __align__(16) __half g_vh [(size_t)M_ * EMB_];          // V: hi only
__device__ __align__(16) __half g_ahi[(size_t)M_ * EMB_];
__device__ __align__(16) __half g_alo[(size_t)M_ * EMB_];

// ---------------- fp32 -> fp16 hi/lo split (x) / fp16 round (weights) -------
__global__ __launch_bounds__(256) void conv_split_x(
    const float* __restrict__ src, int n4)
{
    int i = blockIdx.x * 256 + threadIdx.x;
    if (i >= n4) return;
    float4 v = ((const float4*)src)[i];
    uint32_t h01 = packh2(v.x, v.y), h23 = packh2(v.z, v.w);
    uint32_t l01 = packh2(v.x - h2lo(h01), v.y - h2hi(h01));
    uint32_t l23 = packh2(v.z - h2lo(h23), v.w - h2hi(h23));
    ((uint32_t*)g_xhi)[2 * i] = h01; ((uint32_t*)g_xhi)[2 * i + 1] = h23;
    ((uint32_t*)g_xlo)[2 * i] = l01; ((uint32_t*)g_xlo)[2 * i + 1] = l23;
}
__global__ __launch_bounds__(256) void conv_w(
    const float* __restrict__ w0, const float* __restrict__ w1,
    const float* __restrict__ w2, const float* __restrict__ w3)
{
    const int which = blockIdx.y;
    const float* src = (which == 0) ? w0 : (which == 1) ? w1 : (which == 2) ? w2 : w3;
    __half* hi = g_wh + (size_t)which * EMB_ * EMB_;
    int i = blockIdx.x * 256 + threadIdx.x;
    float4 v = ((const float4*)src)[i];
    ((uint32_t*)hi)[2 * i]     = packh2(v.x, v.y);
    ((uint32_t*)hi)[2 * i + 1] = packh2(v.z, v.w);
}

// ---------------- mma.sync GEMM: D = A @ W^T + bias --------------------------
// fp16 2-term: D = Ah*Wh + Al*Wh. 3-stage cp.async, one barrier per K-chunk.
constexpr int GSTRIDE = 144;
constexpr int GMAT    = 128 * GSTRIDE;             // 18432
constexpr int GSTAGE  = 3 * GMAT;                  // 55296 (Ahi, Alo, Bh)
constexpr int GEMM_SMEM = 3 * GSTAGE;              // 165888

__device__ __forceinline__ void gload_chunk(
    uint32_t sbase, const __half* Ahi, const __half* Alo, const __half* Bh,
    int row0, int col0, int k0, int tid)
{
    #pragma unroll
    for (int i = tid; i < 3072; i += 256) {
        int mat = i >> 10;                 // 0=Ahi, 1=Alo, 2=Bh
        int r   = (i >> 3) & 127;
        int c   = i & 7;
        uint32_t dst = sbase + mat * GMAT + r * GSTRIDE + c * 16;
        const __half* m = (mat == 0) ? Ahi : (mat == 1) ? Alo : Bh;
        int gr = ((mat < 2) ? row0 : col0) + r;
        cpa16(dst, m + (size_t)gr * EMB_ + k0 + c * 8);
    }
    CPA_COMMIT();
}

__global__ __launch_bounds__(256) void gemm_mma_kernel(
    const float* __restrict__ bq, const float* __restrict__ bk,
    const float* __restrict__ bv, float* __restrict__ outp, int mode)
{
    extern __shared__ char smem[];
    const uint32_t sb = smem_u32(smem);
    const int tid = threadIdx.x, wid = tid >> 5, lane = tid & 31;
    const int row0 = blockIdx.y * 128, col0 = blockIdx.x * 128;
    const int z = blockIdx.z;

    const __half *Ahi, *Alo, *Bh;
    const float* bias;
    if (mode == 0) {
        Ahi = g_xhi; Alo = g_xlo;
        Bh  = g_wh + (size_t)z * EMB_ * EMB_;
        bias = (z == 0) ? bq : (z == 1) ? bk : bv;
    } else {
        Ahi = g_ahi; Alo = g_alo;
        Bh  = g_wh + (size_t)3 * EMB_ * EMB_;
        bias = bq;
    }

    const int wm = (wid & 1) * 64;
    const int wn = (wid >> 1) * 32;

    float c[4][4][4] = {};

    gload_chunk(sb + 0 * GSTAGE, Ahi, Alo, Bh, row0, col0, 0,  tid);
    gload_chunk(sb + 1 * GSTAGE, Ahi, Alo, Bh, row0, col0, 64, tid);

    const int a_row = wm + (lane & 7) + ((lane >> 3) & 1) * 8;
    const int a_kc  = ((lane >> 4) & 1) * 8;
    const int b_row = wn + (lane & 7) + ((lane >> 4) & 1) * 8;
    const int b_kc  = ((lane >> 3) & 1) * 8;

    int stage = 0;
    for (int ch = 0; ch < 16; ++ch) {
        CPA_WAIT1();
        __syncthreads();
        if (ch + 2 < 16) {
            int ps = stage + 2; if (ps >= 3) ps -= 3;
            gload_chunk(sb + ps * GSTAGE, Ahi, Alo, Bh,
                        row0, col0, (ch + 2) * 64, tid);
        } else {
            CPA_COMMIT();
        }
        const uint32_t st = sb + stage * GSTAGE;

        #pragma unroll
        for (int kk = 0; kk < 64; kk += 16) {
            uint32_t bhf[2][4];
            #pragma unroll
            for (int pt = 0; pt < 2; ++pt) {
                uint32_t addr = st + 2 * GMAT + (b_row + pt * 16) * GSTRIDE
                              + (kk + b_kc) * 2;
                LDSM4(bhf[pt][0], bhf[pt][1], bhf[pt][2], bhf[pt][3], addr);
            }
            #pragma unroll
            for (int mt = 0; mt < 4; ++mt) {
                uint32_t addr = st + (a_row + mt * 16) * GSTRIDE
                              + (kk + a_kc) * 2;
                uint32_t ah[4], al[4];
                LDSM4(ah[0], ah[1], ah[2], ah[3], addr);
                LDSM4(al[0], al[1], al[2], al[3], addr + GMAT);
                #pragma unroll
                for (int nt = 0; nt < 4; ++nt) {
                    const int pt = nt >> 1, hf = (nt & 1) * 2;
                    MMAH16816(c[mt][nt], ah, bhf[pt][hf], bhf[pt][hf + 1]);
                    MMAH16816(c[mt][nt], al, bhf[pt][hf], bhf[pt][hf + 1]);
                }
            }
        }
        if (++stage == 3) stage = 0;
    }

    #pragma unroll
    for (int mt = 0; mt < 4; ++mt) {
        #pragma unroll
        for (int nt = 0; nt < 4; ++nt) {
            int r = row0 + wm + mt * 16 + (lane >> 2);
            int n = col0 + wn + nt * 8 + (lane & 3) * 2;
            float2 bv2 = *(const float2*)&bias[n];
            float p0 = c[mt][nt][0] + bv2.x, p1 = c[mt][nt][1] + bv2.y;
            float p2 = c[mt][nt][2] + bv2.x, p3 = c[mt][nt][3] + bv2.y;
            if (mode == 0) {
                int h = n >> 6, d = n & 63;
                int bb0 = r >> 11, s0 = r & 2047;
                int bb1 = (r + 8) >> 11, s1 = (r + 8) & 2047;
                size_t i0 = (((size_t)bb0 * H_ + h) * S_ + s0) * HD_ + d;
                size_t i1 = (((size_t)bb1 * H_ + h) * S_ + s1) * HD_ + d;
                if (z == 0) {
                    // Q: pre-scale and split hi/lo
                    p0 *= QSCALE; p1 *= QSCALE; p2 *= QSCALE; p3 *= QSCALE;
                    uint32_t h01 = packh2(p0, p1);
                    uint32_t l01 = packh2(p0 - h2lo(h01), p1 - h2hi(h01));
                    uint32_t h23 = packh2(p2, p3);
                    uint32_t l23 = packh2(p2 - h2lo(h23), p3 - h2hi(h23));
                    *(uint32_t*)&g_qhi[i0] = h01; *(uint32_t*)&g_qlo[i0] = l01;
                    *(uint32_t*)&g_qhi[i1] = h23; *(uint32_t*)&g_qlo[i1] = l23;
                } else {
                    __half* dh = (z == 1) ? g_kh : g_vh;
                    *(uint32_t*)&dh[i0] = packh2(p0, p1);
                    *(uint32_t*)&dh[i1] = packh2(p2, p3);
                }
            } else {
                float2 v0 = {p0, p1}, v1 = {p2, p3};
                *(float2*)&outp[(size_t)r * EMB_ + n] = v0;
                *(float2*)&outp[(size_t)(r + 8) * EMB_ + n] = v1;
            }
        }
    }
}

// ---------------- mma.sync causal flash attention (fp16 2-term) -------------
constexpr int ASTR   = 144;
constexpr int AQMAT  = 128 * ASTR;                  // 18432
constexpr int AKMAT  = 64 * ASTR;                   // 9216
constexpr int ASTAGE = 2 * AKMAT;                   // 18432 (Kh, Vh)
constexpr int ATTN_SMEM = 2 * AQMAT + 2 * ASTAGE;   // 73728 (2+ CTAs/SM)

__device__ __forceinline__ void akv_load(
    uint32_t base, const __half* Kh, const __half* Vh, int kt, int tid)
{
    #pragma unroll
    for (int i = tid; i < 1024; i += 256) {
        int mat = i >> 9;                  // 0=Kh, 1=Vh
        int r   = (i >> 3) & 63;
        int c   = i & 7;
        const __half* m = mat ? Vh : Kh;
        cpa16(base + mat * AKMAT + r * ASTR + c * 16,
              m + (size_t)(kt * 64 + r) * HD_ + c * 8);
    }
}

__global__ __launch_bounds__(256) void attn_mma_kernel()
{
    extern __shared__ char smem[];
    const uint32_t sb = smem_u32(smem);
    const int tid = threadIdx.x, wid = tid >> 5, lane = tid & 31;
    const int qt = (S_ / 128 - 1) - blockIdx.y;   // heavy tiles dispatch first
    const int bh = blockIdx.x;
    const size_t off = (size_t)bh * S_ * HD_;
    const __half *Qh = g_qhi + off, *Ql = g_qlo + off;
    const __half *Kh = g_kh + off, *Vh = g_vh + off;
    const int ntiles = 2 * qt + 2;

    #pragma unroll
    for (int i = tid; i < 2048; i += 256) {
        int mat = i >> 10, r = (i >> 3) & 127, c = i & 7;
        const __half* m = mat ? Ql : Qh;
        cpa16(sb + mat * AQMAT + r * ASTR + c * 16,
              m + (size_t)(qt * 128 + r) * HD_ + c * 8);
    }
    akv_load(sb + 2 * AQMAT, Kh, Vh, 0, tid);
    CPA_COMMIT();
    akv_load(sb + 2 * AQMAT + ASTAGE, Kh, Vh, 1, tid);
    CPA_COMMIT();

    const int a_row = wid * 16 + (lane & 7) + ((lane >> 3) & 1) * 8;
    const int a_kc2 = ((lane >> 4) & 1) * 16;
    const int b_row = (lane & 7) + ((lane >> 4) & 1) * 8;
    const int b_kc2 = ((lane >> 3) & 1) * 16;
    const int v_row = (lane & 7) + ((lane >> 3) & 1) * 8;
    const int v_cc2 = ((lane >> 4) & 1) * 16;
    const int row0g = qt * 128 + wid * 16 + (lane >> 2);

    float O[8][4] = {};
    float m0 = -1e30f, m1 = -1e30f, l0 = 0.0f, l1 = 0.0f;

    for (int kt = 0; kt < ntiles; ++kt) {
        CPA_WAIT1();
        __syncthreads();
        const uint32_t st = sb + 2 * AQMAT + (kt & 1) * ASTAGE;

        // ---- S = Q K^T (fp16 2-term: Qh*Kh + Ql*Kh); Q pre-scaled ----
        float S[8][4] = {};
        #pragma unroll
        for (int ks = 0; ks < 4; ++ks) {
            uint32_t qaddr = sb + a_row * ASTR + ks * 32 + a_kc2;
            uint32_t ah[4], al[4];
            LDSM4(ah[0], ah[1], ah[2], ah[3], qaddr);
            LDSM4(al[0], al[1], al[2], al[3], qaddr + AQMAT);
            #pragma unroll
            for (int g = 0; g < 4; ++g) {
                uint32_t kaddr = st + (g * 16 + b_row) * ASTR + ks * 32 + b_kc2;
                uint32_t kh[4];
                LDSM4(kh[0], kh[1], kh[2], kh[3], kaddr);
                MMAH16816(S[2 * g],     ah, kh[0], kh[1]);
                MMAH16816(S[2 * g],     al, kh[0], kh[1]);
                MMAH16816(S[2 * g + 1], ah, kh[2], kh[3]);
                MMAH16816(S[2 * g + 1], al, kh[2], kh[3]);
            }
        }

        // ---- causal mask (scores already in log2 domain) ----
        if (kt * 64 + 63 > qt * 128 + wid * 16) {
            #pragma unroll
            for (int j = 0; j < 8; ++j) {
                int col = kt * 64 + j * 8 + (lane & 3) * 2;
                if (col     > row0g)     S[j][0] = -1e30f;
                if (col + 1 > row0g)     S[j][1] = -1e30f;
                if (col     > row0g + 8) S[j][2] = -1e30f;
                if (col + 1 > row0g + 8) S[j][3] = -1e30f;
            }
        }

        // ---- online softmax ----
        float mx0 = -1e30f, mx1 = -1e30f;
        #pragma unroll
        for (int j = 0; j < 8; ++j) {
            mx0 = fmaxf(mx0, fmaxf(S[j][0], S[j][1]));
            mx1 = fmaxf(mx1, fmaxf(S[j][2], S[j][3]));
        }
        mx0 = fmaxf(mx0, __shfl_xor_sync(0xffffffffu, mx0, 1));
        mx0 = fmaxf(mx0, __shfl_xor_sync(0xffffffffu, mx0, 2));
        mx1 = fmaxf(mx1, __shfl_xor_sync(0xffffffffu, mx1, 1));
        mx1 = fmaxf(mx1, __shfl_xor_sync(0xffffffffu, mx1, 2));
        float nm0 = fmaxf(m0, mx0), nm1 = fmaxf(m1, mx1);
        float f0 = ex2(m0 - nm0), f1 = ex2(m1 - nm1);
        m0 = nm0; m1 = nm1;
        float s0 = 0.0f, s1 = 0.0f;
        #pragma unroll
        for (int j = 0; j < 8; ++j) {
            S[j][0] = ex2(S[j][0] - nm0); S[j][1] = ex2(S[j][1] - nm0);
            S[j][2] = ex2(S[j][2] - nm1); S[j][3] = ex2(S[j][3] - nm1);
            s0 += S[j][0] + S[j][1];
            s1 += S[j][2] + S[j][3];
        }
        s0 += __shfl_xor_sync(0xffffffffu, s0, 1);
        s0 += __shfl_xor_sync(0xffffffffu, s0, 2);
        s1 += __shfl_xor_sync(0xffffffffu, s1, 1);
        s1 += __shfl_xor_sync(0xffffffffu, s1, 2);
        l0 = l0 * f0 + s0; l1 = l1 * f1 + s1;
        #pragma unroll
        for (int j = 0; j < 8; ++j) {
            O[j][0] *= f0; O[j][1] *= f0; O[j][2] *= f1; O[j][3] *= f1;
        }

        // ---- O += P V (fp16 2-term: Ph*Vh + Pl*Vh) ----
        #pragma unroll
        for (int ks = 0; ks < 4; ++ks) {
            uint32_t ph[4], pl[4];
            ph[0] = packh2(S[2 * ks][0],     S[2 * ks][1]);
            ph[1] = packh2(S[2 * ks][2],     S[2 * ks][3]);
            ph[2] = packh2(S[2 * ks + 1][0], S[2 * ks + 1][1]);
            ph[3] = packh2(S[2 * ks + 1][2], S[2 * ks + 1][3]);
            pl[0] = packh2(S[2 * ks][0]     - h2lo(ph[0]), S[2 * ks][1]     - h2hi(ph[0]));
            pl[1] = packh2(S[2 * ks][2]     - h2lo(ph[1]), S[2 * ks][3]     - h2hi(ph[1]));
            pl[2] = packh2(S[2 * ks + 1][0] - h2lo(ph[2]), S[2 * ks + 1][1] - h2hi(ph[2]));
            pl[3] = packh2(S[2 * ks + 1][2] - h2lo(ph[3]), S[2 * ks + 1][3] - h2hi(ph[3]));
            #pragma unroll
            for (int g = 0; g < 4; ++g) {
                uint32_t vaddr = st + AKMAT + (ks * 16 + v_row) * ASTR
                               + g * 32 + v_cc2;
                uint32_t vh[4];
                LDSM4T(vh[0], vh[1], vh[2], vh[3], vaddr);
                MMAH16816(O[2 * g],     ph, vh[0], vh[1]);
                MMAH16816(O[2 * g],     pl, vh[0], vh[1]);
                MMAH16816(O[2 * g + 1], ph, vh[2], vh[3]);
                MMAH16816(O[2 * g + 1], pl, vh[2], vh[3]);
            }
        }

        __syncthreads();
        if (kt + 2 < ntiles) {
            akv_load(sb + 2 * AQMAT + (kt & 1) * ASTAGE, Kh, Vh, kt + 2, tid);
            CPA_COMMIT();
        } else {
            CPA_COMMIT();
        }
    }

    // ---- epilogue: normalize, split fp16 hi/lo, write [B,S,EMB] ----
    const float inv0 = 1.0f / l0, inv1 = 1.0f / l1;
    const int b = bh >> 4, h = bh & 15;
    const int r0 = qt * 128 + wid * 16 + (lane >> 2);
    const int cc = (lane & 3) * 2;
    #pragma unroll
    for (int j = 0; j < 8; ++j) {
        float p0 = O[j][0] * inv0, p1 = O[j][1] * inv0;
        float p2 = O[j][2] * inv1, p3 = O[j][3] * inv1;
        size_t i0 = ((size_t)b * S_ + r0) * EMB_ + h * 64 + j * 8 + cc;
        size_t i1 = i0 + (size_t)8 * EMB_;
        uint32_t h01 = packh2(p0, p1);
        uint32_t l01 = packh2(p0 - h2lo(h01), p1 - h2hi(h01));
        uint32_t h23 = packh2(p2, p3);
        uint32_t l23 = packh2(p2 - h2lo(h23), p3 - h2hi(h23));
        *(uint32_t*)&g_ahi[i0] = h01; *(uint32_t*)&g_alo[i0] = l01;
        *(uint32_t*)&g_ahi[i1] = h23; *(uint32_t*)&g_alo[i1] = l23;
    }
}

// ---------------- launch ---------------------------------------------------
extern "C" void kernel_launch(void* const* d_in, const int* in_sizes, int n_in,
                              void* d_out, int out_size)
{
    const float* x  = (const float*)d_in[0];
    const float* Wq = (const float*)d_in[1];
    const float* bq = (const float*)d_in[2];
    const float* Wk = (const float*)d_in[3];
    const float* bk = (const float*)d_in[4];
    const float* Wv = (const float*)d_in[5];
    const float* bv = (const float*)d_in[6];
    const float* Wo = (const float*)d_in[7];
    const float* bo = (const float*)d_in[8];
    float* out = (float*)d_out;

    cudaFuncSetAttribute(gemm_mma_kernel,
                         cudaFuncAttributeMaxDynamicSharedMemorySize, GEMM_SMEM);
    cudaFuncSetAttribute(attn_mma_kernel,
                         cudaFuncAttributeMaxDynamicSharedMemorySize, ATTN_SMEM);

    const int n4x = M_ * EMB_ / 4;
    const int n4w = EMB_ * EMB_ / 4;
    conv_split_x<<<n4x / 256, 256>>>(x, n4x);
    conv_w<<<dim3(n4w / 256, 4), 256>>>(Wq, Wk, Wv, Wo);

    // QKV projections (fp16 2-term mma.sync) -> Q hi/lo, K hi, V hi
    gemm_mma_kernel<<<dim3(EMB_ / 128, M_ / 128, 3), 256, GEMM_SMEM>>>(
        bq, bk, bv, nullptr, 0);

    // causal attention (fp16 2-term mma.sync flash)
    attn_mma_kernel<<<dim3(B_ * H_, S_ / 128), 256, ATTN_SMEM>>>();

    // output projection (fp16 2-term mma.sync)
    gemm_mma_kernel<<<dim3(EMB_ / 128, M_ / 128, 1), 256, GEMM_SMEM>>>(
        bo, nullptr, nullptr, out, 1);
}

// round 12
// speedup vs baseline: 1.4898x; 1.1095x over previous
#include <cuda_runtime.h>
#include <cuda_fp16.h>
#include <math.h>
#include <stdint.h>

#define B_   4
#define S_   2048
#define EMB_ 1024
#define H_   16
#define HD_  64
#define M_   (B_ * S_)   // 8192

// ---- ptx helpers (mma.sync / ldmatrix / cp.async) — baseline sm_103 legal --
__device__ __forceinline__ uint32_t smem_u32(const void* p) {
    uint32_t a;
    asm("{ .reg .u64 t; cvta.to.shared.u64 t, %1; cvt.u32.u64 %0, t; }"
        : "=r"(a) : "l"(p));
    return a;
}
__device__ __forceinline__ void cpa16(uint32_t dst, const void* src) {
    asm volatile("cp.async.cg.shared.global [%0], [%1], 16;" :: "r"(dst), "l"(src) : "memory");
}
#define CPA_COMMIT() asm volatile("cp.async.commit_group;" ::: "memory")
#define CPA_WAIT1()  asm volatile("cp.async.wait_group 1;"  ::: "memory")

#define LDSM4(r0, r1, r2, r3, addr) \
    asm volatile("ldmatrix.sync.aligned.m8n8.x4.shared.b16 {%0,%1,%2,%3}, [%4];" \
        : "=r"(r0), "=r"(r1), "=r"(r2), "=r"(r3) : "r"(addr))
#define LDSM4T(r0, r1, r2, r3, addr) \
    asm volatile("ldmatrix.sync.aligned.m8n8.x4.trans.shared.b16 {%0,%1,%2,%3}, [%4];" \
        : "=r"(r0), "=r"(r1), "=r"(r2), "=r"(r3) : "r"(addr))

#define MMAH16816(c, a, b0, b1) \
    asm volatile("mma.sync.aligned.m16n8k16.row.col.f32.f16.f16.f32 " \
        "{%0,%1,%2,%3},{%4,%5,%6,%7},{%8,%9},{%0,%1,%2,%3};" \
        : "+f"((c)[0]), "+f"((c)[1]), "+f"((c)[2]), "+f"((c)[3]) \
        : "r"((a)[0]), "r"((a)[1]), "r"((a)[2]), "r"((a)[3]), "r"(b0), "r"(b1))

__device__ __forceinline__ uint32_t packh2(float lo, float hi) {
    __half2 h = __floats2half2_rn(lo, hi);
    return *(uint32_t*)&h;
}
__device__ __forceinline__ float h2lo(uint32_t p) {
    __half2 h = *(__half2*)&p; return __low2float(h);
}
__device__ __forceinline__ float h2hi(uint32_t p) {
    __half2 h = *(__half2*)&p; return __high2float(h);
}
__device__ __forceinline__ float ex2(float x) {
    float r; asm("ex2.approx.f32 %0, %1;" : "=f"(r) : "f"(x)); return r;
}

// softmax scale folded into Q at projection time: 1/sqrt(64) * log2(e)
#define QSCALE (0.125f * 1.44269504f)

// ---------------- scratch (device globals; no allocation allowed) ----------
__device__ __align__(16) __half g_xhi[(size_t)M_ * EMB_];
__device__ __align__(16) __half g_xlo[(size_t)M_ * EMB_];
__device__ __align__(16) __half g_wh [(size_t)4 * EMB_ * EMB_];   // weights: fp16
__device__ __align__(16) __half g_qhi[(size_t)M_ * EMB_];
__device__ __align__(16) __half g_qlo[(size_t)M_ * EMB_];
__device__ __align__(16) __half g_kh [(size_t)M_ * EMB_];
__device__ __align__(16) __half g_vh [(size_t)M_ * EMB_];
__device__ __align__(16) __half g_ahi[(size_t)M_ * EMB_];
__device__ __align__(16) __half g_alo[(size_t)M_ * EMB_];

// ---------------- fp32 -> fp16 hi/lo split (x) / fp16 round (weights) -------
__global__ __launch_bounds__(256) void conv_split_x(
    const float* __restrict__ src, int n4)
{
    int i = blockIdx.x * 256 + threadIdx.x;
    if (i >= n4) return;
    float4 v = ((const float4*)src)[i];
    uint32_t h01 = packh2(v.x, v.y), h23 = packh2(v.z, v.w);
    uint32_t l01 = packh2(v.x - h2lo(h01), v.y - h2hi(h01));
    uint32_t l23 = packh2(v.z - h2lo(h23), v.w - h2hi(h23));
    ((uint32_t*)g_xhi)[2 * i] = h01; ((uint32_t*)g_xhi)[2 * i + 1] = h23;
    ((uint32_t*)g_xlo)[2 * i] = l01; ((uint32_t*)g_xlo)[2 * i + 1] = l23;
}
__global__ __launch_bounds__(256) void conv_w(
    const float* __restrict__ w0, const float* __restrict__ w1,
    const float* __restrict__ w2, const float* __restrict__ w3)
{
    const int which = blockIdx.y;
    const float* src = (which == 0) ? w0 : (which == 1) ? w1 : (which == 2) ? w2 : w3;
    __half* hi = g_wh + (size_t)which * EMB_ * EMB_;
    int i = blockIdx.x * 256 + threadIdx.x;
    float4 v = ((const float4*)src)[i];
    ((uint32_t*)hi)[2 * i]     = packh2(v.x, v.y);
    ((uint32_t*)hi)[2 * i + 1] = packh2(v.z, v.w);
}

// ---------------- mma.sync GEMM: D = A @ W^T + bias --------------------------
// fp16 2-term: D = Ah*Wh + Al*Wh. 2-stage cp.async, 2 CTAs/SM.
constexpr int GSTRIDE = 144;
constexpr int GMAT    = 128 * GSTRIDE;             // 18432
constexpr int GSTAGE  = 3 * GMAT;                  // 55296 (Ahi, Alo, Bh)
constexpr int GEMM_SMEM = 2 * GSTAGE;              // 110592 -> 2 CTAs/SM

__device__ __forceinline__ void gload_chunk(
    uint32_t sbase, const __half* Ahi, const __half* Alo, const __half* Bh,
    int row0, int col0, int k0, int tid)
{
    #pragma unroll
    for (int i = tid; i < 3072; i += 256) {
        int mat = i >> 10;                 // 0=Ahi, 1=Alo, 2=Bh
        int r   = (i >> 3) & 127;
        int c   = i & 7;
        uint32_t dst = sbase + mat * GMAT + r * GSTRIDE + c * 16;
        const __half* m = (mat == 0) ? Ahi : (mat == 1) ? Alo : Bh;
        int gr = ((mat < 2) ? row0 : col0) + r;
        cpa16(dst, m + (size_t)gr * EMB_ + k0 + c * 8);
    }
    CPA_COMMIT();
}

__global__ __launch_bounds__(256, 2) void gemm_mma_kernel(
    const float* __restrict__ bq, const float* __restrict__ bk,
    const float* __restrict__ bv, float* __restrict__ outp, int mode)
{
    extern __shared__ char smem[];
    const uint32_t sb = smem_u32(smem);
    const int tid = threadIdx.x, wid = tid >> 5, lane = tid & 31;
    const int row0 = blockIdx.y * 128, col0 = blockIdx.x * 128;
    const int z = blockIdx.z;

    const __half *Ahi, *Alo, *Bh;
    const float* bias;
    if (mode == 0) {
        Ahi = g_xhi; Alo = g_xlo;
        Bh  = g_wh + (size_t)z * EMB_ * EMB_;
        bias = (z == 0) ? bq : (z == 1) ? bk : bv;
    } else {
        Ahi = g_ahi; Alo = g_alo;
        Bh  = g_wh + (size_t)3 * EMB_ * EMB_;
        bias = bq;
    }

    const int wm = (wid & 1) * 64;
    const int wn = (wid >> 1) * 32;

    float c[4][4][4] = {};

    gload_chunk(sb + 0 * GSTAGE, Ahi, Alo, Bh, row0, col0, 0,  tid);
    gload_chunk(sb + 1 * GSTAGE, Ahi, Alo, Bh, row0, col0, 64, tid);

    const int a_row = wm + (lane & 7) + ((lane >> 3) & 1) * 8;
    const int a_kc  = ((lane >> 4) & 1) * 8;
    const int b_row = wn + (lane & 7) + ((lane >> 4) & 1) * 8;
    const int b_kc  = ((lane >> 3) & 1) * 8;

    for (int ch = 0; ch < 16; ++ch) {
        const int s = ch & 1;
        CPA_WAIT1();
        __syncthreads();
        const uint32_t st = sb + s * GSTAGE;

        #pragma unroll
        for (int kk = 0; kk < 64; kk += 16) {
            uint32_t bhf[2][4];
            #pragma unroll
            for (int pt = 0; pt < 2; ++pt) {
                uint32_t addr = st + 2 * GMAT + (b_row + pt * 16) * GSTRIDE
                              + (kk + b_kc) * 2;
                LDSM4(bhf[pt][0], bhf[pt][1], bhf[pt][2], bhf[pt][3], addr);
            }
            #pragma unroll
            for (int mt = 0; mt < 4; ++mt) {
                uint32_t addr = st + (a_row + mt * 16) * GSTRIDE
                              + (kk + a_kc) * 2;
                uint32_t ah[4], al[4];
                LDSM4(ah[0], ah[1], ah[2], ah[3], addr);
                LDSM4(al[0], al[1], al[2], al[3], addr + GMAT);
                #pragma unroll
                for (int nt = 0; nt < 4; ++nt) {
                    const int pt = nt >> 1, hf = (nt & 1) * 2;
                    MMAH16816(c[mt][nt], ah, bhf[pt][hf], bhf[pt][hf + 1]);
                    MMAH16816(c[mt][nt], al, bhf[pt][hf], bhf[pt][hf + 1]);
                }
            }
        }
        __syncthreads();
        if (ch + 2 < 16)
            gload_chunk(sb + s * GSTAGE, Ahi, Alo, Bh,
                        row0, col0, (ch + 2) * 64, tid);
        else
            CPA_COMMIT();
    }

    #pragma unroll
    for (int mt = 0; mt < 4; ++mt) {
        #pragma unroll
        for (int nt = 0; nt < 4; ++nt) {
            int r = row0 + wm + mt * 16 + (lane >> 2);
            int n = col0 + wn + nt * 8 + (lane & 3) * 2;
            float2 bv2 = *(const float2*)&bias[n];
            float p0 = c[mt][nt][0] + bv2.x, p1 = c[mt][nt][1] + bv2.y;
            float p2 = c[mt][nt][2] + bv2.x, p3 = c[mt][nt][3] + bv2.y;
            if (mode == 0) {
                int h = n >> 6, d = n & 63;
                int bb0 = r >> 11, s0 = r & 2047;
                int bb1 = (r + 8) >> 11, s1 = (r + 8) & 2047;
                size_t i0 = (((size_t)bb0 * H_ + h) * S_ + s0) * HD_ + d;
                size_t i1 = (((size_t)bb1 * H_ + h) * S_ + s1) * HD_ + d;
                if (z == 0) {
                    p0 *= QSCALE; p1 *= QSCALE; p2 *= QSCALE; p3 *= QSCALE;
                    uint32_t h01 = packh2(p0, p1);
                    uint32_t l01 = packh2(p0 - h2lo(h01), p1 - h2hi(h01));
                    uint32_t h23 = packh2(p2, p3);
                    uint32_t l23 = packh2(p2 - h2lo(h23), p3 - h2hi(h23));
                    *(uint32_t*)&g_qhi[i0] = h01; *(uint32_t*)&g_qlo[i0] = l01;
                    *(uint32_t*)&g_qhi[i1] = h23; *(uint32_t*)&g_qlo[i1] = l23;
                } else {
                    __half* dh = (z == 1) ? g_kh : g_vh;
                    *(uint32_t*)&dh[i0] = packh2(p0, p1);
                    *(uint32_t*)&dh[i1] = packh2(p2, p3);
                }
            } else {
                float2 v0 = {p0, p1}, v1 = {p2, p3};
                *(float2*)&outp[(size_t)r * EMB_ + n] = v0;
                *(float2*)&outp[(size_t)(r + 8) * EMB_ + n] = v1;
            }
        }
    }
}

// ---------------- mma.sync causal flash attention (fp16 2-term) -------------
constexpr int ASTR   = 144;
constexpr int AQMAT  = 128 * ASTR;                  // 18432
constexpr int AKMAT  = 64 * ASTR;                   // 9216
constexpr int ASTAGE = 2 * AKMAT;                   // 18432 (Kh, Vh)
constexpr int ATTN_SMEM = 2 * AQMAT + 2 * ASTAGE;   // 73728 (2 CTAs/SM)

__device__ __forceinline__ void akv_load(
    uint32_t base, const __half* Kh, const __half* Vh, int kt, int tid)
{
    #pragma unroll
    for (int i = tid; i < 1024; i += 256) {
        int mat = i >> 9;                  // 0=Kh, 1=Vh
        int r   = (i >> 3) & 63;
        int c   = i & 7;
        const __half* m = mat ? Vh : Kh;
        cpa16(base + mat * AKMAT + r * ASTR + c * 16,
              m + (size_t)(kt * 64 + r) * HD_ + c * 8);
    }
}

__global__ __launch_bounds__(256) void attn_mma_kernel()
{
    extern __shared__ char smem[];
    const uint32_t sb = smem_u32(smem);
    const int tid = threadIdx.x, wid = tid >> 5, lane = tid & 31;
    const int qt = (S_ / 128 - 1) - blockIdx.y;   // heavy tiles dispatch first
    const int bh = blockIdx.x;
    const size_t off = (size_t)bh * S_ * HD_;
    const __half *Qh = g_qhi + off, *Ql = g_qlo + off;
    const __half *Kh = g_kh + off, *Vh = g_vh + off;
    const int ntiles = 2 * qt + 2;

    #pragma unroll
    for (int i = tid; i < 2048; i += 256) {
        int mat = i >> 10, r = (i >> 3) & 127, c = i & 7;
        const __half* m = mat ? Ql : Qh;
        cpa16(sb + mat * AQMAT + r * ASTR + c * 16,
              m + (size_t)(qt * 128 + r) * HD_ + c * 8);
    }
    akv_load(sb + 2 * AQMAT, Kh, Vh, 0, tid);
    CPA_COMMIT();
    akv_load(sb + 2 * AQMAT + ASTAGE, Kh, Vh, 1, tid);
    CPA_COMMIT();

    const int a_row = wid * 16 + (lane & 7) + ((lane >> 3) & 1) * 8;
    const int a_kc2 = ((lane >> 4) & 1) * 16;
    const int b_row = (lane & 7) + ((lane >> 4) & 1) * 8;
    const int b_kc2 = ((lane >> 3) & 1) * 16;
    const int v_row = (lane & 7) + ((lane >> 3) & 1) * 8;
    const int v_cc2 = ((lane >> 4) & 1) * 16;
    const int row0g = qt * 128 + wid * 16 + (lane >> 2);

    float O[8][4] = {};
    float m0 = -1e30f, m1 = -1e30f, l0 = 0.0f, l1 = 0.0f;

    for (int kt = 0; kt < ntiles; ++kt) {
        CPA_WAIT1();
        __syncthreads();
        const uint32_t st = sb + 2 * AQMAT + (kt & 1) * ASTAGE;

        // ---- S = Q K^T (fp16 2-term: Qh*Kh + Ql*Kh); Q pre-scaled ----
        float S[8][4] = {};
        #pragma unroll
        for (int ks = 0; ks < 4; ++ks) {
            uint32_t qaddr = sb + a_row * ASTR + ks * 32 + a_kc2;
            uint32_t ah[4], al[4];
            LDSM4(ah[0], ah[1], ah[2], ah[3], qaddr);
            LDSM4(al[0], al[1], al[2], al[3], qaddr + AQMAT);
            #pragma unroll
            for (int g = 0; g < 4; ++g) {
                uint32_t kaddr = st + (g * 16 + b_row) * ASTR + ks * 32 + b_kc2;
                uint32_t kh[4];
                LDSM4(kh[0], kh[1], kh[2], kh[3], kaddr);
                MMAH16816(S[2 * g],     ah, kh[0], kh[1]);
                MMAH16816(S[2 * g],     al, kh[0], kh[1]);
                MMAH16816(S[2 * g + 1], ah, kh[2], kh[3]);
                MMAH16816(S[2 * g + 1], al, kh[2], kh[3]);
            }
        }

        // ---- causal mask (scores already in log2 domain) ----
        if (kt * 64 + 63 > qt * 128 + wid * 16) {
            #pragma unroll
            for (int j = 0; j < 8; ++j) {
                int col = kt * 64 + j * 8 + (lane & 3) * 2;
                if (col     > row0g)     S[j][0] = -1e30f;
                if (col + 1 > row0g)     S[j][1] = -1e30f;
                if (col     > row0g + 8) S[j][2] = -1e30f;
                if (col + 1 > row0g + 8) S[j][3] = -1e30f;
            }
        }

        // ---- online softmax ----
        float mx0 = -1e30f, mx1 = -1e30f;
        #pragma unroll
        for (int j = 0; j < 8; ++j) {
            mx0 = fmaxf(mx0, fmaxf(S[j][0], S[j][1]));
            mx1 = fmaxf(mx1, fmaxf(S[j][2], S[j][3]));
        }
        mx0 = fmaxf(mx0, __shfl_xor_sync(0xffffffffu, mx0, 1));
        mx0 = fmaxf(mx0, __shfl_xor_sync(0xffffffffu, mx0, 2));
        mx1 = fmaxf(mx1, __shfl_xor_sync(0xffffffffu, mx1, 1));
        mx1 = fmaxf(mx1, __shfl_xor_sync(0xffffffffu, mx1, 2));
        float nm0 = fmaxf(m0, mx0), nm1 = fmaxf(m1, mx1);
        float f0 = ex2(m0 - nm0), f1 = ex2(m1 - nm1);
        m0 = nm0; m1 = nm1;
        float s0 = 0.0f, s1 = 0.0f;
        #pragma unroll
        for (int j = 0; j < 8; ++j) {
            S[j][0] = ex2(S[j][0] - nm0); S[j][1] = ex2(S[j][1] - nm0);
            S[j][2] = ex2(S[j][2] - nm1); S[j][3] = ex2(S[j][3] - nm1);
            s0 += S[j][0] + S[j][1];
            s1 += S[j][2] + S[j][3];
        }
        s0 += __shfl_xor_sync(0xffffffffu, s0, 1);
        s0 += __shfl_xor_sync(0xffffffffu, s0, 2);
        s1 += __shfl_xor_sync(0xffffffffu, s1, 1);
        s1 += __shfl_xor_sync(0xffffffffu, s1, 2);
        l0 = l0 * f0 + s0; l1 = l1 * f1 + s1;
        #pragma unroll
        for (int j = 0; j < 8; ++j) {
            O[j][0] *= f0; O[j][1] *= f0; O[j][2] *= f1; O[j][3] *= f1;
        }

        // ---- O += P V (fp16 2-term: Ph*Vh + Pl*Vh) ----
        #pragma unroll
        for (int ks = 0; ks < 4; ++ks) {
            uint32_t ph[4], pl[4];
            ph[0] = packh2(S[2 * ks][0],     S[2 * ks][1]);
            ph[1] = packh2(S[2 * ks][2],     S[2 * ks][3]);
            ph[2] = packh2(S[2 * ks + 1][0], S[2 * ks + 1][1]);
            ph[3] = packh2(S[2 * ks + 1][2], S[2 * ks + 1][3]);
            pl[0] = packh2(S[2 * ks][0]     - h2lo(ph[0]), S[2 * ks][1]     - h2hi(ph[0]));
            pl[1] = packh2(S[2 * ks][2]     - h2lo(ph[1]), S[2 * ks][3]     - h2hi(ph[1]));
            pl[2] = packh2(S[2 * ks + 1][0] - h2lo(ph[2]), S[2 * ks + 1][1] - h2hi(ph[2]));
            pl[3] = packh2(S[2 * ks + 1][2] - h2lo(ph[3]), S[2 * ks + 1][3] - h2hi(ph[3]));
            #pragma unroll
            for (int g = 0; g < 4; ++g) {
                uint32_t vaddr = st + AKMAT + (ks * 16 + v_row) * ASTR
                               + g * 32 + v_cc2;
                uint32_t vh[4];
                LDSM4T(vh[0], vh[1], vh[2], vh[3], vaddr);
                MMAH16816(O[2 * g],     ph, vh[0], vh[1]);
                MMAH16816(O[2 * g],     pl, vh[0], vh[1]);
                MMAH16816(O[2 * g + 1], ph, vh[2], vh[3]);
                MMAH16816(O[2 * g + 1], pl, vh[2], vh[3]);
            }
        }

        __syncthreads();
        if (kt + 2 < ntiles) {
            akv_load(sb + 2 * AQMAT + (kt & 1) * ASTAGE, Kh, Vh, kt + 2, tid);
            CPA_COMMIT();
        } else {
            CPA_COMMIT();
        }
    }

    // ---- epilogue: normalize, split fp16 hi/lo, write [B,S,EMB] ----
    const float inv0 = 1.0f / l0, inv1 = 1.0f / l1;
    const int b = bh >> 4, h = bh & 15;
    const int r0 = qt * 128 + wid * 16 + (lane >> 2);
    const int cc = (lane & 3) * 2;
    #pragma unroll
    for (int j = 0; j < 8; ++j) {
        float p0 = O[j][0] * inv0, p1 = O[j][1] * inv0;
        float p2 = O[j][2] * inv1, p3 = O[j][3] * inv1;
        size_t i0 = ((size_t)b * S_ + r0) * EMB_ + h * 64 + j * 8 + cc;
        size_t i1 = i0 + (size_t)8 * EMB_;
        uint32_t h01 = packh2(p0, p1);
        uint32_t l01 = packh2(p0 - h2lo(h01), p1 - h2hi(h01));
        uint32_t h23 = packh2(p2, p3);
        uint32_t l23 = packh2(p2 - h2lo(h23), p3 - h2hi(h23));
        *(uint32_t*)&g_ahi[i0] = h01; *(uint32_t*)&g_alo[i0] = l01;
        *(uint32_t*)&g_ahi[i1] = h23; *(uint32_t*)&g_alo[i1] = l23;
    }
}

// ---------------- launch ---------------------------------------------------
extern "C" void kernel_launch(void* const* d_in, const int* in_sizes, int n_in,
                              void* d_out, int out_size)
{
    const float* x  = (const float*)d_in[0];
    const float* Wq = (const float*)d_in[1];
    const float* bq = (const float*)d_in[2];
    const float* Wk = (const float*)d_in[3];
    const float* bk = (const float*)d_in[4];
    const float* Wv = (const float*)d_in[5];
    const float* bv = (const float*)d_in[6];
    const float* Wo = (const float*)d_in[7];
    const float* bo = (const float*)d_in[8];
    float* out = (float*)d_out;

    cudaFuncSetAttribute(gemm_mma_kernel,
                         cudaFuncAttributeMaxDynamicSharedMemorySize, GEMM_SMEM);
    cudaFuncSetAttribute(attn_mma_kernel,
                         cudaFuncAttributeMaxDynamicSharedMemorySize, ATTN_SMEM);

    const int n4x = M_ * EMB_ / 4;
    const int n4w = EMB_ * EMB_ / 4;
    conv_split_x<<<n4x / 256, 256>>>(x, n4x);
    conv_w<<<dim3(n4w / 256, 4), 256>>>(Wq, Wk, Wv, Wo);

    // QKV projections (fp16 2-term mma.sync, 2 CTAs/SM) -> Q hi/lo, K, V
    gemm_mma_kernel<<<dim3(EMB_ / 128, M_ / 128, 3), 256, GEMM_SMEM>>>(
        bq, bk, bv, nullptr, 0);

    // causal attention (fp16 2-term mma.sync flash)
    attn_mma_kernel<<<dim3(B_ * H_, S_ / 128), 256, ATTN_SMEM>>>();

    // output projection (fp16 2-term mma.sync, 2 CTAs/SM)
    gemm_mma_kernel<<<dim3(EMB_ / 128, M_ / 128, 1), 256, GEMM_SMEM>>>(
        bo, nullptr, nullptr, out, 1);
}

// round 13
// speedup vs baseline: 1.5147x; 1.0167x over previous
#include <cuda_runtime.h>
#include <cuda_fp16.h>
#include <math.h>
#include <stdint.h>

#define B_   4
#define S_   2048
#define EMB_ 1024
#define H_   16
#define HD_  64
#define M_   (B_ * S_)   // 8192

// ---- ptx helpers (mma.sync / ldmatrix / cp.async) — baseline sm_103 legal --
__device__ __forceinline__ uint32_t smem_u32(const void* p) {
    uint32_t a;
    asm("{ .reg .u64 t; cvta.to.shared.u64 t, %1; cvt.u32.u64 %0, t; }"
        : "=r"(a) : "l"(p));
    return a;
}
__device__ __forceinline__ void cpa16(uint32_t dst, const void* src) {
    asm volatile("cp.async.cg.shared.global [%0], [%1], 16;" :: "r"(dst), "l"(src) : "memory");
}
#define CPA_COMMIT() asm volatile("cp.async.commit_group;" ::: "memory")
#define CPA_WAIT1()  asm volatile("cp.async.wait_group 1;"  ::: "memory")

#define LDSM4(r0, r1, r2, r3, addr) \
    asm volatile("ldmatrix.sync.aligned.m8n8.x4.shared.b16 {%0,%1,%2,%3}, [%4];" \
        : "=r"(r0), "=r"(r1), "=r"(r2), "=r"(r3) : "r"(addr))
#define LDSM4T(r0, r1, r2, r3, addr) \
    asm volatile("ldmatrix.sync.aligned.m8n8.x4.trans.shared.b16 {%0,%1,%2,%3}, [%4];" \
        : "=r"(r0), "=r"(r1), "=r"(r2), "=r"(r3) : "r"(addr))

#define MMAH16816(c, a, b0, b1) \
    asm volatile("mma.sync.aligned.m16n8k16.row.col.f32.f16.f16.f32 " \
        "{%0,%1,%2,%3},{%4,%5,%6,%7},{%8,%9},{%0,%1,%2,%3};" \
        : "+f"((c)[0]), "+f"((c)[1]), "+f"((c)[2]), "+f"((c)[3]) \
        : "r"((a)[0]), "r"((a)[1]), "r"((a)[2]), "r"((a)[3]), "r"(b0), "r"(b1))

__device__ __forceinline__ uint32_t packh2(float lo, float hi) {
    __half2 h = __floats2half2_rn(lo, hi);
    return *(uint32_t*)&h;
}
__device__ __forceinline__ float h2lo(uint32_t p) {
    __half2 h = *(__half2*)&p; return __low2float(h);
}
__device__ __forceinline__ float h2hi(uint32_t p) {
    __half2 h = *(__half2*)&p; return __high2float(h);
}
__device__ __forceinline__ float ex2(float x) {
    float r; asm("ex2.approx.f32 %0, %1;" : "=f"(r) : "f"(x)); return r;
}

// softmax scale folded into Q at projection time: 1/sqrt(64) * log2(e)
#define QSCALE (0.125f * 1.44269504f)

// ---------------- scratch (device globals; no allocation allowed) ----------
__device__ __align__(16) __half g_xhi[(size_t)M_ * EMB_];
__device__ __align__(16) __half g_xlo[(size_t)M_ * EMB_];
__device__ __align__(16) __half g_wh [(size_t)4 * EMB_ * EMB_];   // weights: fp16
__device__ __align__(16) __half g_qhi[(size_t)M_ * EMB_];
__device__ __align__(16) __half g_qlo[(size_t)M_ * EMB_];
__device__ __align__(16) __half g_kh [(size_t)M_ * EMB_];
__device__ __align__(16) __half g_vh [(size_t)M_ * EMB_];
__device__ __align__(16) __half g_ahi[(size_t)M_ * EMB_];
__device__ __align__(16) __half g_alo[(size_t)M_ * EMB_];

// ---------------- fp32 -> fp16 hi/lo split (x) / fp16 round (weights) -------
__global__ __launch_bounds__(256) void conv_split_x(
    const float* __restrict__ src, int n4)
{
    int i = blockIdx.x * 256 + threadIdx.x;
    if (i >= n4) return;
    float4 v = ((const float4*)src)[i];
    uint32_t h01 = packh2(v.x, v.y), h23 = packh2(v.z, v.w);
    uint32_t l01 = packh2(v.x - h2lo(h01), v.y - h2hi(h01));
    uint32_t l23 = packh2(v.z - h2lo(h23), v.w - h2hi(h23));
    ((uint32_t*)g_xhi)[2 * i] = h01; ((uint32_t*)g_xhi)[2 * i + 1] = h23;
    ((uint32_t*)g_xlo)[2 * i] = l01; ((uint32_t*)g_xlo)[2 * i + 1] = l23;
}
__global__ __launch_bounds__(256) void conv_w(
    const float* __restrict__ w0, const float* __restrict__ w1,
    const float* __restrict__ w2, const float* __restrict__ w3)
{
    const int which = blockIdx.y;
    const float* src = (which == 0) ? w0 : (which == 1) ? w1 : (which == 2) ? w2 : w3;
    __half* hi = g_wh + (size_t)which * EMB_ * EMB_;
    int i = blockIdx.x * 256 + threadIdx.x;
    float4 v = ((const float4*)src)[i];
    ((uint32_t*)hi)[2 * i]     = packh2(v.x, v.y);
    ((uint32_t*)hi)[2 * i + 1] = packh2(v.z, v.w);
}

// ---------------- mma.sync GEMM: D = A @ W^T + bias (R12 config, frozen) -----
constexpr int GSTRIDE = 144;
constexpr int GMAT    = 128 * GSTRIDE;             // 18432
constexpr int GSTAGE  = 3 * GMAT;                  // 55296 (Ahi, Alo, Bh)
constexpr int GEMM_SMEM = 2 * GSTAGE;              // 110592 -> 2 CTAs/SM

__device__ __forceinline__ void gload_chunk(
    uint32_t sbase, const __half* Ahi, const __half* Alo, const __half* Bh,
    int row0, int col0, int k0, int tid)
{
    #pragma unroll
    for (int i = tid; i < 3072; i += 256) {
        int mat = i >> 10;                 // 0=Ahi, 1=Alo, 2=Bh
        int r   = (i >> 3) & 127;
        int c   = i & 7;
        uint32_t dst = sbase + mat * GMAT + r * GSTRIDE + c * 16;
        const __half* m = (mat == 0) ? Ahi : (mat == 1) ? Alo : Bh;
        int gr = ((mat < 2) ? row0 : col0) + r;
        cpa16(dst, m + (size_t)gr * EMB_ + k0 + c * 8);
    }
    CPA_COMMIT();
}

__global__ __launch_bounds__(256, 2) void gemm_mma_kernel(
    const float* __restrict__ bq, const float* __restrict__ bk,
    const float* __restrict__ bv, float* __restrict__ outp, int mode)
{
    extern __shared__ char smem[];
    const uint32_t sb = smem_u32(smem);
    const int tid = threadIdx.x, wid = tid >> 5, lane = tid & 31;
    const int row0 = blockIdx.y * 128, col0 = blockIdx.x * 128;
    const int z = blockIdx.z;

    const __half *Ahi, *Alo, *Bh;
    const float* bias;
    if (mode == 0) {
        Ahi = g_xhi; Alo = g_xlo;
        Bh  = g_wh + (size_t)z * EMB_ * EMB_;
        bias = (z == 0) ? bq : (z == 1) ? bk : bv;
    } else {
        Ahi = g_ahi; Alo = g_alo;
        Bh  = g_wh + (size_t)3 * EMB_ * EMB_;
        bias = bq;
    }

    const int wm = (wid & 1) * 64;
    const int wn = (wid >> 1) * 32;

    float c[4][4][4] = {};

    gload_chunk(sb + 0 * GSTAGE, Ahi, Alo, Bh, row0, col0, 0,  tid);
    gload_chunk(sb + 1 * GSTAGE, Ahi, Alo, Bh, row0, col0, 64, tid);

    const int a_row = wm + (lane & 7) + ((lane >> 3) & 1) * 8;
    const int a_kc  = ((lane >> 4) & 1) * 8;
    const int b_row = wn + (lane & 7) + ((lane >> 4) & 1) * 8;
    const int b_kc  = ((lane >> 3) & 1) * 8;

    for (int ch = 0; ch < 16; ++ch) {
        const int s = ch & 1;
        CPA_WAIT1();
        __syncthreads();
        const uint32_t st = sb + s * GSTAGE;

        #pragma unroll
        for (int kk = 0; kk < 64; kk += 16) {
            uint32_t bhf[2][4];
            #pragma unroll
            for (int pt = 0; pt < 2; ++pt) {
                uint32_t addr = st + 2 * GMAT + (b_row + pt * 16) * GSTRIDE
                              + (kk + b_kc) * 2;
                LDSM4(bhf[pt][0], bhf[pt][1], bhf[pt][2], bhf[pt][3], addr);
            }
            #pragma unroll
            for (int mt = 0; mt < 4; ++mt) {
                uint32_t addr = st + (a_row + mt * 16) * GSTRIDE
                              + (kk + a_kc) * 2;
                uint32_t ah[4], al[4];
                LDSM4(ah[0], ah[1], ah[2], ah[3], addr);
                LDSM4(al[0], al[1], al[2], al[3], addr + GMAT);
                #pragma unroll
                for (int nt = 0; nt < 4; ++nt) {
                    const int pt = nt >> 1, hf = (nt & 1) * 2;
                    MMAH16816(c[mt][nt], ah, bhf[pt][hf], bhf[pt][hf + 1]);
                    MMAH16816(c[mt][nt], al, bhf[pt][hf], bhf[pt][hf + 1]);
                }
            }
        }
        __syncthreads();
        if (ch + 2 < 16)
            gload_chunk(sb + s * GSTAGE, Ahi, Alo, Bh,
                        row0, col0, (ch + 2) * 64, tid);
        else
            CPA_COMMIT();
    }

    #pragma unroll
    for (int mt = 0; mt < 4; ++mt) {
        #pragma unroll
        for (int nt = 0; nt < 4; ++nt) {
            int r = row0 + wm + mt * 16 + (lane >> 2);
            int n = col0 + wn + nt * 8 + (lane & 3) * 2;
            float2 bv2 = *(const float2*)&bias[n];
            float p0 = c[mt][nt][0] + bv2.x, p1 = c[mt][nt][1] + bv2.y;
            float p2 = c[mt][nt][2] + bv2.x, p3 = c[mt][nt][3] + bv2.y;
            if (mode == 0) {
                int h = n >> 6, d = n & 63;
                int bb0 = r >> 11, s0 = r & 2047;
                int bb1 = (r + 8) >> 11, s1 = (r + 8) & 2047;
                size_t i0 = (((size_t)bb0 * H_ + h) * S_ + s0) * HD_ + d;
                size_t i1 = (((size_t)bb1 * H_ + h) * S_ + s1) * HD_ + d;
                if (z == 0) {
                    p0 *= QSCALE; p1 *= QSCALE; p2 *= QSCALE; p3 *= QSCALE;
                    uint32_t h01 = packh2(p0, p1);
                    uint32_t l01 = packh2(p0 - h2lo(h01), p1 - h2hi(h01));
                    uint32_t h23 = packh2(p2, p3);
                    uint32_t l23 = packh2(p2 - h2lo(h23), p3 - h2hi(h23));
                    *(uint32_t*)&g_qhi[i0] = h01; *(uint32_t*)&g_qlo[i0] = l01;
                    *(uint32_t*)&g_qhi[i1] = h23; *(uint32_t*)&g_qlo[i1] = l23;
                } else {
                    __half* dh = (z == 1) ? g_kh : g_vh;
                    *(uint32_t*)&dh[i0] = packh2(p0, p1);
                    *(uint32_t*)&dh[i1] = packh2(p2, p3);
                }
            } else {
                float2 v0 = {p0, p1}, v1 = {p2, p3};
                *(float2*)&outp[(size_t)r * EMB_ + n] = v0;
                *(float2*)&outp[(size_t)(r + 8) * EMB_ + n] = v1;
            }
        }
    }
}

// ---------------- mma.sync causal flash attention (fp16, 128-key stages) ----
constexpr int ASTR   = 144;
constexpr int AQMAT  = 128 * ASTR;                  // 18432
constexpr int AKMAT  = 128 * ASTR;                  // 18432 (128 keys/stage)
constexpr int ASTAGE = 2 * AKMAT;                   // 36864 (Kh, Vh)
constexpr int ATTN_SMEM = 2 * AQMAT + 2 * ASTAGE;   // 110592 -> 2 CTAs/SM

__device__ __forceinline__ void akv_load(
    uint32_t base, const __half* Kh, const __half* Vh, int kt, int tid)
{
    #pragma unroll
    for (int i = tid; i < 2048; i += 256) {
        int mat = i >> 10;                 // 0=Kh, 1=Vh
        int r   = (i >> 3) & 127;
        int c   = i & 7;
        const __half* m = mat ? Vh : Kh;
        cpa16(base + mat * AKMAT + r * ASTR + c * 16,
              m + (size_t)(kt * 128 + r) * HD_ + c * 8);
    }
}

__global__ __launch_bounds__(256, 2) void attn_mma_kernel()
{
    extern __shared__ char smem[];
    const uint32_t sb = smem_u32(smem);
    const int tid = threadIdx.x, wid = tid >> 5, lane = tid & 31;
    const int qt = (S_ / 128 - 1) - blockIdx.y;   // heavy tiles dispatch first
    const int bh = blockIdx.x;
    const size_t off = (size_t)bh * S_ * HD_;
    const __half *Qh = g_qhi + off, *Ql = g_qlo + off;
    const __half *Kh = g_kh + off, *Vh = g_vh + off;
    const int ntiles = qt + 1;                    // 128-key tiles

    #pragma unroll
    for (int i = tid; i < 2048; i += 256) {
        int mat = i >> 10, r = (i >> 3) & 127, c = i & 7;
        const __half* m = mat ? Ql : Qh;
        cpa16(sb + mat * AQMAT + r * ASTR + c * 16,
              m + (size_t)(qt * 128 + r) * HD_ + c * 8);
    }
    akv_load(sb + 2 * AQMAT, Kh, Vh, 0, tid);
    CPA_COMMIT();
    akv_load(sb + 2 * AQMAT + ASTAGE, Kh, Vh, 1, tid);   // rows <256 always valid
    CPA_COMMIT();

    const int a_row = wid * 16 + (lane & 7) + ((lane >> 3) & 1) * 8;
    const int a_kc2 = ((lane >> 4) & 1) * 16;
    const int b_row = (lane & 7) + ((lane >> 4) & 1) * 8;
    const int b_kc2 = ((lane >> 3) & 1) * 16;
    const int v_row = (lane & 7) + ((lane >> 3) & 1) * 8;
    const int v_cc2 = ((lane >> 4) & 1) * 16;
    const int row0g = qt * 128 + wid * 16 + (lane >> 2);

    float O[8][4] = {};
    float m0 = -1e30f, m1 = -1e30f, l0 = 0.0f, l1 = 0.0f;

    for (int kt = 0; kt < ntiles; ++kt) {
        CPA_WAIT1();
        __syncthreads();
        const uint32_t st = sb + 2 * AQMAT + (kt & 1) * ASTAGE;

        // ---- S = Q K^T over 128 keys (fp16 2-term); Q pre-scaled ----
        float S[16][4];
        #pragma unroll
        for (int j = 0; j < 16; ++j) { S[j][0]=0; S[j][1]=0; S[j][2]=0; S[j][3]=0; }
        #pragma unroll
        for (int ks = 0; ks < 4; ++ks) {
            uint32_t qaddr = sb + a_row * ASTR + ks * 32 + a_kc2;
            uint32_t ah[4], al[4];
            LDSM4(ah[0], ah[1], ah[2], ah[3], qaddr);
            LDSM4(al[0], al[1], al[2], al[3], qaddr + AQMAT);
            #pragma unroll
            for (int g = 0; g < 8; ++g) {
                uint32_t kaddr = st + (g * 16 + b_row) * ASTR + ks * 32 + b_kc2;
                uint32_t kh[4];
                LDSM4(kh[0], kh[1], kh[2], kh[3], kaddr);
                MMAH16816(S[2 * g],     ah, kh[0], kh[1]);
                MMAH16816(S[2 * g],     al, kh[0], kh[1]);
                MMAH16816(S[2 * g + 1], ah, kh[2], kh[3]);
                MMAH16816(S[2 * g + 1], al, kh[2], kh[3]);
            }
        }

        // ---- causal mask (only last tile straddles) ----
        if (kt == qt) {
            #pragma unroll
            for (int j = 0; j < 16; ++j) {
                int col = kt * 128 + j * 8 + (lane & 3) * 2;
                if (col     > row0g)     S[j][0] = -1e30f;
                if (col + 1 > row0g)     S[j][1] = -1e30f;
                if (col     > row0g + 8) S[j][2] = -1e30f;
                if (col + 1 > row0g + 8) S[j][3] = -1e30f;
            }
        }

        // ---- online softmax (one pass per 128 keys) ----
        float mx0 = -1e30f, mx1 = -1e30f;
        #pragma unroll
        for (int j = 0; j < 16; ++j) {
            mx0 = fmaxf(mx0, fmaxf(S[j][0], S[j][1]));
            mx1 = fmaxf(mx1, fmaxf(S[j][2], S[j][3]));
        }
        mx0 = fmaxf(mx0, __shfl_xor_sync(0xffffffffu, mx0, 1));
        mx0 = fmaxf(mx0, __shfl_xor_sync(0xffffffffu, mx0, 2));
        mx1 = fmaxf(mx1, __shfl_xor_sync(0xffffffffu, mx1, 1));
        mx1 = fmaxf(mx1, __shfl_xor_sync(0xffffffffu, mx1, 2));
        float nm0 = fmaxf(m0, mx0), nm1 = fmaxf(m1, mx1);
        float f0 = ex2(m0 - nm0), f1 = ex2(m1 - nm1);
        m0 = nm0; m1 = nm1;
        float s0 = 0.0f, s1 = 0.0f;
        #pragma unroll
        for (int j = 0; j < 16; ++j) {
            S[j][0] = ex2(S[j][0] - nm0); S[j][1] = ex2(S[j][1] - nm0);
            S[j][2] = ex2(S[j][2] - nm1); S[j][3] = ex2(S[j][3] - nm1);
            s0 += S[j][0] + S[j][1];
            s1 += S[j][2] + S[j][3];
        }
        s0 += __shfl_xor_sync(0xffffffffu, s0, 1);
        s0 += __shfl_xor_sync(0xffffffffu, s0, 2);
        s1 += __shfl_xor_sync(0xffffffffu, s1, 1);
        s1 += __shfl_xor_sync(0xffffffffu, s1, 2);
        l0 = l0 * f0 + s0; l1 = l1 * f1 + s1;
        #pragma unroll
        for (int j = 0; j < 8; ++j) {
            O[j][0] *= f0; O[j][1] *= f0; O[j][2] *= f1; O[j][3] *= f1;
        }

        // ---- O += P V over 128 keys (fp16 2-term) ----
        #pragma unroll
        for (int ks = 0; ks < 8; ++ks) {
            uint32_t ph[4], pl[4];
            ph[0] = packh2(S[2 * ks][0],     S[2 * ks][1]);
            ph[1] = packh2(S[2 * ks][2],     S[2 * ks][3]);
            ph[2] = packh2(S[2 * ks + 1][0], S[2 * ks + 1][1]);
            ph[3] = packh2(S[2 * ks + 1][2], S[2 * ks + 1][3]);
            pl[0] = packh2(S[2 * ks][0]     - h2lo(ph[0]), S[2 * ks][1]     - h2hi(ph[0]));
            pl[1] = packh2(S[2 * ks][2]     - h2lo(ph[1]), S[2 * ks][3]     - h2hi(ph[1]));
            pl[2] = packh2(S[2 * ks + 1][0] - h2lo(ph[2]), S[2 * ks + 1][1] - h2hi(ph[2]));
            pl[3] = packh2(S[2 * ks + 1][2] - h2lo(ph[3]), S[2 * ks + 1][3] - h2hi(ph[3]));
            #pragma unroll
            for (int g = 0; g < 4; ++g) {
                uint32_t vaddr = st + AKMAT + (ks * 16 + v_row) * ASTR
                               + g * 32 + v_cc2;
                uint32_t vh[4];
                LDSM4T(vh[0], vh[1], vh[2], vh[3], vaddr);
                MMAH16816(O[2 * g],     ph, vh[0], vh[1]);
                MMAH16816(O[2 * g],     pl, vh[0], vh[1]);
                MMAH16816(O[2 * g + 1], ph, vh[2], vh[3]);
                MMAH16816(O[2 * g + 1], pl, vh[2], vh[3]);
            }
        }

        __syncthreads();
        if (kt + 2 < ntiles) {
            akv_load(sb + 2 * AQMAT + (kt & 1) * ASTAGE, Kh, Vh, kt + 2, tid);
            CPA_COMMIT();
        } else {
            CPA_COMMIT();
        }
    }

    // ---- epilogue: normalize, split fp16 hi/lo, write [B,S,EMB] ----
    const float inv0 = 1.0f / l0, inv1 = 1.0f / l1;
    const int b = bh >> 4, h = bh & 15;
    const int r0 = qt * 128 + wid * 16 + (lane >> 2);
    const int cc = (lane & 3) * 2;
    #pragma unroll
    for (int j = 0; j < 8; ++j) {
        float p0 = O[j][0] * inv0, p1 = O[j][1] * inv0;
        float p2 = O[j][2] * inv1, p3 = O[j][3] * inv1;
        size_t i0 = ((size_t)b * S_ + r0) * EMB_ + h * 64 + j * 8 + cc;
        size_t i1 = i0 + (size_t)8 * EMB_;
        uint32_t h01 = packh2(p0, p1);
        uint32_t l01 = packh2(p0 - h2lo(h01), p1 - h2hi(h01));
        uint32_t h23 = packh2(p2, p3);
        uint32_t l23 = packh2(p2 - h2lo(h23), p3 - h2hi(h23));
        *(uint32_t*)&g_ahi[i0] = h01; *(uint32_t*)&g_alo[i0] = l01;
        *(uint32_t*)&g_ahi[i1] = h23; *(uint32_t*)&g_alo[i1] = l23;
    }
}

// ---------------- launch ---------------------------------------------------
extern "C" void kernel_launch(void* const* d_in, const int* in_sizes, int n_in,
                              void* d_out, int out_size)
{
    const float* x  = (const float*)d_in[0];
    const float* Wq = (const float*)d_in[1];
    const float* bq = (const float*)d_in[2];
    const float* Wk = (const float*)d_in[3];
    const float* bk = (const float*)d_in[4];
    const float* Wv = (const float*)d_in[5];
    const float* bv = (const float*)d_in[6];
    const float* Wo = (const float*)d_in[7];
    const float* bo = (const float*)d_in[8];
    float* out = (float*)d_out;

    cudaFuncSetAttribute(gemm_mma_kernel,
                         cudaFuncAttributeMaxDynamicSharedMemorySize, GEMM_SMEM);
    cudaFuncSetAttribute(attn_mma_kernel,
                         cudaFuncAttributeMaxDynamicSharedMemorySize, ATTN_SMEM);

    const int n4x = M_ * EMB_ / 4;
    const int n4w = EMB_ * EMB_ / 4;
    conv_split_x<<<n4x / 256, 256>>>(x, n4x);
    conv_w<<<dim3(n4w / 256, 4), 256>>>(Wq, Wk, Wv, Wo);

    // QKV projections (fp16 2-term mma.sync, 2 CTAs/SM) -> Q hi/lo, K, V
    gemm_mma_kernel<<<dim3(EMB_ / 128, M_ / 128, 3), 256, GEMM_SMEM>>>(
        bq, bk, bv, nullptr, 0);

    // causal attention (fp16 2-term mma.sync flash, 128-key stages)
    attn_mma_kernel<<<dim3(B_ * H_, S_ / 128), 256, ATTN_SMEM>>>();

    // output projection (fp16 2-term mma.sync, 2 CTAs/SM)
    gemm_mma_kernel<<<dim3(EMB_ / 128, M_ / 128, 1), 256, GEMM_SMEM>>>(
        bo, nullptr, nullptr, out, 1);
}

// round 14
// speedup vs baseline: 1.6193x; 1.0691x over previous
#include <cuda_runtime.h>
#include <cuda_fp16.h>
#include <math.h>
#include <stdint.h>

#define B_   4
#define S_   2048
#define EMB_ 1024
#define H_   16
#define HD_  64
#define M_   (B_ * S_)   // 8192

// ---- ptx helpers (mma.sync / ldmatrix / cp.async) — baseline sm_103 legal --
__device__ __forceinline__ uint32_t smem_u32(const void* p) {
    uint32_t a;
    asm("{ .reg .u64 t; cvta.to.shared.u64 t, %1; cvt.u32.u64 %0, t; }"
        : "=r"(a) : "l"(p));
    return a;
}
__device__ __forceinline__ void cpa16(uint32_t dst, const void* src) {
    asm volatile("cp.async.cg.shared.global [%0], [%1], 16;" :: "r"(dst), "l"(src) : "memory");
}
#define CPA_COMMIT() asm volatile("cp.async.commit_group;" ::: "memory")
#define CPA_WAIT1()  asm volatile("cp.async.wait_group 1;"  ::: "memory")

#define LDSM4(r0, r1, r2, r3, addr) \
    asm volatile("ldmatrix.sync.aligned.m8n8.x4.shared.b16 {%0,%1,%2,%3}, [%4];" \
        : "=r"(r0), "=r"(r1), "=r"(r2), "=r"(r3) : "r"(addr))
#define LDSM4T(r0, r1, r2, r3, addr) \
    asm volatile("ldmatrix.sync.aligned.m8n8.x4.trans.shared.b16 {%0,%1,%2,%3}, [%4];" \
        : "=r"(r0), "=r"(r1), "=r"(r2), "=r"(r3) : "r"(addr))

#define MMAH16816(c, a, b0, b1) \
    asm volatile("mma.sync.aligned.m16n8k16.row.col.f32.f16.f16.f32 " \
        "{%0,%1,%2,%3},{%4,%5,%6,%7},{%8,%9},{%0,%1,%2,%3};" \
        : "+f"((c)[0]), "+f"((c)[1]), "+f"((c)[2]), "+f"((c)[3]) \
        : "r"((a)[0]), "r"((a)[1]), "r"((a)[2]), "r"((a)[3]), "r"(b0), "r"(b1))

__device__ __forceinline__ uint32_t packh2(float lo, float hi) {
    __half2 h = __floats2half2_rn(lo, hi);
    return *(uint32_t*)&h;
}
__device__ __forceinline__ float h2lo(uint32_t p) {
    __half2 h = *(__half2*)&p; return __low2float(h);
}
__device__ __forceinline__ float h2hi(uint32_t p) {
    __half2 h = *(__half2*)&p; return __high2float(h);
}
__device__ __forceinline__ float ex2(float x) {
    float r; asm("ex2.approx.f32 %0, %1;" : "=f"(r) : "f"(x)); return r;
}

// softmax scale folded into Q at projection time: 1/sqrt(64) * log2(e)
#define QSCALE (0.125f * 1.44269504f)

// ---------------- scratch (device globals; no allocation allowed) ----------
__device__ __align__(16) __half g_xhi[(size_t)M_ * EMB_];
__device__ __align__(16) __half g_xlo[(size_t)M_ * EMB_];
__device__ __align__(16) __half g_wh [(size_t)4 * EMB_ * EMB_];   // weights: fp16
__device__ __align__(16) __half g_qhi[(size_t)M_ * EMB_];
__device__ __align__(16) __half g_qlo[(size_t)M_ * EMB_];
__device__ __align__(16) __half g_kh [(size_t)M_ * EMB_];
__device__ __align__(16) __half g_vh [(size_t)M_ * EMB_];
__device__ __align__(16) __half g_ahi[(size_t)M_ * EMB_];
__device__ __align__(16) __half g_alo[(size_t)M_ * EMB_];

// ---------------- fp32 -> fp16 hi/lo split (x) / fp16 round (weights) -------
__global__ __launch_bounds__(256) void conv_split_x(
    const float* __restrict__ src, int n4)
{
    int i = blockIdx.x * 256 + threadIdx.x;
    if (i >= n4) return;
    float4 v = ((const float4*)src)[i];
    uint32_t h01 = packh2(v.x, v.y), h23 = packh2(v.z, v.w);
    uint32_t l01 = packh2(v.x - h2lo(h01), v.y - h2hi(h01));
    uint32_t l23 = packh2(v.z - h2lo(h23), v.w - h2hi(h23));
    ((uint32_t*)g_xhi)[2 * i] = h01; ((uint32_t*)g_xhi)[2 * i + 1] = h23;
    ((uint32_t*)g_xlo)[2 * i] = l01; ((uint32_t*)g_xlo)[2 * i + 1] = l23;
}
__global__ __launch_bounds__(256) void conv_w(
    const float* __restrict__ w0, const float* __restrict__ w1,
    const float* __restrict__ w2, const float* __restrict__ w3)
{
    const int which = blockIdx.y;
    const float* src = (which == 0) ? w0 : (which == 1) ? w1 : (which == 2) ? w2 : w3;
    __half* hi = g_wh + (size_t)which * EMB_ * EMB_;
    int i = blockIdx.x * 256 + threadIdx.x;
    float4 v = ((const float4*)src)[i];
    ((uint32_t*)hi)[2 * i]     = packh2(v.x, v.y);
    ((uint32_t*)hi)[2 * i + 1] = packh2(v.z, v.w);
}

// ---------------- mma.sync GEMM: D = A @ W^T + bias (R12 config, frozen) -----
constexpr int GSTRIDE = 144;
constexpr int GMAT    = 128 * GSTRIDE;             // 18432
constexpr int GSTAGE  = 3 * GMAT;                  // 55296 (Ahi, Alo, Bh)
constexpr int GEMM_SMEM = 2 * GSTAGE;              // 110592 -> 2 CTAs/SM

__device__ __forceinline__ void gload_chunk(
    uint32_t sbase, const __half* Ahi, const __half* Alo, const __half* Bh,
    int row0, int col0, int k0, int tid)
{
    #pragma unroll
    for (int i = tid; i < 3072; i += 256) {
        int mat = i >> 10;                 // 0=Ahi, 1=Alo, 2=Bh
        int r   = (i >> 3) & 127;
        int c   = i & 7;
        uint32_t dst = sbase + mat * GMAT + r * GSTRIDE + c * 16;
        const __half* m = (mat == 0) ? Ahi : (mat == 1) ? Alo : Bh;
        int gr = ((mat < 2) ? row0 : col0) + r;
        cpa16(dst, m + (size_t)gr * EMB_ + k0 + c * 8);
    }
    CPA_COMMIT();
}

__global__ __launch_bounds__(256, 2) void gemm_mma_kernel(
    const float* __restrict__ bq, const float* __restrict__ bk,
    const float* __restrict__ bv, float* __restrict__ outp, int mode)
{
    extern __shared__ char smem[];
    const uint32_t sb = smem_u32(smem);
    const int tid = threadIdx.x, wid = tid >> 5, lane = tid & 31;
    const int row0 = blockIdx.y * 128, col0 = blockIdx.x * 128;
    const int z = blockIdx.z;

    const __half *Ahi, *Alo, *Bh;
    const float* bias;
    if (mode == 0) {
        Ahi = g_xhi; Alo = g_xlo;
        Bh  = g_wh + (size_t)z * EMB_ * EMB_;
        bias = (z == 0) ? bq : (z == 1) ? bk : bv;
    } else {
        Ahi = g_ahi; Alo = g_alo;
        Bh  = g_wh + (size_t)3 * EMB_ * EMB_;
        bias = bq;
    }

    const int wm = (wid & 1) * 64;
    const int wn = (wid >> 1) * 32;

    float c[4][4][4] = {};

    gload_chunk(sb + 0 * GSTAGE, Ahi, Alo, Bh, row0, col0, 0,  tid);
    gload_chunk(sb + 1 * GSTAGE, Ahi, Alo, Bh, row0, col0, 64, tid);

    const int a_row = wm + (lane & 7) + ((lane >> 3) & 1) * 8;
    const int a_kc  = ((lane >> 4) & 1) * 8;
    const int b_row = wn + (lane & 7) + ((lane >> 4) & 1) * 8;
    const int b_kc  = ((lane >> 3) & 1) * 8;

    for (int ch = 0; ch < 16; ++ch) {
        const int s = ch & 1;
        CPA_WAIT1();
        __syncthreads();
        const uint32_t st = sb + s * GSTAGE;

        #pragma unroll
        for (int kk = 0; kk < 64; kk += 16) {
            uint32_t bhf[2][4];
            #pragma unroll
            for (int pt = 0; pt < 2; ++pt) {
                uint32_t addr = st + 2 * GMAT + (b_row + pt * 16) * GSTRIDE
                              + (kk + b_kc) * 2;
                LDSM4(bhf[pt][0], bhf[pt][1], bhf[pt][2], bhf[pt][3], addr);
            }
            #pragma unroll
            for (int mt = 0; mt < 4; ++mt) {
                uint32_t addr = st + (a_row + mt * 16) * GSTRIDE
                              + (kk + a_kc) * 2;
                uint32_t ah[4], al[4];
                LDSM4(ah[0], ah[1], ah[2], ah[3], addr);
                LDSM4(al[0], al[1], al[2], al[3], addr + GMAT);
                #pragma unroll
                for (int nt = 0; nt < 4; ++nt) {
                    const int pt = nt >> 1, hf = (nt & 1) * 2;
                    MMAH16816(c[mt][nt], ah, bhf[pt][hf], bhf[pt][hf + 1]);
                    MMAH16816(c[mt][nt], al, bhf[pt][hf], bhf[pt][hf + 1]);
                }
            }
        }
        __syncthreads();
        if (ch + 2 < 16)
            gload_chunk(sb + s * GSTAGE, Ahi, Alo, Bh,
                        row0, col0, (ch + 2) * 64, tid);
        else
            CPA_COMMIT();
    }

    #pragma unroll
    for (int mt = 0; mt < 4; ++mt) {
        #pragma unroll
        for (int nt = 0; nt < 4; ++nt) {
            int r = row0 + wm + mt * 16 + (lane >> 2);
            int n = col0 + wn + nt * 8 + (lane & 3) * 2;
            float2 bv2 = *(const float2*)&bias[n];
            float p0 = c[mt][nt][0] + bv2.x, p1 = c[mt][nt][1] + bv2.y;
            float p2 = c[mt][nt][2] + bv2.x, p3 = c[mt][nt][3] + bv2.y;
            if (mode == 0) {
                int h = n >> 6, d = n & 63;
                int bb0 = r >> 11, s0 = r & 2047;
                int bb1 = (r + 8) >> 11, s1 = (r + 8) & 2047;
                size_t i0 = (((size_t)bb0 * H_ + h) * S_ + s0) * HD_ + d;
                size_t i1 = (((size_t)bb1 * H_ + h) * S_ + s1) * HD_ + d;
                if (z == 0) {
                    p0 *= QSCALE; p1 *= QSCALE; p2 *= QSCALE; p3 *= QSCALE;
                    uint32_t h01 = packh2(p0, p1);
                    uint32_t l01 = packh2(p0 - h2lo(h01), p1 - h2hi(h01));
                    uint32_t h23 = packh2(p2, p3);
                    uint32_t l23 = packh2(p2 - h2lo(h23), p3 - h2hi(h23));
                    *(uint32_t*)&g_qhi[i0] = h01; *(uint32_t*)&g_qlo[i0] = l01;
                    *(uint32_t*)&g_qhi[i1] = h23; *(uint32_t*)&g_qlo[i1] = l23;
                } else {
                    __half* dh = (z == 1) ? g_kh : g_vh;
                    *(uint32_t*)&dh[i0] = packh2(p0, p1);
                    *(uint32_t*)&dh[i1] = packh2(p2, p3);
                }
            } else {
                float2 v0 = {p0, p1}, v1 = {p2, p3};
                *(float2*)&outp[(size_t)r * EMB_ + n] = v0;
                *(float2*)&outp[(size_t)(r + 8) * EMB_ + n] = v1;
            }
        }
    }
}

// ---------------- mma.sync causal flash attention (fp16, 128-key stages) ----
// QK^T: 2-term (Qh+Ql)*Kh.  PV: 1-term Ph*Vh (P in [0,1], fp16 rounding ok).
constexpr int ASTR   = 144;
constexpr int AQMAT  = 128 * ASTR;                  // 18432
constexpr int AKMAT  = 128 * ASTR;                  // 18432 (128 keys/stage)
constexpr int ASTAGE = 2 * AKMAT;                   // 36864 (Kh, Vh)
constexpr int ATTN_SMEM = 2 * AQMAT + 2 * ASTAGE;   // 110592 -> 2 CTAs/SM

__device__ __forceinline__ void akv_load(
    uint32_t base, const __half* Kh, const __half* Vh, int kt, int tid)
{
    #pragma unroll
    for (int i = tid; i < 2048; i += 256) {
        int mat = i >> 10;                 // 0=Kh, 1=Vh
        int r   = (i >> 3) & 127;
        int c   = i & 7;
        const __half* m = mat ? Vh : Kh;
        cpa16(base + mat * AKMAT + r * ASTR + c * 16,
              m + (size_t)(kt * 128 + r) * HD_ + c * 8);
    }
}

__global__ __launch_bounds__(256, 2) void attn_mma_kernel()
{
    extern __shared__ char smem[];
    const uint32_t sb = smem_u32(smem);
    const int tid = threadIdx.x, wid = tid >> 5, lane = tid & 31;
    const int qt = (S_ / 128 - 1) - blockIdx.y;   // heavy tiles dispatch first
    const int bh = blockIdx.x;
    const size_t off = (size_t)bh * S_ * HD_;
    const __half *Qh = g_qhi + off, *Ql = g_qlo + off;
    const __half *Kh = g_kh + off, *Vh = g_vh + off;
    const int ntiles = qt + 1;                    // 128-key tiles

    #pragma unroll
    for (int i = tid; i < 2048; i += 256) {
        int mat = i >> 10, r = (i >> 3) & 127, c = i & 7;
        const __half* m = mat ? Ql : Qh;
        cpa16(sb + mat * AQMAT + r * ASTR + c * 16,
              m + (size_t)(qt * 128 + r) * HD_ + c * 8);
    }
    akv_load(sb + 2 * AQMAT, Kh, Vh, 0, tid);
    CPA_COMMIT();
    akv_load(sb + 2 * AQMAT + ASTAGE, Kh, Vh, 1, tid);   // rows <256 always valid
    CPA_COMMIT();

    const int a_row = wid * 16 + (lane & 7) + ((lane >> 3) & 1) * 8;
    const int a_kc2 = ((lane >> 4) & 1) * 16;
    const int b_row = (lane & 7) + ((lane >> 4) & 1) * 8;
    const int b_kc2 = ((lane >> 3) & 1) * 16;
    const int v_row = (lane & 7) + ((lane >> 3) & 1) * 8;
    const int v_cc2 = ((lane >> 4) & 1) * 16;
    const int row0g = qt * 128 + wid * 16 + (lane >> 2);

    float O[8][4] = {};
    float m0 = -1e30f, m1 = -1e30f, l0 = 0.0f, l1 = 0.0f;

    for (int kt = 0; kt < ntiles; ++kt) {
        CPA_WAIT1();
        __syncthreads();
        const uint32_t st = sb + 2 * AQMAT + (kt & 1) * ASTAGE;

        // ---- S = Q K^T over 128 keys (fp16 2-term); Q pre-scaled ----
        float S[16][4];
        #pragma unroll
        for (int j = 0; j < 16; ++j) { S[j][0]=0; S[j][1]=0; S[j][2]=0; S[j][3]=0; }
        #pragma unroll
        for (int ks = 0; ks < 4; ++ks) {
            uint32_t qaddr = sb + a_row * ASTR + ks * 32 + a_kc2;
            uint32_t ah[4], al[4];
            LDSM4(ah[0], ah[1], ah[2], ah[3], qaddr);
            LDSM4(al[0], al[1], al[2], al[3], qaddr + AQMAT);
            #pragma unroll
            for (int g = 0; g < 8; ++g) {
                uint32_t kaddr = st + (g * 16 + b_row) * ASTR + ks * 32 + b_kc2;
                uint32_t kh[4];
                LDSM4(kh[0], kh[1], kh[2], kh[3], kaddr);
                MMAH16816(S[2 * g],     ah, kh[0], kh[1]);
                MMAH16816(S[2 * g],     al, kh[0], kh[1]);
                MMAH16816(S[2 * g + 1], ah, kh[2], kh[3]);
                MMAH16816(S[2 * g + 1], al, kh[2], kh[3]);
            }
        }

        // ---- causal mask (only last tile straddles) ----
        if (kt == qt) {
            #pragma unroll
            for (int j = 0; j < 16; ++j) {
                int col = kt * 128 + j * 8 + (lane & 3) * 2;
                if (col     > row0g)     S[j][0] = -1e30f;
                if (col + 1 > row0g)     S[j][1] = -1e30f;
                if (col     > row0g + 8) S[j][2] = -1e30f;
                if (col + 1 > row0g + 8) S[j][3] = -1e30f;
            }
        }

        // ---- online softmax (one pass per 128 keys) ----
        float mx0 = -1e30f, mx1 = -1e30f;
        #pragma unroll
        for (int j = 0; j < 16; ++j) {
            mx0 = fmaxf(mx0, fmaxf(S[j][0], S[j][1]));
            mx1 = fmaxf(mx1, fmaxf(S[j][2], S[j][3]));
        }
        mx0 = fmaxf(mx0, __shfl_xor_sync(0xffffffffu, mx0, 1));
        mx0 = fmaxf(mx0, __shfl_xor_sync(0xffffffffu, mx0, 2));
        mx1 = fmaxf(mx1, __shfl_xor_sync(0xffffffffu, mx1, 1));
        mx1 = fmaxf(mx1, __shfl_xor_sync(0xffffffffu, mx1, 2));
        float nm0 = fmaxf(m0, mx0), nm1 = fmaxf(m1, mx1);
        float f0 = ex2(m0 - nm0), f1 = ex2(m1 - nm1);
        m0 = nm0; m1 = nm1;
        float s0 = 0.0f, s1 = 0.0f;
        #pragma unroll
        for (int j = 0; j < 16; ++j) {
            S[j][0] = ex2(S[j][0] - nm0); S[j][1] = ex2(S[j][1] - nm0);
            S[j][2] = ex2(S[j][2] - nm1); S[j][3] = ex2(S[j][3] - nm1);
            s0 += S[j][0] + S[j][1];
            s1 += S[j][2] + S[j][3];
        }
        s0 += __shfl_xor_sync(0xffffffffu, s0, 1);
        s0 += __shfl_xor_sync(0xffffffffu, s0, 2);
        s1 += __shfl_xor_sync(0xffffffffu, s1, 1);
        s1 += __shfl_xor_sync(0xffffffffu, s1, 2);
        l0 = l0 * f0 + s0; l1 = l1 * f1 + s1;
        #pragma unroll
        for (int j = 0; j < 8; ++j) {
            O[j][0] *= f0; O[j][1] *= f0; O[j][2] *= f1; O[j][3] *= f1;
        }

        // ---- O += P V over 128 keys (fp16 1-term: P in [0,1]) ----
        #pragma unroll
        for (int ks = 0; ks < 8; ++ks) {
            uint32_t ph[4];
            ph[0] = packh2(S[2 * ks][0],     S[2 * ks][1]);
            ph[1] = packh2(S[2 * ks][2],     S[2 * ks][3]);
            ph[2] = packh2(S[2 * ks + 1][0], S[2 * ks + 1][1]);
            ph[3] = packh2(S[2 * ks + 1][2], S[2 * ks + 1][3]);
            #pragma unroll
            for (int g = 0; g < 4; ++g) {
                uint32_t vaddr = st + AKMAT + (ks * 16 + v_row) * ASTR
                               + g * 32 + v_cc2;
                uint32_t vh[4];
                LDSM4T(vh[0], vh[1], vh[2], vh[3], vaddr);
                MMAH16816(O[2 * g],     ph, vh[0], vh[1]);
                MMAH16816(O[2 * g + 1], ph, vh[2], vh[3]);
            }
        }

        __syncthreads();
        if (kt + 2 < ntiles) {
            akv_load(sb + 2 * AQMAT + (kt & 1) * ASTAGE, Kh, Vh, kt + 2, tid);
            CPA_COMMIT();
        } else {
            CPA_COMMIT();
        }
    }

    // ---- epilogue: normalize, split fp16 hi/lo, write [B,S,EMB] ----
    const float inv0 = 1.0f / l0, inv1 = 1.0f / l1;
    const int b = bh >> 4, h = bh & 15;
    const int r0 = qt * 128 + wid * 16 + (lane >> 2);
    const int cc = (lane & 3) * 2;
    #pragma unroll
    for (int j = 0; j < 8; ++j) {
        float p0 = O[j][0] * inv0, p1 = O[j][1] * inv0;
        float p2 = O[j][2] * inv1, p3 = O[j][3] * inv1;
        size_t i0 = ((size_t)b * S_ + r0) * EMB_ + h * 64 + j * 8 + cc;
        size_t i1 = i0 + (size_t)8 * EMB_;
        uint32_t h01 = packh2(p0, p1);
        uint32_t l01 = packh2(p0 - h2lo(h01), p1 - h2hi(h01));
        uint32_t h23 = packh2(p2, p3);
        uint32_t l23 = packh2(p2 - h2lo(h23), p3 - h2hi(h23));
        *(uint32_t*)&g_ahi[i0] = h01; *(uint32_t*)&g_alo[i0] = l01;
        *(uint32_t*)&g_ahi[i1] = h23; *(uint32_t*)&g_alo[i1] = l23;
    }
}

// ---------------- launch ---------------------------------------------------
extern "C" void kernel_launch(void* const* d_in, const int* in_sizes, int n_in,
                              void* d_out, int out_size)
{
    const float* x  = (const float*)d_in[0];
    const float* Wq = (const float*)d_in[1];
    const float* bq = (const float*)d_in[2];
    const float* Wk = (const float*)d_in[3];
    const float* bk = (const float*)d_in[4];
    const float* Wv = (const float*)d_in[5];
    const float* bv = (const float*)d_in[6];
    const float* Wo = (const float*)d_in[7];
    const float* bo = (const float*)d_in[8];
    float* out = (float*)d_out;

    cudaFuncSetAttribute(gemm_mma_kernel,
                         cudaFuncAttributeMaxDynamicSharedMemorySize, GEMM_SMEM);
    cudaFuncSetAttribute(attn_mma_kernel,
                         cudaFuncAttributeMaxDynamicSharedMemorySize, ATTN_SMEM);

    const int n4x = M_ * EMB_ / 4;
    const int n4w = EMB_ * EMB_ / 4;
    conv_split_x<<<n4x / 256, 256>>>(x, n4x);
    conv_w<<<dim3(n4w / 256, 4), 256>>>(Wq, Wk, Wv, Wo);

    // QKV projections (fp16 2-term mma.sync, 2 CTAs/SM) -> Q hi/lo, K, V
    gemm_mma_kernel<<<dim3(EMB_ / 128, M_ / 128, 3), 256, GEMM_SMEM>>>(
        bq, bk, bv, nullptr, 0);

    // causal attention (fp16 mma.sync flash, 128-key stages, PV 1-term)
    attn_mma_kernel<<<dim3(B_ * H_, S_ / 128), 256, ATTN_SMEM>>>();

    // output projection (fp16 2-term mma.sync, 2 CTAs/SM)
    gemm_mma_kernel<<<dim3(EMB_ / 128, M_ / 128, 1), 256, GEMM_SMEM>>>(
        bo, nullptr, nullptr, out, 1);
}

// round 15
// speedup vs baseline: 1.7730x; 1.0949x over previous
#include <cuda_runtime.h>
#include <cuda_fp16.h>
#include <math.h>
#include <stdint.h>

#define B_   4
#define S_   2048
#define EMB_ 1024
#define H_   16
#define HD_  64
#define M_   (B_ * S_)   // 8192

// ---- ptx helpers (mma.sync / ldmatrix / cp.async) — baseline sm_103 legal --
__device__ __forceinline__ uint32_t smem_u32(const void* p) {
    uint32_t a;
    asm("{ .reg .u64 t; cvta.to.shared.u64 t, %1; cvt.u32.u64 %0, t; }"
        : "=r"(a) : "l"(p));
    return a;
}
__device__ __forceinline__ void cpa16(uint32_t dst, const void* src) {
    asm volatile("cp.async.cg.shared.global [%0], [%1], 16;" :: "r"(dst), "l"(src) : "memory");
}
#define CPA_COMMIT() asm volatile("cp.async.commit_group;" ::: "memory")
#define CPA_WAIT1()  asm volatile("cp.async.wait_group 1;"  ::: "memory")

#define LDSM4(r0, r1, r2, r3, addr) \
    asm volatile("ldmatrix.sync.aligned.m8n8.x4.shared.b16 {%0,%1,%2,%3}, [%4];" \
        : "=r"(r0), "=r"(r1), "=r"(r2), "=r"(r3) : "r"(addr))
#define LDSM4T(r0, r1, r2, r3, addr) \
    asm volatile("ldmatrix.sync.aligned.m8n8.x4.trans.shared.b16 {%0,%1,%2,%3}, [%4];" \
        : "=r"(r0), "=r"(r1), "=r"(r2), "=r"(r3) : "r"(addr))

#define MMAH16816(c, a, b0, b1) \
    asm volatile("mma.sync.aligned.m16n8k16.row.col.f32.f16.f16.f32 " \
        "{%0,%1,%2,%3},{%4,%5,%6,%7},{%8,%9},{%0,%1,%2,%3};" \
        : "+f"((c)[0]), "+f"((c)[1]), "+f"((c)[2]), "+f"((c)[3]) \
        : "r"((a)[0]), "r"((a)[1]), "r"((a)[2]), "r"((a)[3]), "r"(b0), "r"(b1))

__device__ __forceinline__ uint32_t packh2(float lo, float hi) {
    __half2 h = __floats2half2_rn(lo, hi);
    return *(uint32_t*)&h;
}
__device__ __forceinline__ float h2lo(uint32_t p) {
    __half2 h = *(__half2*)&p; return __low2float(h);
}
__device__ __forceinline__ float h2hi(uint32_t p) {
    __half2 h = *(__half2*)&p; return __high2float(h);
}
__device__ __forceinline__ float ex2(float x) {
    float r; asm("ex2.approx.f32 %0, %1;" : "=f"(r) : "f"(x)); return r;
}

// softmax scale folded into Q at projection time: 1/sqrt(64) * log2(e)
#define QSCALE (0.125f * 1.44269504f)

// ---------------- scratch (device globals; no allocation allowed) ----------
__device__ __align__(16) __half g_xhi[(size_t)M_ * EMB_];
__device__ __align__(16) __half g_xlo[(size_t)M_ * EMB_];
__device__ __align__(16) __half g_wh [(size_t)4 * EMB_ * EMB_];   // weights: fp16
__device__ __align__(16) __half g_qhi[(size_t)M_ * EMB_];
__device__ __align__(16) __half g_qlo[(size_t)M_ * EMB_];
__device__ __align__(16) __half g_kh [(size_t)M_ * EMB_];
__device__ __align__(16) __half g_vh [(size_t)M_ * EMB_];
__device__ __align__(16) __half g_ah [(size_t)M_ * EMB_];          // attn out: fp16 1-term

// ---------------- fp32 -> fp16 hi/lo split (x) / fp16 round (weights) -------
__global__ __launch_bounds__(256) void conv_split_x(
    const float* __restrict__ src, int n4)
{
    int i = blockIdx.x * 256 + threadIdx.x;
    if (i >= n4) return;
    float4 v = ((const float4*)src)[i];
    uint32_t h01 = packh2(v.x, v.y), h23 = packh2(v.z, v.w);
    uint32_t l01 = packh2(v.x - h2lo(h01), v.y - h2hi(h01));
    uint32_t l23 = packh2(v.z - h2lo(h23), v.w - h2hi(h23));
    ((uint32_t*)g_xhi)[2 * i] = h01; ((uint32_t*)g_xhi)[2 * i + 1] = h23;
    ((uint32_t*)g_xlo)[2 * i] = l01; ((uint32_t*)g_xlo)[2 * i + 1] = l23;
}
__global__ __launch_bounds__(256) void conv_w(
    const float* __restrict__ w0, const float* __restrict__ w1,
    const float* __restrict__ w2, const float* __restrict__ w3)
{
    const int which = blockIdx.y;
    const float* src = (which == 0) ? w0 : (which == 1) ? w1 : (which == 2) ? w2 : w3;
    __half* hi = g_wh + (size_t)which * EMB_ * EMB_;
    int i = blockIdx.x * 256 + threadIdx.x;
    float4 v = ((const float4*)src)[i];
    ((uint32_t*)hi)[2 * i]     = packh2(v.x, v.y);
    ((uint32_t*)hi)[2 * i + 1] = packh2(v.z, v.w);
}

// ---------------- mma.sync GEMM: D = A @ W^T + bias --------------------------
// MODE 0 (QKV): A = (xhi, xlo) 2-term. MODE 1 (oproj): A = g_ah 1-term.
constexpr int GSTRIDE = 144;
constexpr int GMAT    = 128 * GSTRIDE;             // 18432
constexpr int GSTAGE  = 3 * GMAT;                  // 55296 (Ahi, Alo, Bh)
constexpr int GEMM_SMEM = 2 * GSTAGE;              // 110592 -> 2 CTAs/SM

template<int MODE>
__device__ __forceinline__ void gload_chunk(
    uint32_t sbase, const __half* Ahi, const __half* Alo, const __half* Bh,
    int row0, int col0, int k0, int tid)
{
    if (MODE == 0) {
        #pragma unroll
        for (int i = tid; i < 3072; i += 256) {
            int mat = i >> 10;                 // 0=Ahi, 1=Alo, 2=Bh
            int r   = (i >> 3) & 127;
            int c   = i & 7;
            uint32_t dst = sbase + mat * GMAT + r * GSTRIDE + c * 16;
            const __half* m = (mat == 0) ? Ahi : (mat == 1) ? Alo : Bh;
            int gr = ((mat < 2) ? row0 : col0) + r;
            cpa16(dst, m + (size_t)gr * EMB_ + k0 + c * 8);
        }
    } else {
        #pragma unroll
        for (int i = tid; i < 2048; i += 256) {
            int mat = i >> 10;                 // 0=Ahi, 1=Bh (slot 2)
            int r   = (i >> 3) & 127;
            int c   = i & 7;
            uint32_t dst = sbase + (mat ? 2 * GMAT : 0) + r * GSTRIDE + c * 16;
            const __half* m = mat ? Bh : Ahi;
            int gr = (mat ? col0 : row0) + r;
            cpa16(dst, m + (size_t)gr * EMB_ + k0 + c * 8);
        }
    }
    CPA_COMMIT();
}

template<int MODE>
__global__ __launch_bounds__(256, 2) void gemm_mma_kernel(
    const float* __restrict__ bq, const float* __restrict__ bk,
    const float* __restrict__ bv, float* __restrict__ outp)
{
    extern __shared__ char smem[];
    const uint32_t sb = smem_u32(smem);
    const int tid = threadIdx.x, wid = tid >> 5, lane = tid & 31;
    const int row0 = blockIdx.y * 128, col0 = blockIdx.x * 128;
    const int z = blockIdx.z;

    const __half *Ahi, *Alo, *Bh;
    const float* bias;
    if (MODE == 0) {
        Ahi = g_xhi; Alo = g_xlo;
        Bh  = g_wh + (size_t)z * EMB_ * EMB_;
        bias = (z == 0) ? bq : (z == 1) ? bk : bv;
    } else {
        Ahi = g_ah; Alo = nullptr;
        Bh  = g_wh + (size_t)3 * EMB_ * EMB_;
        bias = bq;
    }

    const int wm = (wid & 1) * 64;
    const int wn = (wid >> 1) * 32;

    float c[4][4][4] = {};

    gload_chunk<MODE>(sb + 0 * GSTAGE, Ahi, Alo, Bh, row0, col0, 0,  tid);
    gload_chunk<MODE>(sb + 1 * GSTAGE, Ahi, Alo, Bh, row0, col0, 64, tid);

    const int a_row = wm + (lane & 7) + ((lane >> 3) & 1) * 8;
    const int a_kc  = ((lane >> 4) & 1) * 8;
    const int b_row = wn + (lane & 7) + ((lane >> 4) & 1) * 8;
    const int b_kc  = ((lane >> 3) & 1) * 8;

    for (int ch = 0; ch < 16; ++ch) {
        const int s = ch & 1;
        CPA_WAIT1();
        __syncthreads();
        const uint32_t st = sb + s * GSTAGE;

        #pragma unroll
        for (int kk = 0; kk < 64; kk += 16) {
            uint32_t bhf[2][4];
            #pragma unroll
            for (int pt = 0; pt < 2; ++pt) {
                uint32_t addr = st + 2 * GMAT + (b_row + pt * 16) * GSTRIDE
                              + (kk + b_kc) * 2;
                LDSM4(bhf[pt][0], bhf[pt][1], bhf[pt][2], bhf[pt][3], addr);
            }
            #pragma unroll
            for (int mt = 0; mt < 4; ++mt) {
                uint32_t addr = st + (a_row + mt * 16) * GSTRIDE
                              + (kk + a_kc) * 2;
                uint32_t ah[4];
                LDSM4(ah[0], ah[1], ah[2], ah[3], addr);
                if (MODE == 0) {
                    uint32_t al[4];
                    LDSM4(al[0], al[1], al[2], al[3], addr + GMAT);
                    #pragma unroll
                    for (int nt = 0; nt < 4; ++nt) {
                        const int pt = nt >> 1, hf = (nt & 1) * 2;
                        MMAH16816(c[mt][nt], ah, bhf[pt][hf], bhf[pt][hf + 1]);
                        MMAH16816(c[mt][nt], al, bhf[pt][hf], bhf[pt][hf + 1]);
                    }
                } else {
                    #pragma unroll
                    for (int nt = 0; nt < 4; ++nt) {
                        const int pt = nt >> 1, hf = (nt & 1) * 2;
                        MMAH16816(c[mt][nt], ah, bhf[pt][hf], bhf[pt][hf + 1]);
                    }
                }
            }
        }
        __syncthreads();
        if (ch + 2 < 16)
            gload_chunk<MODE>(sb + s * GSTAGE, Ahi, Alo, Bh,
                              row0, col0, (ch + 2) * 64, tid);
        else
            CPA_COMMIT();
    }

    #pragma unroll
    for (int mt = 0; mt < 4; ++mt) {
        #pragma unroll
        for (int nt = 0; nt < 4; ++nt) {
            int r = row0 + wm + mt * 16 + (lane >> 2);
            int n = col0 + wn + nt * 8 + (lane & 3) * 2;
            float2 bv2 = *(const float2*)&bias[n];
            float p0 = c[mt][nt][0] + bv2.x, p1 = c[mt][nt][1] + bv2.y;
            float p2 = c[mt][nt][2] + bv2.x, p3 = c[mt][nt][3] + bv2.y;
            if (MODE == 0) {
                int h = n >> 6, d = n & 63;
                int bb0 = r >> 11, s0 = r & 2047;
                int bb1 = (r + 8) >> 11, s1 = (r + 8) & 2047;
                size_t i0 = (((size_t)bb0 * H_ + h) * S_ + s0) * HD_ + d;
                size_t i1 = (((size_t)bb1 * H_ + h) * S_ + s1) * HD_ + d;
                if (z == 0) {
                    p0 *= QSCALE; p1 *= QSCALE; p2 *= QSCALE; p3 *= QSCALE;
                    uint32_t h01 = packh2(p0, p1);
                    uint32_t l01 = packh2(p0 - h2lo(h01), p1 - h2hi(h01));
                    uint32_t h23 = packh2(p2, p3);
                    uint32_t l23 = packh2(p2 - h2lo(h23), p3 - h2hi(h23));
                    *(uint32_t*)&g_qhi[i0] = h01; *(uint32_t*)&g_qlo[i0] = l01;
                    *(uint32_t*)&g_qhi[i1] = h23; *(uint32_t*)&g_qlo[i1] = l23;
                } else {
                    __half* dh = (z == 1) ? g_kh : g_vh;
                    *(uint32_t*)&dh[i0] = packh2(p0, p1);
                    *(uint32_t*)&dh[i1] = packh2(p2, p3);
                }
            } else {
                float2 v0 = {p0, p1}, v1 = {p2, p3};
                *(float2*)&outp[(size_t)r * EMB_ + n] = v0;
                *(float2*)&outp[(size_t)(r + 8) * EMB_ + n] = v1;
            }
        }
    }
}

// ---------------- mma.sync causal flash attention (fp16, 128-key stages) ----
// QK^T: 2-term (Qh+Ql)*Kh.  PV: 1-term Ph*Vh.  Output: fp16 1-term.
constexpr int ASTR   = 144;
constexpr int AQMAT  = 128 * ASTR;                  // 18432
constexpr int AKMAT  = 128 * ASTR;                  // 18432 (128 keys/stage)
constexpr int ASTAGE = 2 * AKMAT;                   // 36864 (Kh, Vh)
constexpr int ATTN_SMEM = 2 * AQMAT + 2 * ASTAGE;   // 110592 -> 2 CTAs/SM

__device__ __forceinline__ void akv_load(
    uint32_t base, const __half* Kh, const __half* Vh, int kt, int tid)
{
    #pragma unroll
    for (int i = tid; i < 2048; i += 256) {
        int mat = i >> 10;                 // 0=Kh, 1=Vh
        int r   = (i >> 3) & 127;
        int c   = i & 7;
        const __half* m = mat ? Vh : Kh;
        cpa16(base + mat * AKMAT + r * ASTR + c * 16,
              m + (size_t)(kt * 128 + r) * HD_ + c * 8);
    }
}

__global__ __launch_bounds__(256, 2) void attn_mma_kernel()
{
    extern __shared__ char smem[];
    const uint32_t sb = smem_u32(smem);
    const int tid = threadIdx.x, wid = tid >> 5, lane = tid & 31;
    const int qt = (S_ / 128 - 1) - blockIdx.y;   // heavy tiles dispatch first
    const int bh = blockIdx.x;
    const size_t off = (size_t)bh * S_ * HD_;
    const __half *Qh = g_qhi + off, *Ql = g_qlo + off;
    const __half *Kh = g_kh + off, *Vh = g_vh + off;
    const int ntiles = qt + 1;                    // 128-key tiles

    #pragma unroll
    for (int i = tid; i < 2048; i += 256) {
        int mat = i >> 10, r = (i >> 3) & 127, c = i & 7;
        const __half* m = mat ? Ql : Qh;
        cpa16(sb + mat * AQMAT + r * ASTR + c * 16,
              m + (size_t)(qt * 128 + r) * HD_ + c * 8);
    }
    akv_load(sb + 2 * AQMAT, Kh, Vh, 0, tid);
    CPA_COMMIT();
    akv_load(sb + 2 * AQMAT + ASTAGE, Kh, Vh, 1, tid);   // rows <256 always valid
    CPA_COMMIT();

    const int a_row = wid * 16 + (lane & 7) + ((lane >> 3) & 1) * 8;
    const int a_kc2 = ((lane >> 4) & 1) * 16;
    const int b_row = (lane & 7) + ((lane >> 4) & 1) * 8;
    const int b_kc2 = ((lane >> 3) & 1) * 16;
    const int v_row = (lane & 7) + ((lane >> 3) & 1) * 8;
    const int v_cc2 = ((lane >> 4) & 1) * 16;
    const int row0g = qt * 128 + wid * 16 + (lane >> 2);

    float O[8][4] = {};
    float m0 = -1e30f, m1 = -1e30f, l0 = 0.0f, l1 = 0.0f;

    for (int kt = 0; kt < ntiles; ++kt) {
        CPA_WAIT1();
        __syncthreads();
        const uint32_t st = sb + 2 * AQMAT + (kt & 1) * ASTAGE;

        // ---- S = Q K^T over 128 keys (fp16 2-term); Q pre-scaled ----
        float S[16][4];
        #pragma unroll
        for (int j = 0; j < 16; ++j) { S[j][0]=0; S[j][1]=0; S[j][2]=0; S[j][3]=0; }
        #pragma unroll
        for (int ks = 0; ks < 4; ++ks) {
            uint32_t qaddr = sb + a_row * ASTR + ks * 32 + a_kc2;
            uint32_t ah[4], al[4];
            LDSM4(ah[0], ah[1], ah[2], ah[3], qaddr);
            LDSM4(al[0], al[1], al[2], al[3], qaddr + AQMAT);
            #pragma unroll
            for (int g = 0; g < 8; ++g) {
                uint32_t kaddr = st + (g * 16 + b_row) * ASTR + ks * 32 + b_kc2;
                uint32_t kh[4];
                LDSM4(kh[0], kh[1], kh[2], kh[3], kaddr);
                MMAH16816(S[2 * g],     ah, kh[0], kh[1]);
                MMAH16816(S[2 * g],     al, kh[0], kh[1]);
                MMAH16816(S[2 * g + 1], ah, kh[2], kh[3]);
                MMAH16816(S[2 * g + 1], al, kh[2], kh[3]);
            }
        }

        // ---- causal mask (only last tile straddles) ----
        if (kt == qt) {
            #pragma unroll
            for (int j = 0; j < 16; ++j) {
                int col = kt * 128 + j * 8 + (lane & 3) * 2;
                if (col     > row0g)     S[j][0] = -1e30f;
                if (col + 1 > row0g)     S[j][1] = -1e30f;
                if (col     > row0g + 8) S[j][2] = -1e30f;
                if (col + 1 > row0g + 8) S[j][3] = -1e30f;
            }
        }

        // ---- online softmax (one pass per 128 keys) ----
        float mx0 = -1e30f, mx1 = -1e30f;
        #pragma unroll
        for (int j = 0; j < 16; ++j) {
            mx0 = fmaxf(mx0, fmaxf(S[j][0], S[j][1]));
            mx1 = fmaxf(mx1, fmaxf(S[j][2], S[j][3]));
        }
        mx0 = fmaxf(mx0, __shfl_xor_sync(0xffffffffu, mx0, 1));
        mx0 = fmaxf(mx0, __shfl_xor_sync(0xffffffffu, mx0, 2));
        mx1 = fmaxf(mx1, __shfl_xor_sync(0xffffffffu, mx1, 1));
        mx1 = fmaxf(mx1, __shfl_xor_sync(0xffffffffu, mx1, 2));
        float nm0 = fmaxf(m0, mx0), nm1 = fmaxf(m1, mx1);
        float f0 = ex2(m0 - nm0), f1 = ex2(m1 - nm1);
        m0 = nm0; m1 = nm1;
        float s0 = 0.0f, s1 = 0.0f;
        #pragma unroll
        for (int j = 0; j < 16; ++j) {
            S[j][0] = ex2(S[j][0] - nm0); S[j][1] = ex2(S[j][1] - nm0);
            S[j][2] = ex2(S[j][2] - nm1); S[j][3] = ex2(S[j][3] - nm1);
            s0 += S[j][0] + S[j][1];
            s1 += S[j][2] + S[j][3];
        }
        s0 += __shfl_xor_sync(0xffffffffu, s0, 1);
        s0 += __shfl_xor_sync(0xffffffffu, s0, 2);
        s1 += __shfl_xor_sync(0xffffffffu, s1, 1);
        s1 += __shfl_xor_sync(0xffffffffu, s1, 2);
        l0 = l0 * f0 + s0; l1 = l1 * f1 + s1;
        #pragma unroll
        for (int j = 0; j < 8; ++j) {
            O[j][0] *= f0; O[j][1] *= f0; O[j][2] *= f1; O[j][3] *= f1;
        }

        // ---- O += P V over 128 keys (fp16 1-term) ----
        #pragma unroll
        for (int ks = 0; ks < 8; ++ks) {
            uint32_t ph[4];
            ph[0] = packh2(S[2 * ks][0],     S[2 * ks][1]);
            ph[1] = packh2(S[2 * ks][2],     S[2 * ks][3]);
            ph[2] = packh2(S[2 * ks + 1][0], S[2 * ks + 1][1]);
            ph[3] = packh2(S[2 * ks + 1][2], S[2 * ks + 1][3]);
            #pragma unroll
            for (int g = 0; g < 4; ++g) {
                uint32_t vaddr = st + AKMAT + (ks * 16 + v_row) * ASTR
                               + g * 32 + v_cc2;
                uint32_t vh[4];
                LDSM4T(vh[0], vh[1], vh[2], vh[3], vaddr);
                MMAH16816(O[2 * g],     ph, vh[0], vh[1]);
                MMAH16816(O[2 * g + 1], ph, vh[2], vh[3]);
            }
        }

        __syncthreads();
        if (kt + 2 < ntiles) {
            akv_load(sb + 2 * AQMAT + (kt & 1) * ASTAGE, Kh, Vh, kt + 2, tid);
            CPA_COMMIT();
        } else {
            CPA_COMMIT();
        }
    }

    // ---- epilogue: normalize, fp16 round, write [B,S,EMB] ----
    const float inv0 = 1.0f / l0, inv1 = 1.0f / l1;
    const int b = bh >> 4, h = bh & 15;
    const int r0 = qt * 128 + wid * 16 + (lane >> 2);
    const int cc = (lane & 3) * 2;
    #pragma unroll
    for (int j = 0; j < 8; ++j) {
        float p0 = O[j][0] * inv0, p1 = O[j][1] * inv0;
        float p2 = O[j][2] * inv1, p3 = O[j][3] * inv1;
        size_t i0 = ((size_t)b * S_ + r0) * EMB_ + h * 64 + j * 8 + cc;
        size_t i1 = i0 + (size_t)8 * EMB_;
        *(uint32_t*)&g_ah[i0] = packh2(p0, p1);
        *(uint32_t*)&g_ah[i1] = packh2(p2, p3);
    }
}

// ---------------- launch ---------------------------------------------------
extern "C" void kernel_launch(void* const* d_in, const int* in_sizes, int n_in,
                              void* d_out, int out_size)
{
    const float* x  = (const float*)d_in[0];
    const float* Wq = (const float*)d_in[1];
    const float* bq = (const float*)d_in[2];
    const float* Wk = (const float*)d_in[3];
    const float* bk = (const float*)d_in[4];
    const float* Wv = (const float*)d_in[5];
    const float* bv = (const float*)d_in[6];
    const float* Wo = (const float*)d_in[7];
    const float* bo = (const float*)d_in[8];
    float* out = (float*)d_out;

    cudaFuncSetAttribute(gemm_mma_kernel<0>,
                         cudaFuncAttributeMaxDynamicSharedMemorySize, GEMM_SMEM);
    cudaFuncSetAttribute(gemm_mma_kernel<1>,
                         cudaFuncAttributeMaxDynamicSharedMemorySize, GEMM_SMEM);
    cudaFuncSetAttribute(attn_mma_kernel,
                         cudaFuncAttributeMaxDynamicSharedMemorySize, ATTN_SMEM);

    const int n4x = M_ * EMB_ / 4;
    const int n4w = EMB_ * EMB_ / 4;
    conv_split_x<<<n4x / 256, 256>>>(x, n4x);
    conv_w<<<dim3(n4w / 256, 4), 256>>>(Wq, Wk, Wv, Wo);

    // QKV projections (fp16 2-term mma.sync, 2 CTAs/SM) -> Q hi/lo, K, V
    gemm_mma_kernel<0><<<dim3(EMB_ / 128, M_ / 128, 3), 256, GEMM_SMEM>>>(
        bq, bk, bv, nullptr);

    // causal attention (fp16 mma.sync flash, 128-key stages, PV 1-term)
    attn_mma_kernel<<<dim3(B_ * H_, S_ / 128), 256, ATTN_SMEM>>>();

    // output projection (fp16 1-term mma.sync, 2 CTAs/SM)
    gemm_mma_kernel<1><<<dim3(EMB_ / 128, M_ / 128, 1), 256, GEMM_SMEM>>>(
        bo, nullptr, nullptr, out);
}

// round 16
// speedup vs baseline: 2.5682x; 1.4486x over previous
#include <cuda_runtime.h>
#include <cuda_fp16.h>
#include <math.h>
#include <stdint.h>

#define B_   4
#define S_   2048
#define EMB_ 1024
#define H_   16
#define HD_  64
#define M_   (B_ * S_)   // 8192

// ---- ptx helpers (mma.sync / ldmatrix / cp.async) — baseline sm_103 legal --
__device__ __forceinline__ uint32_t smem_u32(const void* p) {
    uint32_t a;
    asm("{ .reg .u64 t; cvta.to.shared.u64 t, %1; cvt.u32.u64 %0, t; }"
        : "=r"(a) : "l"(p));
    return a;
}
__device__ __forceinline__ void cpa16(uint32_t dst, const void* src) {
    asm volatile("cp.async.cg.shared.global [%0], [%1], 16;" :: "r"(dst), "l"(src) : "memory");
}
#define CPA_COMMIT() asm volatile("cp.async.commit_group;" ::: "memory")
#define CPA_WAIT1()  asm volatile("cp.async.wait_group 1;"  ::: "memory")

#define LDSM4(r0, r1, r2, r3, addr) \
    asm volatile("ldmatrix.sync.aligned.m8n8.x4.shared.b16 {%0,%1,%2,%3}, [%4];" \
        : "=r"(r0), "=r"(r1), "=r"(r2), "=r"(r3) : "r"(addr))
#define LDSM4T(r0, r1, r2, r3, addr) \
    asm volatile("ldmatrix.sync.aligned.m8n8.x4.trans.shared.b16 {%0,%1,%2,%3}, [%4];" \
        : "=r"(r0), "=r"(r1), "=r"(r2), "=r"(r3) : "r"(addr))

#define MMAH16816(c, a, b0, b1) \
    asm volatile("mma.sync.aligned.m16n8k16.row.col.f32.f16.f16.f32 " \
        "{%0,%1,%2,%3},{%4,%5,%6,%7},{%8,%9},{%0,%1,%2,%3};" \
        : "+f"((c)[0]), "+f"((c)[1]), "+f"((c)[2]), "+f"((c)[3]) \
        : "r"((a)[0]), "r"((a)[1]), "r"((a)[2]), "r"((a)[3]), "r"(b0), "r"(b1))

__device__ __forceinline__ uint32_t packh2(float lo, float hi) {
    __half2 h = __floats2half2_rn(lo, hi);
    return *(uint32_t*)&h;
}
__device__ __forceinline__ float ex2(float x) {
    float r; asm("ex2.approx.f32 %0, %1;" : "=f"(r) : "f"(x)); return r;
}

// softmax scale folded into Q at projection time: 1/sqrt(64) * log2(e)
#define QSCALE (0.125f * 1.44269504f)

// ---------------- scratch (device globals; no allocation allowed) ----------
__device__ __align__(16) __half g_xh [(size_t)M_ * EMB_];          // x: fp16
__device__ __align__(16) __half g_wh [(size_t)4 * EMB_ * EMB_];    // weights: fp16
__device__ __align__(16) __half g_qh [(size_t)M_ * EMB_];          // Q (pre-scaled)
__device__ __align__(16) __half g_kh [(size_t)M_ * EMB_];
__device__ __align__(16) __half g_vh [(size_t)M_ * EMB_];
__device__ __align__(16) __half g_ah [(size_t)M_ * EMB_];          // attn out

// ---------------- fp32 -> fp16 round (x and weights) ------------------------
__global__ __launch_bounds__(256) void conv_x(
    const float* __restrict__ src, int n4)
{
    int i = blockIdx.x * 256 + threadIdx.x;
    if (i >= n4) return;
    float4 v = ((const float4*)src)[i];
    ((uint32_t*)g_xh)[2 * i]     = packh2(v.x, v.y);
    ((uint32_t*)g_xh)[2 * i + 1] = packh2(v.z, v.w);
}
__global__ __launch_bounds__(256) void conv_w(
    const float* __restrict__ w0, const float* __restrict__ w1,
    const float* __restrict__ w2, const float* __restrict__ w3)
{
    const int which = blockIdx.y;
    const float* src = (which == 0) ? w0 : (which == 1) ? w1 : (which == 2) ? w2 : w3;
    __half* hi = g_wh + (size_t)which * EMB_ * EMB_;
    int i = blockIdx.x * 256 + threadIdx.x;
    float4 v = ((const float4*)src)[i];
    ((uint32_t*)hi)[2 * i]     = packh2(v.x, v.y);
    ((uint32_t*)hi)[2 * i + 1] = packh2(v.z, v.w);
}

// ---------------- mma.sync GEMM: D = A @ W^T + bias (fp16 1-term) ------------
// MODE 0: A = x, W = W[z], epilogue -> g_qh (scaled) / g_kh / g_vh [B,H,S,hd]
// MODE 1: A = g_ah, W = W[3], epilogue -> fp32 outp[m*EMB+n]
constexpr int GSTRIDE = 144;
constexpr int GMAT    = 128 * GSTRIDE;             // 18432
constexpr int GSTAGE  = 2 * GMAT;                  // 36864 (A, B)
constexpr int GEMM_SMEM = 2 * GSTAGE;              // 73728 -> 2 CTAs/SM

__device__ __forceinline__ void gload_chunk(
    uint32_t sbase, const __half* A, const __half* Bh,
    int row0, int col0, int k0, int tid)
{
    #pragma unroll
    for (int i = tid; i < 2048; i += 256) {
        int mat = i >> 10;                 // 0=A, 1=Bh
        int r   = (i >> 3) & 127;
        int c   = i & 7;
        uint32_t dst = sbase + mat * GMAT + r * GSTRIDE + c * 16;
        const __half* m = mat ? Bh : A;
        int gr = (mat ? col0 : row0) + r;
        cpa16(dst, m + (size_t)gr * EMB_ + k0 + c * 8);
    }
    CPA_COMMIT();
}

template<int MODE>
__global__ __launch_bounds__(256, 2) void gemm_mma_kernel(
    const float* __restrict__ bq, const float* __restrict__ bk,
    const float* __restrict__ bv, float* __restrict__ outp)
{
    extern __shared__ char smem[];
    const uint32_t sb = smem_u32(smem);
    const int tid = threadIdx.x, wid = tid >> 5, lane = tid & 31;
    const int row0 = blockIdx.y * 128, col0 = blockIdx.x * 128;
    const int z = blockIdx.z;

    const __half *A, *Bh;
    const float* bias;
    if (MODE == 0) {
        A  = g_xh;
        Bh = g_wh + (size_t)z * EMB_ * EMB_;
        bias = (z == 0) ? bq : (z == 1) ? bk : bv;
    } else {
        A  = g_ah;
        Bh = g_wh + (size_t)3 * EMB_ * EMB_;
        bias = bq;
    }

    const int wm = (wid & 1) * 64;
    const int wn = (wid >> 1) * 32;

    float c[4][4][4] = {};

    gload_chunk(sb + 0 * GSTAGE, A, Bh, row0, col0, 0,  tid);
    gload_chunk(sb + 1 * GSTAGE, A, Bh, row0, col0, 64, tid);

    const int a_row = wm + (lane & 7) + ((lane >> 3) & 1) * 8;
    const int a_kc  = ((lane >> 4) & 1) * 8;
    const int b_row = wn + (lane & 7) + ((lane >> 4) & 1) * 8;
    const int b_kc  = ((lane >> 3) & 1) * 8;

    for (int ch = 0; ch < 16; ++ch) {
        const int s = ch & 1;
        CPA_WAIT1();
        __syncthreads();
        const uint32_t st = sb + s * GSTAGE;

        #pragma unroll
        for (int kk = 0; kk < 64; kk += 16) {
            uint32_t bhf[2][4];
            #pragma unroll
            for (int pt = 0; pt < 2; ++pt) {
                uint32_t addr = st + GMAT + (b_row + pt * 16) * GSTRIDE
                              + (kk + b_kc) * 2;
                LDSM4(bhf[pt][0], bhf[pt][1], bhf[pt][2], bhf[pt][3], addr);
            }
            #pragma unroll
            for (int mt = 0; mt < 4; ++mt) {
                uint32_t addr = st + (a_row + mt * 16) * GSTRIDE
                              + (kk + a_kc) * 2;
                uint32_t ah[4];
                LDSM4(ah[0], ah[1], ah[2], ah[3], addr);
                #pragma unroll
                for (int nt = 0; nt < 4; ++nt) {
                    const int pt = nt >> 1, hf = (nt & 1) * 2;
                    MMAH16816(c[mt][nt], ah, bhf[pt][hf], bhf[pt][hf + 1]);
                }
            }
        }
        __syncthreads();
        if (ch + 2 < 16)
            gload_chunk(sb + s * GSTAGE, A, Bh, row0, col0, (ch + 2) * 64, tid);
        else
            CPA_COMMIT();
    }

    #pragma unroll
    for (int mt = 0; mt < 4; ++mt) {
        #pragma unroll
        for (int nt = 0; nt < 4; ++nt) {
            int r = row0 + wm + mt * 16 + (lane >> 2);
            int n = col0 + wn + nt * 8 + (lane & 3) * 2;
            float2 bv2 = *(const float2*)&bias[n];
            float p0 = c[mt][nt][0] + bv2.x, p1 = c[mt][nt][1] + bv2.y;
            float p2 = c[mt][nt][2] + bv2.x, p3 = c[mt][nt][3] + bv2.y;
            if (MODE == 0) {
                int h = n >> 6, d = n & 63;
                int bb0 = r >> 11, s0 = r & 2047;
                int bb1 = (r + 8) >> 11, s1 = (r + 8) & 2047;
                size_t i0 = (((size_t)bb0 * H_ + h) * S_ + s0) * HD_ + d;
                size_t i1 = (((size_t)bb1 * H_ + h) * S_ + s1) * HD_ + d;
                __half* dh;
                if (z == 0) {
                    p0 *= QSCALE; p1 *= QSCALE; p2 *= QSCALE; p3 *= QSCALE;
                    dh = g_qh;
                } else {
                    dh = (z == 1) ? g_kh : g_vh;
                }
                *(uint32_t*)&dh[i0] = packh2(p0, p1);
                *(uint32_t*)&dh[i1] = packh2(p2, p3);
            } else {
                float2 v0 = {p0, p1}, v1 = {p2, p3};
                *(float2*)&outp[(size_t)r * EMB_ + n] = v0;
                *(float2*)&outp[(size_t)(r + 8) * EMB_ + n] = v1;
            }
        }
    }
}

// ---------------- mma.sync causal flash attention (full fp16 1-term) --------
constexpr int ASTR   = 144;
constexpr int AQMAT  = 128 * ASTR;                  // 18432 (Q, single mat)
constexpr int AKMAT  = 128 * ASTR;                  // 18432 (128 keys/stage)
constexpr int ASTAGE = 2 * AKMAT;                   // 36864 (Kh, Vh)
constexpr int ATTN_SMEM = AQMAT + 2 * ASTAGE;       // 92160 -> 2 CTAs/SM

__device__ __forceinline__ void akv_load(
    uint32_t base, const __half* Kh, const __half* Vh, int kt, int tid)
{
    #pragma unroll
    for (int i = tid; i < 2048; i += 256) {
        int mat = i >> 10;                 // 0=Kh, 1=Vh
        int r   = (i >> 3) & 127;
        int c   = i & 7;
        const __half* m = mat ? Vh : Kh;
        cpa16(base + mat * AKMAT + r * ASTR + c * 16,
              m + (size_t)(kt * 128 + r) * HD_ + c * 8);
    }
}

__global__ __launch_bounds__(256, 2) void attn_mma_kernel()
{
    extern __shared__ char smem[];
    const uint32_t sb = smem_u32(smem);
    const int tid = threadIdx.x, wid = tid >> 5, lane = tid & 31;
    const int qt = (S_ / 128 - 1) - blockIdx.y;   // heavy tiles dispatch first
    const int bh = blockIdx.x;
    const size_t off = (size_t)bh * S_ * HD_;
    const __half *Qh = g_qh + off;
    const __half *Kh = g_kh + off, *Vh = g_vh + off;
    const int ntiles = qt + 1;                    // 128-key tiles

    #pragma unroll
    for (int i = tid; i < 1024; i += 256) {
        int r = i >> 3, c = i & 7;
        cpa16(sb + r * ASTR + c * 16,
              Qh + (size_t)(qt * 128 + r) * HD_ + c * 8);
    }
    akv_load(sb + AQMAT, Kh, Vh, 0, tid);
    CPA_COMMIT();
    akv_load(sb + AQMAT + ASTAGE, Kh, Vh, 1, tid);   // rows <256 always valid
    CPA_COMMIT();

    const int a_row = wid * 16 + (lane & 7) + ((lane >> 3) & 1) * 8;
    const int a_kc2 = ((lane >> 4) & 1) * 16;
    const int b_row = (lane & 7) + ((lane >> 4) & 1) * 8;
    const int b_kc2 = ((lane >> 3) & 1) * 16;
    const int v_row = (lane & 7) + ((lane >> 3) & 1) * 8;
    const int v_cc2 = ((lane >> 4) & 1) * 16;
    const int row0g = qt * 128 + wid * 16 + (lane >> 2);

    float O[8][4] = {};
    float m0 = -1e30f, m1 = -1e30f, l0 = 0.0f, l1 = 0.0f;

    for (int kt = 0; kt < ntiles; ++kt) {
        CPA_WAIT1();
        __syncthreads();
        const uint32_t st = sb + AQMAT + (kt & 1) * ASTAGE;

        // ---- S = Q K^T over 128 keys (fp16 1-term); Q pre-scaled ----
        float S[16][4];
        #pragma unroll
        for (int j = 0; j < 16; ++j) { S[j][0]=0; S[j][1]=0; S[j][2]=0; S[j][3]=0; }
        #pragma unroll
        for (int ks = 0; ks < 4; ++ks) {
            uint32_t qaddr = sb + a_row * ASTR + ks * 32 + a_kc2;
            uint32_t ah[4];
            LDSM4(ah[0], ah[1], ah[2], ah[3], qaddr);
            #pragma unroll
            for (int g = 0; g < 8; ++g) {
                uint32_t kaddr = st + (g * 16 + b_row) * ASTR + ks * 32 + b_kc2;
                uint32_t kh[4];
                LDSM4(kh[0], kh[1], kh[2], kh[3], kaddr);
                MMAH16816(S[2 * g],     ah, kh[0], kh[1]);
                MMAH16816(S[2 * g + 1], ah, kh[2], kh[3]);
            }
        }

        // ---- causal mask (only last tile straddles) ----
        if (kt == qt) {
            #pragma unroll
            for (int j = 0; j < 16; ++j) {
                int col = kt * 128 + j * 8 + (lane & 3) * 2;
                if (col     > row0g)     S[j][0] = -1e30f;
                if (col + 1 > row0g)     S[j][1] = -1e30f;
                if (col     > row0g + 8) S[j][2] = -1e30f;
                if (col + 1 > row0g + 8) S[j][3] = -1e30f;
            }
        }

        // ---- online softmax (one pass per 128 keys) ----
        float mx0 = -1e30f, mx1 = -1e30f;
        #pragma unroll
        for (int j = 0; j < 16; ++j) {
            mx0 = fmaxf(mx0, fmaxf(S[j][0], S[j][1]));
            mx1 = fmaxf(mx1, fmaxf(S[j][2], S[j][3]));
        }
        mx0 = fmaxf(mx0, __shfl_xor_sync(0xffffffffu, mx0, 1));
        mx0 = fmaxf(mx0, __shfl_xor_sync(0xffffffffu, mx0, 2));
        mx1 = fmaxf(mx1, __shfl_xor_sync(0xffffffffu, mx1, 1));
        mx1 = fmaxf(mx1, __shfl_xor_sync(0xffffffffu, mx1, 2));
        float nm0 = fmaxf(m0, mx0), nm1 = fmaxf(m1, mx1);
        float f0 = ex2(m0 - nm0), f1 = ex2(m1 - nm1);
        m0 = nm0; m1 = nm1;
        float s0 = 0.0f, s1 = 0.0f;
        #pragma unroll
        for (int j = 0; j < 16; ++j) {
            S[j][0] = ex2(S[j][0] - nm0); S[j][1] = ex2(S[j][1] - nm0);
            S[j][2] = ex2(S[j][2] - nm1); S[j][3] = ex2(S[j][3] - nm1);
            s0 += S[j][0] + S[j][1];
            s1 += S[j][2] + S[j][3];
        }
        s0 += __shfl_xor_sync(0xffffffffu, s0, 1);
        s0 += __shfl_xor_sync(0xffffffffu, s0, 2);
        s1 += __shfl_xor_sync(0xffffffffu, s1, 1);
        s1 += __shfl_xor_sync(0xffffffffu, s1, 2);
        l0 = l0 * f0 + s0; l1 = l1 * f1 + s1;
        #pragma unroll
        for (int j = 0; j < 8; ++j) {
            O[j][0] *= f0; O[j][1] *= f0; O[j][2] *= f1; O[j][3] *= f1;
        }

        // ---- O += P V over 128 keys (fp16 1-term) ----
        #pragma unroll
        for (int ks = 0; ks < 8; ++ks) {
            uint32_t ph[4];
            ph[0] = packh2(S[2 * ks][0],     S[2 * ks][1]);
            ph[1] = packh2(S[2 * ks][2],     S[2 * ks][3]);
            ph[2] = packh2(S[2 * ks + 1][0], S[2 * ks + 1][1]);
            ph[3] = packh2(S[2 * ks + 1][2], S[2 * ks + 1][3]);
            #pragma unroll
            for (int g = 0; g < 4; ++g) {
                uint32_t vaddr = st + AKMAT + (ks * 16 + v_row) * ASTR
                               + g * 32 + v_cc2;
                uint32_t vh[4];
                LDSM4T(vh[0], vh[1], vh[2], vh[3], vaddr);
                MMAH16816(O[2 * g],     ph, vh[0], vh[1]);
                MMAH16816(O[2 * g + 1], ph, vh[2], vh[3]);
            }
        }

        __syncthreads();
        if (kt + 2 < ntiles) {
            akv_load(sb + AQMAT + (kt & 1) * ASTAGE, Kh, Vh, kt + 2, tid);
            CPA_COMMIT();
        } else {
            CPA_COMMIT();
        }
    }

    // ---- epilogue: normalize, fp16 round, write [B,S,EMB] ----
    const float inv0 = 1.0f / l0, inv1 = 1.0f / l1;
    const int b = bh >> 4, h = bh & 15;
    const int r0 = qt * 128 + wid * 16 + (lane >> 2);
    const int cc = (lane & 3) * 2;
    #pragma unroll
    for (int j = 0; j < 8; ++j) {
        float p0 = O[j][0] * inv0, p1 = O[j][1] * inv0;
        float p2 = O[j][2] * inv1, p3 = O[j][3] * inv1;
        size_t i0 = ((size_t)b * S_ + r0) * EMB_ + h * 64 + j * 8 + cc;
        size_t i1 = i0 + (size_t)8 * EMB_;
        *(uint32_t*)&g_ah[i0] = packh2(p0, p1);
        *(uint32_t*)&g_ah[i1] = packh2(p2, p3);
    }
}

// ---------------- launch ---------------------------------------------------
extern "C" void kernel_launch(void* const* d_in, const int* in_sizes, int n_in,
                              void* d_out, int out_size)
{
    const float* x  = (const float*)d_in[0];
    const float* Wq = (const float*)d_in[1];
    const float* bq = (const float*)d_in[2];
    const float* Wk = (const float*)d_in[3];
    const float* bk = (const float*)d_in[4];
    const float* Wv = (const float*)d_in[5];
    const float* bv = (const float*)d_in[6];
    const float* Wo = (const float*)d_in[7];
    const float* bo = (const float*)d_in[8];
    float* out = (float*)d_out;

    cudaFuncSetAttribute(gemm_mma_kernel<0>,
                         cudaFuncAttributeMaxDynamicSharedMemorySize, GEMM_SMEM);
    cudaFuncSetAttribute(gemm_mma_kernel<1>,
                         cudaFuncAttributeMaxDynamicSharedMemorySize, GEMM_SMEM);
    cudaFuncSetAttribute(attn_mma_kernel,
                         cudaFuncAttributeMaxDynamicSharedMemorySize, ATTN_SMEM);

    const int n4x = M_ * EMB_ / 4;
    const int n4w = EMB_ * EMB_ / 4;
    conv_x<<<n4x / 256, 256>>>(x, n4x);
    conv_w<<<dim3(n4w / 256, 4), 256>>>(Wq, Wk, Wv, Wo);

    // QKV projections (fp16 1-term mma.sync, 2 CTAs/SM) -> Q (scaled), K, V
    gemm_mma_kernel<0><<<dim3(EMB_ / 128, M_ / 128, 3), 256, GEMM_SMEM>>>(
        bq, bk, bv, nullptr);

    // causal attention (full fp16 mma.sync flash, 128-key stages)
    attn_mma_kernel<<<dim3(B_ * H_, S_ / 128), 256, ATTN_SMEM>>>();

    // output projection (fp16 1-term mma.sync, 2 CTAs/SM)
    gemm_mma_kernel<1><<<dim3(EMB_ / 128, M_ / 128, 1), 256, GEMM_SMEM>>>(
        bo, nullptr, nullptr, out);
}

// round 17
// speedup vs baseline: 2.6410x; 1.0283x over previous
#include <cuda_runtime.h>
#include <cuda_fp16.h>
#include <math.h>
#include <stdint.h>

#define B_   4
#define S_   2048
#define EMB_ 1024
#define H_   16
#define HD_  64
#define M_   (B_ * S_)   // 8192

// ---- ptx helpers (mma.sync / ldmatrix / cp.async) — baseline sm_103 legal --
__device__ __forceinline__ uint32_t smem_u32(const void* p) {
    uint32_t a;
    asm("{ .reg .u64 t; cvta.to.shared.u64 t, %1; cvt.u32.u64 %0, t; }"
        : "=r"(a) : "l"(p));
    return a;
}
__device__ __forceinline__ void cpa16(uint32_t dst, const void* src) {
    asm volatile("cp.async.cg.shared.global [%0], [%1], 16;" :: "r"(dst), "l"(src) : "memory");
}
#define CPA_COMMIT() asm volatile("cp.async.commit_group;" ::: "memory")
#define CPA_WAIT1()  asm volatile("cp.async.wait_group 1;"  ::: "memory")

#define LDSM4(r0, r1, r2, r3, addr) \
    asm volatile("ldmatrix.sync.aligned.m8n8.x4.shared.b16 {%0,%1,%2,%3}, [%4];" \
        : "=r"(r0), "=r"(r1), "=r"(r2), "=r"(r3) : "r"(addr))
#define LDSM4T(r0, r1, r2, r3, addr) \
    asm volatile("ldmatrix.sync.aligned.m8n8.x4.trans.shared.b16 {%0,%1,%2,%3}, [%4];" \
        : "=r"(r0), "=r"(r1), "=r"(r2), "=r"(r3) : "r"(addr))
#define LDSM2T(r0, r1, addr) \
    asm volatile("ldmatrix.sync.aligned.m8n8.x2.trans.shared.b16 {%0,%1}, [%2];" \
        : "=r"(r0), "=r"(r1) : "r"(addr))

#define MMAH16816(c, a, b0, b1) \
    asm volatile("mma.sync.aligned.m16n8k16.row.col.f32.f16.f16.f32 " \
        "{%0,%1,%2,%3},{%4,%5,%6,%7},{%8,%9},{%0,%1,%2,%3};" \
        : "+f"((c)[0]), "+f"((c)[1]), "+f"((c)[2]), "+f"((c)[3]) \
        : "r"((a)[0]), "r"((a)[1]), "r"((a)[2]), "r"((a)[3]), "r"(b0), "r"(b1))

__device__ __forceinline__ uint32_t packh2(float lo, float hi) {
    __half2 h = __floats2half2_rn(lo, hi);
    return *(uint32_t*)&h;
}
__device__ __forceinline__ float ex2(float x) {
    float r; asm("ex2.approx.f32 %0, %1;" : "=f"(r) : "f"(x)); return r;
}
__device__ __forceinline__ uint32_t ex2x2(uint32_t a) {
    uint32_t r; asm("ex2.approx.f16x2 %0, %1;" : "=r"(r) : "r"(a)); return r;
}

// softmax scale folded into Q at projection time: 1/sqrt(64) * log2(e)
#define QSCALE (0.125f * 1.44269504f)

// ---------------- scratch (device globals; no allocation allowed) ----------
__device__ __align__(16) __half g_xh [(size_t)M_ * EMB_];          // x: fp16
__device__ __align__(16) __half g_wh [(size_t)4 * EMB_ * EMB_];    // weights: fp16
__device__ __align__(16) __half g_qh [(size_t)M_ * EMB_];          // Q (pre-scaled)
__device__ __align__(16) __half g_kh [(size_t)M_ * EMB_];
__device__ __align__(16) __half g_vh [(size_t)M_ * EMB_];
__device__ __align__(16) __half g_ah [(size_t)M_ * EMB_];          // attn out

// ---------------- fp32 -> fp16 round (x and weights) ------------------------
__global__ __launch_bounds__(256) void conv_x(
    const float* __restrict__ src, int n4)
{
    int i = blockIdx.x * 256 + threadIdx.x;
    if (i >= n4) return;
    float4 v = ((const float4*)src)[i];
    ((uint32_t*)g_xh)[2 * i]     = packh2(v.x, v.y);
    ((uint32_t*)g_xh)[2 * i + 1] = packh2(v.z, v.w);
}
__global__ __launch_bounds__(256) void conv_w(
    const float* __restrict__ w0, const float* __restrict__ w1,
    const float* __restrict__ w2, const float* __restrict__ w3)
{
    const int which = blockIdx.y;
    const float* src = (which == 0) ? w0 : (which == 1) ? w1 : (which == 2) ? w2 : w3;
    __half* hi = g_wh + (size_t)which * EMB_ * EMB_;
    int i = blockIdx.x * 256 + threadIdx.x;
    float4 v = ((const float4*)src)[i];
    ((uint32_t*)hi)[2 * i]     = packh2(v.x, v.y);
    ((uint32_t*)hi)[2 * i + 1] = packh2(v.z, v.w);
}

// ---------------- mma.sync GEMM: D = A @ W^T + bias (fp16 1-term) ------------
constexpr int GSTRIDE = 144;
constexpr int GMAT    = 128 * GSTRIDE;             // 18432
constexpr int GSTAGE  = 2 * GMAT;                  // 36864 (A, B)
constexpr int GEMM_SMEM = 2 * GSTAGE;              // 73728 -> 2 CTAs/SM

__device__ __forceinline__ void gload_chunk(
    uint32_t sbase, const __half* A, const __half* Bh,
    int row0, int col0, int k0, int tid)
{
    #pragma unroll
    for (int i = tid; i < 2048; i += 256) {
        int mat = i >> 10;                 // 0=A, 1=Bh
        int r   = (i >> 3) & 127;
        int c   = i & 7;
        uint32_t dst = sbase + mat * GMAT + r * GSTRIDE + c * 16;
        const __half* m = mat ? Bh : A;
        int gr = (mat ? col0 : row0) + r;
        cpa16(dst, m + (size_t)gr * EMB_ + k0 + c * 8);
    }
    CPA_COMMIT();
}

template<int MODE>
__global__ __launch_bounds__(256, 2) void gemm_mma_kernel(
    const float* __restrict__ bq, const float* __restrict__ bk,
    const float* __restrict__ bv, float* __restrict__ outp)
{
    extern __shared__ char smem[];
    const uint32_t sb = smem_u32(smem);
    const int tid = threadIdx.x, wid = tid >> 5, lane = tid & 31;
    const int row0 = blockIdx.y * 128, col0 = blockIdx.x * 128;
    const int z = blockIdx.z;

    const __half *A, *Bh;
    const float* bias;
    if (MODE == 0) {
        A  = g_xh;
        Bh = g_wh + (size_t)z * EMB_ * EMB_;
        bias = (z == 0) ? bq : (z == 1) ? bk : bv;
    } else {
        A  = g_ah;
        Bh = g_wh + (size_t)3 * EMB_ * EMB_;
        bias = bq;
    }

    const int wm = (wid & 1) * 64;
    const int wn = (wid >> 1) * 32;

    float c[4][4][4] = {};

    gload_chunk(sb + 0 * GSTAGE, A, Bh, row0, col0, 0,  tid);
    gload_chunk(sb + 1 * GSTAGE, A, Bh, row0, col0, 64, tid);

    const int a_row = wm + (lane & 7) + ((lane >> 3) & 1) * 8;
    const int a_kc  = ((lane >> 4) & 1) * 8;
    const int b_row = wn + (lane & 7) + ((lane >> 4) & 1) * 8;
    const int b_kc  = ((lane >> 3) & 1) * 8;

    for (int ch = 0; ch < 16; ++ch) {
        const int s = ch & 1;
        CPA_WAIT1();
        __syncthreads();
        const uint32_t st = sb + s * GSTAGE;

        #pragma unroll
        for (int kk = 0; kk < 64; kk += 16) {
            uint32_t bhf[2][4];
            #pragma unroll
            for (int pt = 0; pt < 2; ++pt) {
                uint32_t addr = st + GMAT + (b_row + pt * 16) * GSTRIDE
                              + (kk + b_kc) * 2;
                LDSM4(bhf[pt][0], bhf[pt][1], bhf[pt][2], bhf[pt][3], addr);
            }
            #pragma unroll
            for (int mt = 0; mt < 4; ++mt) {
                uint32_t addr = st + (a_row + mt * 16) * GSTRIDE
                              + (kk + a_kc) * 2;
                uint32_t ah[4];
                LDSM4(ah[0], ah[1], ah[2], ah[3], addr);
                #pragma unroll
                for (int nt = 0; nt < 4; ++nt) {
                    const int pt = nt >> 1, hf = (nt & 1) * 2;
                    MMAH16816(c[mt][nt], ah, bhf[pt][hf], bhf[pt][hf + 1]);
                }
            }
        }
        __syncthreads();
        if (ch + 2 < 16)
            gload_chunk(sb + s * GSTAGE, A, Bh, row0, col0, (ch + 2) * 64, tid);
        else
            CPA_COMMIT();
    }

    #pragma unroll
    for (int mt = 0; mt < 4; ++mt) {
        #pragma unroll
        for (int nt = 0; nt < 4; ++nt) {
            int r = row0 + wm + mt * 16 + (lane >> 2);
            int n = col0 + wn + nt * 8 + (lane & 3) * 2;
            float2 bv2 = *(const float2*)&bias[n];
            float p0 = c[mt][nt][0] + bv2.x, p1 = c[mt][nt][1] + bv2.y;
            float p2 = c[mt][nt][2] + bv2.x, p3 = c[mt][nt][3] + bv2.y;
            if (MODE == 0) {
                int h = n >> 6, d = n & 63;
                int bb0 = r >> 11, s0 = r & 2047;
                int bb1 = (r + 8) >> 11, s1 = (r + 8) & 2047;
                size_t i0 = (((size_t)bb0 * H_ + h) * S_ + s0) * HD_ + d;
                size_t i1 = (((size_t)bb1 * H_ + h) * S_ + s1) * HD_ + d;
                __half* dh;
                if (z == 0) {
                    p0 *= QSCALE; p1 *= QSCALE; p2 *= QSCALE; p3 *= QSCALE;
                    dh = g_qh;
                } else {
                    dh = (z == 1) ? g_kh : g_vh;
                }
                *(uint32_t*)&dh[i0] = packh2(p0, p1);
                *(uint32_t*)&dh[i1] = packh2(p2, p3);
            } else {
                float2 v0 = {p0, p1}, v1 = {p2, p3};
                *(float2*)&outp[(size_t)r * EMB_ + n] = v0;
                *(float2*)&outp[(size_t)(r + 8) * EMB_ + n] = v1;
            }
        }
    }
}

// ---------------- mma.sync causal flash attention (full fp16 1-term) --------
// Row sums via ones-column MMA (V pad col 64 = 1.0); softmax exp in f16x2.
constexpr int ASTR   = 144;
constexpr int AQMAT  = 128 * ASTR;                  // 18432 (Q, single mat)
constexpr int AKMAT  = 128 * ASTR;                  // 18432 (128 keys/stage)
constexpr int ASTAGE = 2 * AKMAT;                   // 36864 (Kh, Vh)
constexpr int ATTN_SMEM = AQMAT + 2 * ASTAGE;       // 92160 -> 2 CTAs/SM

__device__ __forceinline__ void akv_load(
    uint32_t base, const __half* Kh, const __half* Vh, int kt, int tid)
{
    #pragma unroll
    for (int i = tid; i < 2048; i += 256) {
        int mat = i >> 10;                 // 0=Kh, 1=Vh
        int r   = (i >> 3) & 127;
        int c   = i & 7;
        const __half* m = mat ? Vh : Kh;
        cpa16(base + mat * AKMAT + r * ASTR + c * 16,
              m + (size_t)(kt * 128 + r) * HD_ + c * 8);
    }
}

__global__ __launch_bounds__(256, 2) void attn_mma_kernel()
{
    extern __shared__ char smem[];
    const uint32_t sb = smem_u32(smem);
    const int tid = threadIdx.x, wid = tid >> 5, lane = tid & 31;
    const int qt = (S_ / 128 - 1) - blockIdx.y;   // heavy tiles dispatch first
    const int bh = blockIdx.x;
    const size_t off = (size_t)bh * S_ * HD_;
    const __half *Qh = g_qh + off;
    const __half *Kh = g_kh + off, *Vh = g_vh + off;
    const int ntiles = qt + 1;                    // 128-key tiles

    #pragma unroll
    for (int i = tid; i < 1024; i += 256) {
        int r = i >> 3, c = i & 7;
        cpa16(sb + r * ASTR + c * 16,
              Qh + (size_t)(qt * 128 + r) * HD_ + c * 8);
    }
    akv_load(sb + AQMAT, Kh, Vh, 0, tid);
    CPA_COMMIT();
    akv_load(sb + AQMAT + ASTAGE, Kh, Vh, 1, tid);   // rows <256 always valid
    CPA_COMMIT();

    // init V padding (bytes 128..143 of every V row, both stages):
    // col 64 = 1.0 (ones column for row-sum MMA), cols 65..71 = 0.
    // cp.async never writes these bytes; synced by the per-tile barrier.
    {
        int st_ = tid >> 7, r = tid & 127;
        uint32_t addr = sb + AQMAT + st_ * ASTAGE + AKMAT + r * ASTR + 128;
        asm volatile("st.shared.v4.b32 [%0], {%1, %2, %2, %2};"
                     :: "r"(addr), "r"(0x00003C00u), "r"(0u) : "memory");
    }

    const int a_row = wid * 16 + (lane & 7) + ((lane >> 3) & 1) * 8;
    const int a_kc2 = ((lane >> 4) & 1) * 16;
    const int b_row = (lane & 7) + ((lane >> 4) & 1) * 8;
    const int b_kc2 = ((lane >> 3) & 1) * 16;
    const int v_row = (lane & 7) + ((lane >> 3) & 1) * 8;
    const int v_cc2 = ((lane >> 4) & 1) * 16;
    const int row0g = qt * 128 + wid * 16 + (lane >> 2);

    float O[8][4] = {};
    float Oe[4] = {};                 // ones-column accumulator: l lives here
    float m0 = -1e30f, m1 = -1e30f;

    for (int kt = 0; kt < ntiles; ++kt) {
        CPA_WAIT1();
        __syncthreads();
        const uint32_t st = sb + AQMAT + (kt & 1) * ASTAGE;

        // ---- S = Q K^T over 128 keys (fp16 1-term); Q pre-scaled ----
        float S[16][4];
        #pragma unroll
        for (int j = 0; j < 16; ++j) { S[j][0]=0; S[j][1]=0; S[j][2]=0; S[j][3]=0; }
        #pragma unroll
        for (int ks = 0; ks < 4; ++ks) {
            uint32_t qaddr = sb + a_row * ASTR + ks * 32 + a_kc2;
            uint32_t ah[4];
            LDSM4(ah[0], ah[1], ah[2], ah[3], qaddr);
            #pragma unroll
            for (int g = 0; g < 8; ++g) {
                uint32_t kaddr = st + (g * 16 + b_row) * ASTR + ks * 32 + b_kc2;
                uint32_t kh[4];
                LDSM4(kh[0], kh[1], kh[2], kh[3], kaddr);
                MMAH16816(S[2 * g],     ah, kh[0], kh[1]);
                MMAH16816(S[2 * g + 1], ah, kh[2], kh[3]);
            }
        }

        // ---- causal mask (only last tile straddles) ----
        if (kt == qt) {
            #pragma unroll
            for (int j = 0; j < 16; ++j) {
                int col = kt * 128 + j * 8 + (lane & 3) * 2;
                if (col     > row0g)     S[j][0] = -1e30f;
                if (col + 1 > row0g)     S[j][1] = -1e30f;
                if (col     > row0g + 8) S[j][2] = -1e30f;
                if (col + 1 > row0g + 8) S[j][3] = -1e30f;
            }
        }

        // ---- online max (sums come from the ones-column MMA) ----
        float mx0 = -1e30f, mx1 = -1e30f;
        #pragma unroll
        for (int j = 0; j < 16; ++j) {
            mx0 = fmaxf(mx0, fmaxf(S[j][0], S[j][1]));
            mx1 = fmaxf(mx1, fmaxf(S[j][2], S[j][3]));
        }
        mx0 = fmaxf(mx0, __shfl_xor_sync(0xffffffffu, mx0, 1));
        mx0 = fmaxf(mx0, __shfl_xor_sync(0xffffffffu, mx0, 2));
        mx1 = fmaxf(mx1, __shfl_xor_sync(0xffffffffu, mx1, 1));
        mx1 = fmaxf(mx1, __shfl_xor_sync(0xffffffffu, mx1, 2));
        float nm0 = fmaxf(m0, mx0), nm1 = fmaxf(m1, mx1);
        float f0 = ex2(m0 - nm0), f1 = ex2(m1 - nm1);
        m0 = nm0; m1 = nm1;

        // ---- P = ex2(S - m) directly in f16x2 (pre-packed for MMA) ----
        uint32_t P01[16], P23[16];
        #pragma unroll
        for (int j = 0; j < 16; ++j) {
            P01[j] = ex2x2(packh2(S[j][0] - nm0, S[j][1] - nm0));
            P23[j] = ex2x2(packh2(S[j][2] - nm1, S[j][3] - nm1));
        }

        #pragma unroll
        for (int j = 0; j < 8; ++j) {
            O[j][0] *= f0; O[j][1] *= f0; O[j][2] *= f1; O[j][3] *= f1;
        }
        Oe[0] *= f0; Oe[1] *= f0; Oe[2] *= f1; Oe[3] *= f1;

        // ---- O += P V over 128 keys; Oe += P . ones ----
        #pragma unroll
        for (int ks = 0; ks < 8; ++ks) {
            uint32_t ph[4];
            ph[0] = P01[2 * ks];     ph[1] = P23[2 * ks];
            ph[2] = P01[2 * ks + 1]; ph[3] = P23[2 * ks + 1];
            #pragma unroll
            for (int g = 0; g < 4; ++g) {
                uint32_t vaddr = st + AKMAT + (ks * 16 + v_row) * ASTR
                               + g * 32 + v_cc2;
                uint32_t vh[4];
                LDSM4T(vh[0], vh[1], vh[2], vh[3], vaddr);
                MMAH16816(O[2 * g],     ph, vh[0], vh[1]);
                MMAH16816(O[2 * g + 1], ph, vh[2], vh[3]);
            }
            uint32_t ve0, ve1;
            LDSM2T(ve0, ve1, st + AKMAT + (ks * 16 + v_row) * ASTR + 128);
            MMAH16816(Oe, ph, ve0, ve1);
        }

        __syncthreads();
        if (kt + 2 < ntiles) {
            akv_load(sb + AQMAT + (kt & 1) * ASTAGE, Kh, Vh, kt + 2, tid);
            CPA_COMMIT();
        } else {
            CPA_COMMIT();
        }
    }

    // ---- epilogue: l from ones column (quad lane 0), normalize, write ----
    float l0 = __shfl_sync(0xffffffffu, Oe[0], lane & 28);
    float l1 = __shfl_sync(0xffffffffu, Oe[2], lane & 28);
    const float inv0 = 1.0f / l0, inv1 = 1.0f / l1;
    const int b = bh >> 4, h = bh & 15;
    const int r0 = qt * 128 + wid * 16 + (lane >> 2);
    const int cc = (lane & 3) * 2;
    #pragma unroll
    for (int j = 0; j < 8; ++j) {
        float p0 = O[j][0] * inv0, p1 = O[j][1] * inv0;
        float p2 = O[j][2] * inv1, p3 = O[j][3] * inv1;
        size_t i0 = ((size_t)b * S_ + r0) * EMB_ + h * 64 + j * 8 + cc;
        size_t i1 = i0 + (size_t)8 * EMB_;
        *(uint32_t*)&g_ah[i0] = packh2(p0, p1);
        *(uint32_t*)&g_ah[i1] = packh2(p2, p3);
    }
}

// ---------------- launch ---------------------------------------------------
extern "C" void kernel_launch(void* const* d_in, const int* in_sizes, int n_in,
                              void* d_out, int out_size)
{
    const float* x  = (const float*)d_in[0];
    const float* Wq = (const float*)d_in[1];
    const float* bq = (const float*)d_in[2];
    const float* Wk = (const float*)d_in[3];
    const float* bk = (const float*)d_in[4];
    const float* Wv = (const float*)d_in[5];
    const float* bv = (const float*)d_in[6];
    const float* Wo = (const float*)d_in[7];
    const float* bo = (const float*)d_in[8];
    float* out = (float*)d_out;

    cudaFuncSetAttribute(gemm_mma_kernel<0>,
                         cudaFuncAttributeMaxDynamicSharedMemorySize, GEMM_SMEM);
    cudaFuncSetAttribute(gemm_mma_kernel<1>,
                         cudaFuncAttributeMaxDynamicSharedMemorySize, GEMM_SMEM);
    cudaFuncSetAttribute(attn_mma_kernel,
                         cudaFuncAttributeMaxDynamicSharedMemorySize, ATTN_SMEM);

    const int n4x = M_ * EMB_ / 4;
    const int n4w = EMB_ * EMB_ / 4;
    conv_x<<<n4x / 256, 256>>>(x, n4x);
    conv_w<<<dim3(n4w / 256, 4), 256>>>(Wq, Wk, Wv, Wo);

    // QKV projections (fp16 1-term mma.sync, 2 CTAs/SM) -> Q (scaled), K, V
    gemm_mma_kernel<0><<<dim3(EMB_ / 128, M_ / 128, 3), 256, GEMM_SMEM>>>(
        bq, bk, bv, nullptr);

    // causal attention (fp16 flash, ones-column row sums, f16x2 softmax)
    attn_mma_kernel<<<dim3(B_ * H_, S_ / 128), 256, ATTN_SMEM>>>();

    // output projection (fp16 1-term mma.sync, 2 CTAs/SM)
    gemm_mma_kernel<1><<<dim3(EMB_ / 128, M_ / 128, 1), 256, GEMM_SMEM>>>(
        bo, nullptr, nullptr, out);
}